// round 6
// baseline (speedup 1.0000x reference)
#include <cuda_runtime.h>
#include <cuda_bf16.h>
#include <math.h>
#include <stdint.h>

typedef unsigned int u32;
typedef unsigned long long u64;

#define N_SAMP 2048
#define MDIMS  36
#define REP    10
#define FEAT   360
#define DENSE_N 16384        // 256*8*8

// ---------------- packed f32x2 helpers ----------------
__device__ __forceinline__ u64 fma2(u64 a, u64 b, u64 c) {
    u64 d;
    asm("fma.rn.f32x2 %0, %1, %2, %3;" : "=l"(d) : "l"(a), "l"(b), "l"(c));
    return d;
}
__device__ __forceinline__ u64 bcast2(float x) {
    u64 r; unsigned xi = __float_as_uint(x);
    asm("mov.b64 %0, {%1, %2};" : "=l"(r) : "r"(xi), "r"(xi));
    return r;
}
__device__ __forceinline__ u64 pack2(float lo, float hi) {
    u64 r; unsigned a = __float_as_uint(lo), b = __float_as_uint(hi);
    asm("mov.b64 %0, {%1, %2};" : "=l"(r) : "r"(a), "r"(b));
    return r;
}
__device__ __forceinline__ float2 unpk2(u64 p) {
    unsigned lo, hi;
    asm("mov.b64 {%0, %1}, %2;" : "=r"(lo), "=r"(hi) : "l"(p));
    return make_float2(__uint_as_float(lo), __uint_as_float(hi));
}

// ---------------- bf16 pack/unpack ----------------
__device__ __forceinline__ u32 bf16pack(float lo, float hi) {
    u32 r;
    asm("cvt.rn.satfinite.bf16x2.f32 %0, %1, %2;" : "=r"(r) : "f"(hi), "f"(lo));
    return r;
}
__device__ __forceinline__ float2 bf16unpk(u32 u) {
    __nv_bfloat162 h = *reinterpret_cast<__nv_bfloat162*>(&u);
    return __bfloat1622float2(h);
}

// ---------------- warp MMA + cp.async helpers ----------------
__device__ __forceinline__ u32 smem_to_u32(const void* p) {
    u32 a;
    asm("{ .reg .u64 t; cvta.to.shared.u64 t, %1; cvt.u32.u64 %0, t; }" : "=r"(a) : "l"(p));
    return a;
}
__device__ __forceinline__ void ldsm4(u32* r, u32 addr) {
    asm volatile("ldmatrix.sync.aligned.m8n8.x4.shared.b16 {%0,%1,%2,%3}, [%4];"
                 : "=r"(r[0]), "=r"(r[1]), "=r"(r[2]), "=r"(r[3]) : "r"(addr));
}
__device__ __forceinline__ void mma16816(float* d, const u32* a, u32 b0, u32 b1) {
    asm volatile(
        "mma.sync.aligned.m16n8k16.row.col.f32.bf16.bf16.f32 "
        "{%0,%1,%2,%3}, {%4,%5,%6,%7}, {%8,%9}, {%0,%1,%2,%3};"
        : "+f"(d[0]), "+f"(d[1]), "+f"(d[2]), "+f"(d[3])
        : "r"(a[0]), "r"(a[1]), "r"(a[2]), "r"(a[3]), "r"(b0), "r"(b1));
}
__device__ __forceinline__ void cp16(u32 dst, const void* src, bool p) {
    asm volatile("cp.async.cg.shared.global [%0], [%1], 16, %2;"
                 :: "r"(dst), "l"(src), "r"(p ? 16 : 0) : "memory");
}
__device__ __forceinline__ void cp_commit() {
    asm volatile("cp.async.commit_group;" ::: "memory");
}
__device__ __forceinline__ void cp_wait1() {
    asm volatile("cp.async.wait_group 1;" ::: "memory");
}
__device__ __forceinline__ void cp_wait0() {
    asm volatile("cp.async.wait_group 0;" ::: "memory");
}

// ---------------- scratch ----------------
__device__ float g_JD[286];
__device__ float g_item[N_SAMP * FEAT];
__device__ __align__(16) __nv_bfloat16 g_h0hi[N_SAMP * 16384];      // NHWC [n,8,8,256]
__device__ __align__(16) __nv_bfloat16 g_h0lo[N_SAMP * 16384];
__device__ __align__(16) __nv_bfloat16 g_h1hi[N_SAMP * 256 * 128];  // NHWC [n,16,16,128]
__device__ __align__(16) __nv_bfloat16 g_h1lo[N_SAMP * 256 * 128];
__device__ __align__(16) float g_h2[N_SAMP * 1024 * 64];            // NHWC [n,32,32,64] fp32
__device__ __align__(16) __nv_bfloat16 g_w1hi[4 * 128 * 1024];
__device__ __align__(16) __nv_bfloat16 g_w1lo[4 * 128 * 1024];
__device__ __align__(16) __nv_bfloat16 g_w2hi[4 * 64 * 512];
__device__ __align__(16) __nv_bfloat16 g_w2lo[4 * 64 * 512];

__device__ __constant__ int c_off[7] = {0, 1, 10, 35, 84, 165, 286};

// ---------------- J_l init ----------------
__device__ double dfact(int n) { double r = 1.0; for (int i = 2; i <= n; i++) r *= (double)i; return r; }

__device__ double small_d(int l, int mp, int m) {
    const double ch = 0.70710678118654752440, sh = 0.70710678118654752440;
    double pref = sqrt(dfact(l + mp) * dfact(l - mp) * dfact(l + m) * dfact(l - m));
    int smin = max(0, m - mp), smax = min(l + m, l - mp);
    double tot = 0.0;
    for (int s = smin; s <= smax; s++) {
        double sign = ((mp - m + s) & 1) ? -1.0 : 1.0;
        double denom = dfact(l + m - s) * dfact(s) * dfact(mp - m + s) * dfact(l - mp - s);
        tot += sign / denom * pow(ch, (double)(2 * l + m - mp - 2 * s)) * pow(sh, (double)(mp - m + 2 * s));
    }
    return pref * tot;
}

__device__ void c2r_row(int l, int i, int* col, double* re, double* im, int* cnt) {
    int m = i - l;
    const double s = 0.70710678118654752440;
    if (m < 0) {
        double sgn = (m & 1) ? -1.0 : 1.0;
        col[0] = l + m; re[0] = 0.0; im[0] = s;
        col[1] = l - m; re[1] = 0.0; im[1] = -sgn * s;
        *cnt = 2;
    } else if (m == 0) {
        col[0] = l; re[0] = 1.0; im[0] = 0.0; *cnt = 1;
    } else {
        double sgn = (m & 1) ? -1.0 : 1.0;
        col[0] = l - m; re[0] = s;        im[0] = 0.0;
        col[1] = l + m; re[1] = sgn * s;  im[1] = 0.0;
        *cnt = 2;
    }
}

__global__ void init_jd_kernel() {
    int idx = threadIdx.x;
    if (idx >= 286) return;
    int l = 0;
    while (idx >= c_off[l + 1]) l++;
    int e = idx - c_off[l];
    int sz = 2 * l + 1;
    int i = e / sz, j = e % sz;
    int ca_c[2], cb_c[2], na, nb;
    double ca_re[2], ca_im[2], cb_re[2], cb_im[2];
    c2r_row(l, i, ca_c, ca_re, ca_im, &na);
    c2r_row(l, j, cb_c, cb_re, cb_im, &nb);
    double acc = 0.0;
    for (int a = 0; a < na; a++)
        for (int b = 0; b < nb; b++) {
            double cross = ca_re[a] * cb_re[b] + ca_im[a] * cb_im[b];
            if (cross != 0.0) acc += cross * small_d(l, ca_c[a] - l, cb_c[b] - l);
        }
    g_JD[idx] = (float)acc;
}

// ---------------- Wigner (parallel over l) ----------------
__device__ __forceinline__ void zrot_apply(const float* v, int sz, int l, float ang, float* out) {
    for (int i = 0; i < sz; i++) {
        float f = (float)(l - i);
        float s, c;
        sincosf(f * ang, &s, &c);
        out[i] = c * v[i] + s * v[sz - 1 - i];
    }
}

__global__ void wigner_kernel(const float* __restrict__ angles, const float* __restrict__ item_rep) {
    int t = blockIdx.x * blockDim.x + threadIdx.x;
    if (t >= N_SAMP * REP * 6) return;
    int l = t % 6;
    int nr = t / 6;
    int n = nr / REP, r = nr % REP;
    float a0 = angles[n * 3 + 0], a1 = angles[n * 3 + 1], a2 = angles[n * 3 + 2];
    float v[11], w[11];
    int sz = 2 * l + 1;
    const float* J = &g_JD[c_off[l]];
    for (int i = 0; i < sz; i++) v[i] = item_rep[(l * l + i) * REP + r];
    zrot_apply(v, sz, l, a2, w);
    for (int i = 0; i < sz; i++) { float s = 0.f; for (int j = 0; j < sz; j++) s += J[i * sz + j] * w[j]; v[i] = s; }
    zrot_apply(v, sz, l, a1, w);
    for (int i = 0; i < sz; i++) { float s = 0.f; for (int j = 0; j < sz; j++) s += J[i * sz + j] * w[j]; v[i] = s; }
    zrot_apply(v, sz, l, a0, w);
    for (int i = 0; i < sz; i++) g_item[n * FEAT + (l * l + i) * REP + r] = w[i];
}

// ---------------- dense: relu(item@w0+b0) -> NHWC bf16 hi/lo ----------------
__global__ __launch_bounds__(256) void dense_kernel(const float* __restrict__ A,
                                                    const float* __restrict__ B,
                                                    const float* __restrict__ bias,
                                                    __nv_bfloat16* __restrict__ Chi,
                                                    __nv_bfloat16* __restrict__ Clo) {
    __shared__ float As[8][68];
    __shared__ float Bs[8][64];
    int tid = threadIdx.x;
    int bn = blockIdx.x, bm = blockIdx.y;
    int tx = tid & 15, ty = tid >> 4;
    u64 accp[4][2];
#pragma unroll
    for (int i = 0; i < 4; i++) { accp[i][0] = 0ull; accp[i][1] = 0ull; }

    int ka = tid & 7, ma = tid >> 3;
    int kb = tid >> 6, nb = tid & 63;
    const float* Ab = A + (size_t)(bm * 64) * FEAT;
    const float* Bb = B + bn * 64;

    for (int k0 = 0; k0 < FEAT; k0 += 8) {
        __syncthreads();
        As[ka][ma]      = Ab[(size_t)ma * FEAT + k0 + ka];
        As[ka][ma + 32] = Ab[(size_t)(ma + 32) * FEAT + k0 + ka];
        Bs[kb][nb]      = Bb[(size_t)(k0 + kb) * DENSE_N + nb];
        Bs[kb + 4][nb]  = Bb[(size_t)(k0 + kb + 4) * DENSE_N + nb];
        __syncthreads();
#pragma unroll
        for (int k = 0; k < 8; k++) {
            float4 a4 = *(const float4*)&As[k][ty * 4];
            ulonglong2 b2 = *(const ulonglong2*)&Bs[k][tx * 4];
            u64 ab[4] = {bcast2(a4.x), bcast2(a4.y), bcast2(a4.z), bcast2(a4.w)};
#pragma unroll
            for (int i = 0; i < 4; i++) {
                accp[i][0] = fma2(ab[i], b2.x, accp[i][0]);
                accp[i][1] = fma2(ab[i], b2.y, accp[i][1]);
            }
        }
    }
    float4 bi4 = *(const float4*)&bias[bn * 64 + tx * 4];
    float bv[4] = {bi4.x, bi4.y, bi4.z, bi4.w};
#pragma unroll
    for (int i = 0; i < 4; i++) {
        int m = bm * 64 + ty * 4 + i;
        float2 p0 = unpk2(accp[i][0]);
        float2 p1 = unpk2(accp[i][1]);
        float vals[4] = {fmaxf(p0.x + bv[0], 0.f), fmaxf(p0.y + bv[1], 0.f),
                         fmaxf(p1.x + bv[2], 0.f), fmaxf(p1.y + bv[3], 0.f)};
#pragma unroll
        for (int jj = 0; jj < 4; jj++) {
            int pix = tx * 4 + jj;
            size_t idx = ((size_t)m * 64 + pix) * 256 + bn;
            __nv_bfloat16 h = __float2bfloat16(vals[jj]);
            Chi[idx] = h;
            Clo[idx] = __float2bfloat16(vals[jj] - __bfloat162float(h));
        }
    }
}

// ---------------- weight repack + bf16 split: [parity][co][k=(tap,ci)] --------
__global__ void repack_w_kernel(const float* __restrict__ w, __nv_bfloat16* __restrict__ bhi,
                                __nv_bfloat16* __restrict__ blo, int COUT, int CIN) {
    int idx = blockIdx.x * 256 + threadIdx.x;
    int K = 4 * CIN;
    int total = 4 * COUT * K;
    if (idx >= total) return;
    int p = idx / (COUT * K);
    int r = idx % (COUT * K);
    int co = r / K;
    int k = r % K;
    int t = k / CIN, ci = k % CIN;
    int dy = t >> 1, dx = t & 1, ry = p >> 1, rx = p & 1;
    float v = w[((co * CIN + ci) * 4 + (2 * dy + ry)) * 4 + (2 * dx + rx)];
    __nv_bfloat16 h = __float2bfloat16(v);
    bhi[idx] = h;
    blo[idx] = __float2bfloat16(v - __bfloat162float(h));
}

// ---------------- HMMA implicit-GEMM deconv (K32 stages, 2 CTA/SM) ------------
template <int CIN, int COUT, int HIN, bool OUT_BF16>
__global__ __launch_bounds__(256, 2) void deconv_mma_kernel(
    const __nv_bfloat16* __restrict__ in_hi, const __nv_bfloat16* __restrict__ in_lo,
    const __nv_bfloat16* __restrict__ w_hi,  const __nv_bfloat16* __restrict__ w_lo,
    __nv_bfloat16* __restrict__ out_hi, __nv_bfloat16* __restrict__ out_lo,
    float* __restrict__ out_f) {
    constexpr int NSTAGE = 4 * CIN / 32;
    constexpr int HOUT = 2 * HIN;
    constexpr int PIX = HIN * HIN;
    constexpr int SROW = 80;             // 32 bf16 (64B) + 16B pad
    constexpr int ABYTES = 128 * SROW;
    constexpr int BBYTES = COUT * SROW;
    constexpr int STAGEB = 2 * ABYTES + 2 * BBYTES;
    constexpr int NF8 = COUT / 16;
    constexpr int NG  = COUT / 32;
    constexpr int BT4 = COUT * 4 / 256;  // B cp16 tasks per thread per tensor

    extern __shared__ __align__(16) char smem[];
    const u32 u0 = smem_to_u32(smem);

    const int tid = threadIdx.x;
    const int wid = tid >> 5;
    const int lid = tid & 31;
    const int wm = wid >> 1;
    const int wn = wid & 1;
    const int m0 = blockIdx.x * 128;
    const int par = blockIdx.y;
    const int ry = par >> 1, rx = par & 1;

    // per-thread A-copy geometry: 2 tasks of 16B per tensor
    int a_row[2], a_u4[2], a_qy[2], a_qx[2];
    size_t a_nb[2];
#pragma unroll
    for (int k = 0; k < 2; k++) {
        int idx = tid + k * 256;
        a_row[k] = idx >> 2;
        a_u4[k]  = idx & 3;
        int r = m0 + a_row[k];
        int n = r / PIX, q = r % PIX;
        a_qy[k] = q / HIN;
        a_qx[k] = q % HIN;
        a_nb[k] = (size_t)n * PIX * CIN;
    }

    auto load_stage = [&](int s, int buf) {
        const int t_tap = s / (CIN / 32);
        const int ci0   = (s % (CIN / 32)) * 32;
        const int dy = t_tap >> 1, dx = t_tap & 1;
        const u32 uAh = u0 + buf * STAGEB;
        const u32 uAl = uAh + ABYTES;
        const u32 uBh = uAh + 2 * ABYTES;
        const u32 uBl = uBh + BBYTES;
#pragma unroll
        for (int k = 0; k < 2; k++) {
            int y = a_qy[k] + dy - 1 + ry;
            int x = a_qx[k] + dx - 1 + rx;
            bool p = (y >= 0) && (y < HIN) && (x >= 0) && (x < HIN);
            int yc = p ? y : 0, xc = p ? x : 0;
            size_t base = a_nb[k] + ((size_t)yc * HIN + xc) * CIN + ci0 + a_u4[k] * 8;
            u32 doff = a_row[k] * SROW + a_u4[k] * 16;
            cp16(uAh + doff, &in_hi[base], p);
            cp16(uAl + doff, &in_lo[base], p);
        }
#pragma unroll
        for (int k = 0; k < BT4; k++) {
            int idx = tid + k * 256;
            int co = idx >> 2, u4 = idx & 3;
            size_t base = ((size_t)par * COUT + co) * (4 * CIN) + s * 32 + u4 * 8;
            u32 doff = co * SROW + u4 * 16;
            cp16(uBh + doff, &w_hi[base], true);
            cp16(uBl + doff, &w_lo[base], true);
        }
        cp_commit();
    };

    const int lrow = lid & 15;
    const int lcol = (lid >> 4) << 4;
    const int aoff0 = (wm * 32 + lrow) * SROW + lcol;
    const int aoff1 = aoff0 + 16 * SROW;
    int boff[NG];
#pragma unroll
    for (int g = 0; g < NG; g++) boff[g] = (wn * (COUT / 2) + g * 16 + lrow) * SROW + lcol;

    float acc[2][NF8][4];
#pragma unroll
    for (int t = 0; t < 2; t++)
#pragma unroll
        for (int f = 0; f < NF8; f++)
#pragma unroll
            for (int j = 0; j < 4; j++) acc[t][f][j] = 0.f;

    load_stage(0, 0);

    for (int s = 0; s < NSTAGE; s++) {
        const int buf = s & 1;
        if (s + 1 < NSTAGE) { load_stage(s + 1, buf ^ 1); cp_wait1(); }
        else                { cp_wait0(); }
        __syncthreads();

        const u32 uAh = u0 + buf * STAGEB;
        const u32 uAl = uAh + ABYTES;
        const u32 uBh = uAh + 2 * ABYTES;
        const u32 uBl = uBh + BBYTES;
#pragma unroll
        for (int ks = 0; ks < 2; ks++) {
            u32 ah[2][4], al[2][4];
            u32 bh[NG][4], bl[NG][4];
            ldsm4(ah[0], uAh + aoff0 + ks * 32);
            ldsm4(ah[1], uAh + aoff1 + ks * 32);
            ldsm4(al[0], uAl + aoff0 + ks * 32);
            ldsm4(al[1], uAl + aoff1 + ks * 32);
#pragma unroll
            for (int g = 0; g < NG; g++) {
                ldsm4(bh[g], uBh + boff[g] + ks * 32);
                ldsm4(bl[g], uBl + boff[g] + ks * 32);
            }
            // term-outermost: consecutive MMAs hit different accumulators
#pragma unroll
            for (int tm = 0; tm < 2; tm++)
#pragma unroll
                for (int g = 0; g < NG; g++)
#pragma unroll
                    for (int h = 0; h < 2; h++)
                        mma16816(acc[tm][g * 2 + h], ah[tm], bh[g][h], bh[g][h + 2]);
#pragma unroll
            for (int tm = 0; tm < 2; tm++)
#pragma unroll
                for (int g = 0; g < NG; g++)
#pragma unroll
                    for (int h = 0; h < 2; h++)
                        mma16816(acc[tm][g * 2 + h], ah[tm], bl[g][h], bl[g][h + 2]);
#pragma unroll
            for (int tm = 0; tm < 2; tm++)
#pragma unroll
                for (int g = 0; g < NG; g++)
#pragma unroll
                    for (int h = 0; h < 2; h++)
                        mma16816(acc[tm][g * 2 + h], al[tm], bh[g][h], bh[g][h + 2]);
        }
        __syncthreads();
    }

    // ---- epilogue: ReLU + NHWC store ----
#pragma unroll
    for (int tm = 0; tm < 2; tm++) {
        int r0 = m0 + wm * 32 + tm * 16 + (lid >> 2);
#pragma unroll
        for (int rr = 0; rr < 2; rr++) {
            int r = r0 + rr * 8;
            int n = r / PIX, q = r % PIX;
            int yo = 2 * (q / HIN) + ry;
            int xo = 2 * (q % HIN) + rx;
            size_t obase = (((size_t)n * HOUT + yo) * HOUT + xo) * COUT;
#pragma unroll
            for (int f = 0; f < NF8; f++) {
                int ch = wn * (COUT / 2) + f * 8 + (lid & 3) * 2;
                float v0 = fmaxf(acc[tm][f][rr * 2 + 0], 0.f);
                float v1 = fmaxf(acc[tm][f][rr * 2 + 1], 0.f);
                if (OUT_BF16) {
                    u32 hp = bf16pack(v0, v1);
                    float2 hf = bf16unpk(hp);
                    u32 lp = bf16pack(v0 - hf.x, v1 - hf.y);
                    *(u32*)&out_hi[obase + ch] = hp;
                    *(u32*)&out_lo[obase + ch] = lp;
                } else {
                    *(float2*)&out_f[obase + ch] = make_float2(v0, v1);
                }
            }
        }
    }
}

// ---------------- deconv3: 64 -> 3, NHWC fp32 input, NCHW output ----------------
__global__ __launch_bounds__(256) void deconv3_kernel(const float* __restrict__ in,
                                                      const float* __restrict__ wgt,
                                                      float* __restrict__ out) {
    int n = blockIdx.x;
    __shared__ float sin_[34 * 34 * 4];
    __shared__ float wsm[3 * 64 * 16 * 2];
    int tid = threadIdx.x;

    for (int idx = tid; idx < 3072; idx += 256) {
        int tap = idx & 15;
        int cc = idx >> 4;
        int co = cc % 3, ci = cc / 3;
        float w = wgt[(co * 64 + ci) * 16 + tap];
        wsm[((ci * 3 + co) * 16 + tap) * 2 + 0] = w;
        wsm[((ci * 3 + co) * 16 + tap) * 2 + 1] = w;
    }

    int qy0 = (tid >> 4) * 2;
    int qx0 = (tid & 15) * 2;
    u64 accp[3][8];
#pragma unroll
    for (int c = 0; c < 3; c++)
#pragma unroll
        for (int i = 0; i < 8; i++) accp[c][i] = 0ull;

    const float* in_n = in + (size_t)n * 1024 * 64;
    for (int ci0 = 0; ci0 < 64; ci0 += 4) {
        __syncthreads();
        for (int idx = tid; idx < 1156; idx += 256) {
            int py = idx / 34, px = idx % 34;
            int y = py - 1, x = px - 1;
            float4 v = make_float4(0.f, 0.f, 0.f, 0.f);
            if (y >= 0 && y < 32 && x >= 0 && x < 32)
                v = *(const float4*)&in_n[(y * 32 + x) * 64 + ci0];
            *(float4*)&sin_[idx * 4] = v;
        }
        __syncthreads();
#pragma unroll 1
        for (int ci = 0; ci < 4; ci++) {
            float iv[4][4];
#pragma unroll
            for (int yy = 0; yy < 4; yy++)
#pragma unroll
                for (int xx = 0; xx < 4; xx++)
                    iv[yy][xx] = sin_[((qy0 + yy) * 34 + qx0 + xx) * 4 + ci];
            u64 ivp2[4][3];
#pragma unroll
            for (int yy = 0; yy < 4; yy++)
#pragma unroll
                for (int xx = 0; xx < 3; xx++)
                    ivp2[yy][xx] = pack2(iv[yy][xx], iv[yy][xx + 1]);
#pragma unroll
            for (int co = 0; co < 3; co++) {
#pragma unroll
                for (int tap = 0; tap < 16; tap++) {
                    const int ky = tap >> 2, kx = tap & 3;
                    const int ry = ky & 1, dy = ky >> 1;
                    const int rx = kx & 1, dx = kx >> 1;
                    u64 wp = *(const u64*)&wsm[(((ci0 + ci) * 3 + co) * 16 + tap) * 2];
#pragma unroll
                    for (int qy = 0; qy < 2; qy++) {
                        const int o = qy * 4 + ry * 2 + rx;
                        accp[co][o] = fma2(wp, ivp2[qy + dy + ry][dx + rx], accp[co][o]);
                    }
                }
            }
        }
    }
    float* out_n = out + (size_t)n * 3 * 4096;
#pragma unroll
    for (int co = 0; co < 3; co++)
#pragma unroll
        for (int qy = 0; qy < 2; qy++)
#pragma unroll
            for (int ry = 0; ry < 2; ry++)
#pragma unroll
                for (int rx = 0; rx < 2; rx++) {
                    float2 v = unpk2(accp[co][qy * 4 + ry * 2 + rx]);
                    int yo = 2 * (qy0 + qy) + ry;
                    int xo0 = 2 * (qx0 + 0) + rx;
                    int xo1 = 2 * (qx0 + 1) + rx;
                    out_n[co * 4096 + yo * 64 + xo0] = v.x;
                    out_n[co * 4096 + yo * 64 + xo1] = v.y;
                }
}

// -----------------------------------------------------------------------------------------
extern "C" void kernel_launch(void* const* d_in, const int* in_sizes, int n_in,
                              void* d_out, int out_size) {
    (void)in_sizes; (void)n_in; (void)out_size;
    const float* angles   = (const float*)d_in[0];
    const float* item_rep = (const float*)d_in[1];
    const float* w0       = (const float*)d_in[2];
    const float* b0       = (const float*)d_in[3];
    const float* w1       = (const float*)d_in[4];
    const float* w2       = (const float*)d_in[5];
    const float* w3       = (const float*)d_in[6];
    float* out = (float*)d_out;

    float *p_item, *p_h2;
    cudaGetSymbolAddress((void**)&p_item, g_item);
    cudaGetSymbolAddress((void**)&p_h2, g_h2);
    __nv_bfloat16 *p_h0hi, *p_h0lo, *p_h1hi, *p_h1lo;
    cudaGetSymbolAddress((void**)&p_h0hi, g_h0hi);
    cudaGetSymbolAddress((void**)&p_h0lo, g_h0lo);
    cudaGetSymbolAddress((void**)&p_h1hi, g_h1hi);
    cudaGetSymbolAddress((void**)&p_h1lo, g_h1lo);
    __nv_bfloat16 *p_w1hi, *p_w1lo, *p_w2hi, *p_w2lo;
    cudaGetSymbolAddress((void**)&p_w1hi, g_w1hi);
    cudaGetSymbolAddress((void**)&p_w1lo, g_w1lo);
    cudaGetSymbolAddress((void**)&p_w2hi, g_w2hi);
    cudaGetSymbolAddress((void**)&p_w2lo, g_w2lo);

    constexpr int SMEM1 = 2 * (2 * 128 * 80 + 2 * 128 * 80);  // 81920 -> 2 CTA/SM
    constexpr int SMEM2 = 2 * (2 * 128 * 80 + 2 * 64 * 80);   // 61440 -> 2-3 CTA/SM
    cudaFuncSetAttribute(deconv_mma_kernel<256, 128, 8, true>,
                         cudaFuncAttributeMaxDynamicSharedMemorySize, SMEM1);
    cudaFuncSetAttribute(deconv_mma_kernel<128, 64, 16, false>,
                         cudaFuncAttributeMaxDynamicSharedMemorySize, SMEM2);

    init_jd_kernel<<<1, 288>>>();
    repack_w_kernel<<<(4 * 128 * 1024) / 256, 256>>>(w1, p_w1hi, p_w1lo, 128, 256);
    repack_w_kernel<<<(4 * 64 * 512) / 256, 256>>>(w2, p_w2hi, p_w2lo, 64, 128);
    wigner_kernel<<<(N_SAMP * REP * 6 + 127) / 128, 128>>>(angles, item_rep);
    dense_kernel<<<dim3(DENSE_N / 64, N_SAMP / 64), 256>>>(p_item, w0, b0, p_h0hi, p_h0lo);
    deconv_mma_kernel<256, 128, 8, true><<<dim3(1024, 4), 256, SMEM1>>>(
        p_h0hi, p_h0lo, p_w1hi, p_w1lo, p_h1hi, p_h1lo, nullptr);
    deconv_mma_kernel<128, 64, 16, false><<<dim3(4096, 4), 256, SMEM2>>>(
        p_h1hi, p_h1lo, p_w2hi, p_w2lo, nullptr, nullptr, p_h2);
    deconv3_kernel<<<N_SAMP, 256>>>(p_h2, w3, out);
}

// round 7
// speedup vs baseline: 1.0617x; 1.0617x over previous
#include <cuda_runtime.h>
#include <cuda_bf16.h>
#include <math.h>
#include <stdint.h>

typedef unsigned int u32;
typedef unsigned long long u64;

#define N_SAMP 2048
#define MDIMS  36
#define REP    10
#define FEAT   360
#define DENSE_N 16384        // 256*8*8

// ---------------- packed f32x2 helpers ----------------
__device__ __forceinline__ u64 fma2(u64 a, u64 b, u64 c) {
    u64 d;
    asm("fma.rn.f32x2 %0, %1, %2, %3;" : "=l"(d) : "l"(a), "l"(b), "l"(c));
    return d;
}
__device__ __forceinline__ u64 bcast2(float x) {
    u64 r; unsigned xi = __float_as_uint(x);
    asm("mov.b64 %0, {%1, %2};" : "=l"(r) : "r"(xi), "r"(xi));
    return r;
}
__device__ __forceinline__ u64 pack2(float lo, float hi) {
    u64 r; unsigned a = __float_as_uint(lo), b = __float_as_uint(hi);
    asm("mov.b64 %0, {%1, %2};" : "=l"(r) : "r"(a), "r"(b));
    return r;
}
__device__ __forceinline__ float2 unpk2(u64 p) {
    unsigned lo, hi;
    asm("mov.b64 {%0, %1}, %2;" : "=r"(lo), "=r"(hi) : "l"(p));
    return make_float2(__uint_as_float(lo), __uint_as_float(hi));
}

// ---------------- bf16 pack/unpack ----------------
__device__ __forceinline__ u32 bf16pack(float lo, float hi) {
    u32 r;
    asm("cvt.rn.satfinite.bf16x2.f32 %0, %1, %2;" : "=r"(r) : "f"(hi), "f"(lo));
    return r;
}
__device__ __forceinline__ float2 bf16unpk(u32 u) {
    __nv_bfloat162 h = *reinterpret_cast<__nv_bfloat162*>(&u);
    return __bfloat1622float2(h);
}

// ---------------- warp MMA + cp.async helpers ----------------
__device__ __forceinline__ u32 smem_to_u32(const void* p) {
    u32 a;
    asm("{ .reg .u64 t; cvta.to.shared.u64 t, %1; cvt.u32.u64 %0, t; }" : "=r"(a) : "l"(p));
    return a;
}
__device__ __forceinline__ void ldsm4(u32* r, u32 addr) {
    asm volatile("ldmatrix.sync.aligned.m8n8.x4.shared.b16 {%0,%1,%2,%3}, [%4];"
                 : "=r"(r[0]), "=r"(r[1]), "=r"(r[2]), "=r"(r[3]) : "r"(addr));
}
__device__ __forceinline__ void mma16816(float* d, const u32* a, u32 b0, u32 b1) {
    asm volatile(
        "mma.sync.aligned.m16n8k16.row.col.f32.bf16.bf16.f32 "
        "{%0,%1,%2,%3}, {%4,%5,%6,%7}, {%8,%9}, {%0,%1,%2,%3};"
        : "+f"(d[0]), "+f"(d[1]), "+f"(d[2]), "+f"(d[3])
        : "r"(a[0]), "r"(a[1]), "r"(a[2]), "r"(a[3]), "r"(b0), "r"(b1));
}
__device__ __forceinline__ void cp16(u32 dst, const void* src, bool p) {
    asm volatile("cp.async.cg.shared.global [%0], [%1], 16, %2;"
                 :: "r"(dst), "l"(src), "r"(p ? 16 : 0) : "memory");
}
__device__ __forceinline__ void cp_commit() {
    asm volatile("cp.async.commit_group;" ::: "memory");
}
__device__ __forceinline__ void cp_wait1() {
    asm volatile("cp.async.wait_group 1;" ::: "memory");
}
__device__ __forceinline__ void cp_wait0() {
    asm volatile("cp.async.wait_group 0;" ::: "memory");
}

// ---------------- scratch ----------------
__device__ float g_JD[286];
__device__ float g_item[N_SAMP * FEAT];
__device__ __align__(16) __nv_bfloat16 g_h0hi[N_SAMP * 16384];      // NHWC [n,8,8,256]
__device__ __align__(16) __nv_bfloat16 g_h0lo[N_SAMP * 16384];
__device__ __align__(16) __nv_bfloat16 g_h1hi[N_SAMP * 256 * 128];  // NHWC [n,16,16,128]
__device__ __align__(16) __nv_bfloat16 g_h1lo[N_SAMP * 256 * 128];
__device__ __align__(16) float g_h2[N_SAMP * 1024 * 64];            // NHWC [n,32,32,64] fp32
__device__ __align__(16) __nv_bfloat16 g_w1hi[4 * 128 * 1024];      // [par][chunk][co][tap*32+ci]
__device__ __align__(16) __nv_bfloat16 g_w1lo[4 * 128 * 1024];
__device__ __align__(16) __nv_bfloat16 g_w2hi[4 * 64 * 512];
__device__ __align__(16) __nv_bfloat16 g_w2lo[4 * 64 * 512];

__device__ __constant__ int c_off[7] = {0, 1, 10, 35, 84, 165, 286};

// ---------------- J_l init ----------------
__device__ double dfact(int n) { double r = 1.0; for (int i = 2; i <= n; i++) r *= (double)i; return r; }

__device__ double small_d(int l, int mp, int m) {
    const double ch = 0.70710678118654752440, sh = 0.70710678118654752440;
    double pref = sqrt(dfact(l + mp) * dfact(l - mp) * dfact(l + m) * dfact(l - m));
    int smin = max(0, m - mp), smax = min(l + m, l - mp);
    double tot = 0.0;
    for (int s = smin; s <= smax; s++) {
        double sign = ((mp - m + s) & 1) ? -1.0 : 1.0;
        double denom = dfact(l + m - s) * dfact(s) * dfact(mp - m + s) * dfact(l - mp - s);
        tot += sign / denom * pow(ch, (double)(2 * l + m - mp - 2 * s)) * pow(sh, (double)(mp - m + 2 * s));
    }
    return pref * tot;
}

__device__ void c2r_row(int l, int i, int* col, double* re, double* im, int* cnt) {
    int m = i - l;
    const double s = 0.70710678118654752440;
    if (m < 0) {
        double sgn = (m & 1) ? -1.0 : 1.0;
        col[0] = l + m; re[0] = 0.0; im[0] = s;
        col[1] = l - m; re[1] = 0.0; im[1] = -sgn * s;
        *cnt = 2;
    } else if (m == 0) {
        col[0] = l; re[0] = 1.0; im[0] = 0.0; *cnt = 1;
    } else {
        double sgn = (m & 1) ? -1.0 : 1.0;
        col[0] = l - m; re[0] = s;        im[0] = 0.0;
        col[1] = l + m; re[1] = sgn * s;  im[1] = 0.0;
        *cnt = 2;
    }
}

__global__ void init_jd_kernel() {
    int idx = threadIdx.x;
    if (idx >= 286) return;
    int l = 0;
    while (idx >= c_off[l + 1]) l++;
    int e = idx - c_off[l];
    int sz = 2 * l + 1;
    int i = e / sz, j = e % sz;
    int ca_c[2], cb_c[2], na, nb;
    double ca_re[2], ca_im[2], cb_re[2], cb_im[2];
    c2r_row(l, i, ca_c, ca_re, ca_im, &na);
    c2r_row(l, j, cb_c, cb_re, cb_im, &nb);
    double acc = 0.0;
    for (int a = 0; a < na; a++)
        for (int b = 0; b < nb; b++) {
            double cross = ca_re[a] * cb_re[b] + ca_im[a] * cb_im[b];
            if (cross != 0.0) acc += cross * small_d(l, ca_c[a] - l, cb_c[b] - l);
        }
    g_JD[idx] = (float)acc;
}

// ---------------- Wigner (parallel over l) ----------------
__device__ __forceinline__ void zrot_apply(const float* v, int sz, int l, float ang, float* out) {
    for (int i = 0; i < sz; i++) {
        float f = (float)(l - i);
        float s, c;
        sincosf(f * ang, &s, &c);
        out[i] = c * v[i] + s * v[sz - 1 - i];
    }
}

__global__ void wigner_kernel(const float* __restrict__ angles, const float* __restrict__ item_rep) {
    int t = blockIdx.x * blockDim.x + threadIdx.x;
    if (t >= N_SAMP * REP * 6) return;
    int l = t % 6;
    int nr = t / 6;
    int n = nr / REP, r = nr % REP;
    float a0 = angles[n * 3 + 0], a1 = angles[n * 3 + 1], a2 = angles[n * 3 + 2];
    float v[11], w[11];
    int sz = 2 * l + 1;
    const float* J = &g_JD[c_off[l]];
    for (int i = 0; i < sz; i++) v[i] = item_rep[(l * l + i) * REP + r];
    zrot_apply(v, sz, l, a2, w);
    for (int i = 0; i < sz; i++) { float s = 0.f; for (int j = 0; j < sz; j++) s += J[i * sz + j] * w[j]; v[i] = s; }
    zrot_apply(v, sz, l, a1, w);
    for (int i = 0; i < sz; i++) { float s = 0.f; for (int j = 0; j < sz; j++) s += J[i * sz + j] * w[j]; v[i] = s; }
    zrot_apply(v, sz, l, a0, w);
    for (int i = 0; i < sz; i++) g_item[n * FEAT + (l * l + i) * REP + r] = w[i];
}

// ---------------- dense: relu(item@w0+b0) -> NHWC bf16 hi/lo ----------------
__global__ __launch_bounds__(256) void dense_kernel(const float* __restrict__ A,
                                                    const float* __restrict__ B,
                                                    const float* __restrict__ bias,
                                                    __nv_bfloat16* __restrict__ Chi,
                                                    __nv_bfloat16* __restrict__ Clo) {
    __shared__ float As[8][68];
    __shared__ float Bs[8][64];
    int tid = threadIdx.x;
    int bn = blockIdx.x, bm = blockIdx.y;
    int tx = tid & 15, ty = tid >> 4;
    u64 accp[4][2];
#pragma unroll
    for (int i = 0; i < 4; i++) { accp[i][0] = 0ull; accp[i][1] = 0ull; }

    int ka = tid & 7, ma = tid >> 3;
    int kb = tid >> 6, nb = tid & 63;
    const float* Ab = A + (size_t)(bm * 64) * FEAT;
    const float* Bb = B + bn * 64;

    for (int k0 = 0; k0 < FEAT; k0 += 8) {
        __syncthreads();
        As[ka][ma]      = Ab[(size_t)ma * FEAT + k0 + ka];
        As[ka][ma + 32] = Ab[(size_t)(ma + 32) * FEAT + k0 + ka];
        Bs[kb][nb]      = Bb[(size_t)(k0 + kb) * DENSE_N + nb];
        Bs[kb + 4][nb]  = Bb[(size_t)(k0 + kb + 4) * DENSE_N + nb];
        __syncthreads();
#pragma unroll
        for (int k = 0; k < 8; k++) {
            float4 a4 = *(const float4*)&As[k][ty * 4];
            ulonglong2 b2 = *(const ulonglong2*)&Bs[k][tx * 4];
            u64 ab[4] = {bcast2(a4.x), bcast2(a4.y), bcast2(a4.z), bcast2(a4.w)};
#pragma unroll
            for (int i = 0; i < 4; i++) {
                accp[i][0] = fma2(ab[i], b2.x, accp[i][0]);
                accp[i][1] = fma2(ab[i], b2.y, accp[i][1]);
            }
        }
    }
    float4 bi4 = *(const float4*)&bias[bn * 64 + tx * 4];
    float bv[4] = {bi4.x, bi4.y, bi4.z, bi4.w};
#pragma unroll
    for (int i = 0; i < 4; i++) {
        int m = bm * 64 + ty * 4 + i;
        float2 p0 = unpk2(accp[i][0]);
        float2 p1 = unpk2(accp[i][1]);
        float vals[4] = {fmaxf(p0.x + bv[0], 0.f), fmaxf(p0.y + bv[1], 0.f),
                         fmaxf(p1.x + bv[2], 0.f), fmaxf(p1.y + bv[3], 0.f)};
#pragma unroll
        for (int jj = 0; jj < 4; jj++) {
            int pix = tx * 4 + jj;
            size_t idx = ((size_t)m * 64 + pix) * 256 + bn;
            __nv_bfloat16 h = __float2bfloat16(vals[jj]);
            Chi[idx] = h;
            Clo[idx] = __float2bfloat16(vals[jj] - __bfloat162float(h));
        }
    }
}

// ------- weight repack + split: [par][chunk(32ci)][co][tap*32 + ci_in] -------
__global__ void repack_w_kernel(const float* __restrict__ w, __nv_bfloat16* __restrict__ bhi,
                                __nv_bfloat16* __restrict__ blo, int COUT, int CIN) {
    int idx = blockIdx.x * 256 + threadIdx.x;
    int NCHUNK = CIN / 32;
    int total = 4 * NCHUNK * COUT * 128;
    if (idx >= total) return;
    int cii = idx & 31;
    int tap = (idx >> 5) & 3;
    int co  = (idx >> 7) % COUT;
    int chunk = (idx / (128 * COUT)) % NCHUNK;
    int par = idx / (128 * COUT * NCHUNK);
    int ci = chunk * 32 + cii;
    int dy = tap >> 1, dx = tap & 1, ry = par >> 1, rx = par & 1;
    float v = w[((co * CIN + ci) * 4 + (2 * dy + ry)) * 4 + (2 * dx + rx)];
    __nv_bfloat16 h = __float2bfloat16(v);
    bhi[idx] = h;
    blo[idx] = __float2bfloat16(v - __bfloat162float(h));
}

// ------- HMMA implicit-GEMM deconv with shared halo patch across taps --------
// SampleMode (HIN==8): CTA = 2 samples, parity = blockIdx.y (0..3).
// RowMode (HIN==16, MERGE_RX): CTA = 128 pixel rows, ry = blockIdx.y (0..1),
//   both rx parities computed from one patch.
template <int CIN, int COUT, int HIN, bool MERGE_RX, bool OUT_BF16>
__global__ __launch_bounds__(256) void deconv_mma_kernel(
    const __nv_bfloat16* __restrict__ in_hi, const __nv_bfloat16* __restrict__ in_lo,
    const __nv_bfloat16* __restrict__ w_hi,  const __nv_bfloat16* __restrict__ w_lo,
    __nv_bfloat16* __restrict__ out_hi, __nv_bfloat16* __restrict__ out_lo,
    float* __restrict__ out_f) {
    constexpr int NCHUNK = CIN / 32;
    constexpr int HOUT = 2 * HIN;
    constexpr int PIX = HIN * HIN;
    constexpr bool SAMPLE_MODE = (HIN == 8);
    constexpr int PW = SAMPLE_MODE ? 9 : 18;
    constexpr int SLOTS = 162;               // 2*81 or 9*18
    constexpr int SROW = 80;                 // 32 ci * 2B + 16 pad
    constexpr int ABYTES = 164 * SROW;       // padded
    constexpr int SROWB = 272;               // 128 k * 2B + 16 pad
    constexpr int BROWS = (MERGE_RX ? 2 : 1) * COUT;   // 128 in both layers
    constexpr int BBYTES = BROWS * SROWB;
    constexpr int STAGEB = 2 * ABYTES + 2 * BBYTES;
    constexpr int NPAR = MERGE_RX ? 2 : 1;
    constexpr int NG = COUT / 32;            // ldsm n-groups per warp
    constexpr int NF8 = COUT / 16;           // n8 frags per warp

    extern __shared__ __align__(16) char smem[];
    const u32 u0 = smem_to_u32(smem);

    const int tid = threadIdx.x;
    const int wid = tid >> 5;
    const int lid = tid & 31;
    const int wm = wid >> 1;
    const int wn = wid & 1;
    const int par = blockIdx.y;
    const int ry = MERGE_RX ? par : (par >> 1);
    const int rx0 = MERGE_RX ? 0 : (par & 1);
    const int m0 = blockIdx.x * 128;         // RowMode: global pixel-row base
    const int n0 = SAMPLE_MODE ? blockIdx.x * 2 : (m0 >> 8);
    const int qy0 = SAMPLE_MODE ? 0 : ((m0 & 255) >> 4);

    auto load_stage = [&](int s, int buf) {
        const int ci0 = s * 32;
        const u32 uAh = u0 + buf * STAGEB;
        const u32 uAl = uAh + ABYTES;
        const u32 uBh = uAh + 2 * ABYTES;
        const u32 uBl = uBh + BBYTES;
        for (int idx = tid; idx < SLOTS * 4; idx += 256) {
            int slot = idx >> 2, qd = idx & 3;
            int n, y, x;
            if (SAMPLE_MODE) {
                int smp = slot / 81, rr = slot % 81;
                n = n0 + smp;
                y = rr / 9 - 1 + ry;
                x = rr % 9 - 1 + rx0;
            } else {
                n = n0;
                y = slot / 18 + qy0 - 1 + ry;
                x = slot % 18 - 1;
            }
            bool p = (y >= 0) && (y < HIN) && (x >= 0) && (x < HIN);
            int yc = p ? y : 0, xc = p ? x : 0;
            size_t base = (((size_t)n * HIN + yc) * HIN + xc) * CIN + ci0 + qd * 8;
            u32 doff = slot * SROW + qd * 16;
            cp16(uAh + doff, &in_hi[base], p);
            cp16(uAl + doff, &in_lo[base], p);
        }
        for (int idx = tid; idx < BROWS * 16; idx += 256) {
            int row = idx >> 4, qd = idx & 15;
            int co, wpar;
            if (MERGE_RX) { co = row % COUT; wpar = ry * 2 + (row / COUT); }
            else          { co = row;        wpar = par; }
            size_t base = (((size_t)(wpar * NCHUNK + s) * COUT + co) << 7) + qd * 8;
            u32 doff = row * SROWB + qd * 16;
            cp16(uBh + doff, &w_hi[base], true);
            cp16(uBl + doff, &w_lo[base], true);
        }
        cp_commit();
    };

    // per-lane A base slot for the two m16 tiles
    const int lrow = lid & 15;
    const int lcol = (lid >> 4) << 4;
    int bslot[2];
#pragma unroll
    for (int tm = 0; tm < 2; tm++) {
        int row = wm * 32 + tm * 16 + lrow;
        if (SAMPLE_MODE) {
            int smp = row >> 6, q = row & 63;
            bslot[tm] = smp * 81 + (q >> 3) * 9 + (q & 7);
        } else {
            int q = (m0 + row) & 255;
            bslot[tm] = ((q >> 4) - qy0) * PW + (q & 15);
        }
    }

    float acc[NPAR][2][NF8][4];
#pragma unroll
    for (int p = 0; p < NPAR; p++)
#pragma unroll
        for (int t = 0; t < 2; t++)
#pragma unroll
            for (int f = 0; f < NF8; f++)
#pragma unroll
                for (int j = 0; j < 4; j++) acc[p][t][f][j] = 0.f;

    load_stage(0, 0);

    for (int s = 0; s < NCHUNK; s++) {
        const int buf = s & 1;
        if (s + 1 < NCHUNK) { load_stage(s + 1, buf ^ 1); cp_wait1(); }
        else                { cp_wait0(); }
        __syncthreads();

        const u32 uAh = u0 + buf * STAGEB;
        const u32 uAl = uAh + ABYTES;
        const u32 uBh = uAh + 2 * ABYTES;
        const u32 uBl = uBh + BBYTES;
#pragma unroll
        for (int tap = 0; tap < 4; tap++) {
            const int dy = tap >> 1, dx = tap & 1;
#pragma unroll
            for (int ks = 0; ks < 2; ks++) {
#pragma unroll
                for (int prx = 0; prx < NPAR; prx++) {
                    u32 ah[2][4], al[2][4];
#pragma unroll
                    for (int tm = 0; tm < 2; tm++) {
                        u32 aaddr = (u32)((bslot[tm] + dy * PW + dx + prx) * SROW) + ks * 32 + lcol;
                        ldsm4(ah[tm], uAh + aaddr);
                        ldsm4(al[tm], uAl + aaddr);
                    }
                    u32 bh[NG][4], bl[NG][4];
#pragma unroll
                    for (int g = 0; g < NG; g++) {
                        u32 baddr = (u32)((prx * COUT + wn * (COUT / 2) + g * 16 + lrow) * SROWB)
                                    + tap * 64 + ks * 32 + lcol;
                        ldsm4(bh[g], uBh + baddr);
                        ldsm4(bl[g], uBl + baddr);
                    }
                    // 3 split terms, term-outermost
#pragma unroll
                    for (int tm = 0; tm < 2; tm++)
#pragma unroll
                        for (int g = 0; g < NG; g++)
#pragma unroll
                            for (int h = 0; h < 2; h++)
                                mma16816(acc[prx][tm][g * 2 + h], ah[tm], bh[g][h], bh[g][h + 2]);
#pragma unroll
                    for (int tm = 0; tm < 2; tm++)
#pragma unroll
                        for (int g = 0; g < NG; g++)
#pragma unroll
                            for (int h = 0; h < 2; h++)
                                mma16816(acc[prx][tm][g * 2 + h], ah[tm], bl[g][h], bl[g][h + 2]);
#pragma unroll
                    for (int tm = 0; tm < 2; tm++)
#pragma unroll
                        for (int g = 0; g < NG; g++)
#pragma unroll
                            for (int h = 0; h < 2; h++)
                                mma16816(acc[prx][tm][g * 2 + h], al[tm], bh[g][h], bh[g][h + 2]);
                }
            }
        }
        __syncthreads();
    }

    // ---- epilogue: ReLU + NHWC store ----
#pragma unroll
    for (int prx = 0; prx < NPAR; prx++) {
        const int rx = MERGE_RX ? prx : rx0;
#pragma unroll
        for (int tm = 0; tm < 2; tm++) {
            int r0 = wm * 32 + tm * 16 + (lid >> 2);
#pragma unroll
            for (int rr = 0; rr < 2; rr++) {
                int r = r0 + rr * 8;
                int n, yo, xo;
                if (SAMPLE_MODE) {
                    n = n0 + (r >> 6);
                    int q = r & 63;
                    yo = 2 * (q >> 3) + ry;
                    xo = 2 * (q & 7) + rx;
                } else {
                    int R = m0 + r;
                    n = R >> 8;
                    int q = R & 255;
                    yo = 2 * (q >> 4) + ry;
                    xo = 2 * (q & 15) + rx;
                }
                size_t obase = (((size_t)n * HOUT + yo) * HOUT + xo) * COUT;
#pragma unroll
                for (int f = 0; f < NF8; f++) {
                    int ch = wn * (COUT / 2) + f * 8 + (lid & 3) * 2;
                    float v0 = fmaxf(acc[prx][tm][f][rr * 2 + 0], 0.f);
                    float v1 = fmaxf(acc[prx][tm][f][rr * 2 + 1], 0.f);
                    if (OUT_BF16) {
                        u32 hp = bf16pack(v0, v1);
                        float2 hf = bf16unpk(hp);
                        u32 lp = bf16pack(v0 - hf.x, v1 - hf.y);
                        *(u32*)&out_hi[obase + ch] = hp;
                        *(u32*)&out_lo[obase + ch] = lp;
                    } else {
                        *(float2*)&out_f[obase + ch] = make_float2(v0, v1);
                    }
                }
            }
        }
    }
}

// ---------------- deconv3: 64 -> 3, NHWC fp32 input, NCHW output ----------------
__global__ __launch_bounds__(256) void deconv3_kernel(const float* __restrict__ in,
                                                      const float* __restrict__ wgt,
                                                      float* __restrict__ out) {
    int n = blockIdx.x;
    __shared__ float sin_[34 * 34 * 4];
    __shared__ float wsm[3 * 64 * 16 * 2];
    int tid = threadIdx.x;

    for (int idx = tid; idx < 3072; idx += 256) {
        int tap = idx & 15;
        int cc = idx >> 4;
        int co = cc % 3, ci = cc / 3;
        float w = wgt[(co * 64 + ci) * 16 + tap];
        wsm[((ci * 3 + co) * 16 + tap) * 2 + 0] = w;
        wsm[((ci * 3 + co) * 16 + tap) * 2 + 1] = w;
    }

    int qy0 = (tid >> 4) * 2;
    int qx0 = (tid & 15) * 2;
    u64 accp[3][8];
#pragma unroll
    for (int c = 0; c < 3; c++)
#pragma unroll
        for (int i = 0; i < 8; i++) accp[c][i] = 0ull;

    const float* in_n = in + (size_t)n * 1024 * 64;
    for (int ci0 = 0; ci0 < 64; ci0 += 4) {
        __syncthreads();
        for (int idx = tid; idx < 1156; idx += 256) {
            int py = idx / 34, px = idx % 34;
            int y = py - 1, x = px - 1;
            float4 v = make_float4(0.f, 0.f, 0.f, 0.f);
            if (y >= 0 && y < 32 && x >= 0 && x < 32)
                v = *(const float4*)&in_n[(y * 32 + x) * 64 + ci0];
            *(float4*)&sin_[idx * 4] = v;
        }
        __syncthreads();
#pragma unroll 1
        for (int ci = 0; ci < 4; ci++) {
            float iv[4][4];
#pragma unroll
            for (int yy = 0; yy < 4; yy++)
#pragma unroll
                for (int xx = 0; xx < 4; xx++)
                    iv[yy][xx] = sin_[((qy0 + yy) * 34 + qx0 + xx) * 4 + ci];
            u64 ivp2[4][3];
#pragma unroll
            for (int yy = 0; yy < 4; yy++)
#pragma unroll
                for (int xx = 0; xx < 3; xx++)
                    ivp2[yy][xx] = pack2(iv[yy][xx], iv[yy][xx + 1]);
#pragma unroll
            for (int co = 0; co < 3; co++) {
#pragma unroll
                for (int tap = 0; tap < 16; tap++) {
                    const int ky = tap >> 2, kx = tap & 3;
                    const int ry = ky & 1, dy = ky >> 1;
                    const int rx = kx & 1, dx = kx >> 1;
                    u64 wp = *(const u64*)&wsm[(((ci0 + ci) * 3 + co) * 16 + tap) * 2];
#pragma unroll
                    for (int qy = 0; qy < 2; qy++) {
                        const int o = qy * 4 + ry * 2 + rx;
                        accp[co][o] = fma2(wp, ivp2[qy + dy + ry][dx + rx], accp[co][o]);
                    }
                }
            }
        }
    }
    float* out_n = out + (size_t)n * 3 * 4096;
#pragma unroll
    for (int co = 0; co < 3; co++)
#pragma unroll
        for (int qy = 0; qy < 2; qy++)
#pragma unroll
            for (int ry = 0; ry < 2; ry++)
#pragma unroll
                for (int rx = 0; rx < 2; rx++) {
                    float2 v = unpk2(accp[co][qy * 4 + ry * 2 + rx]);
                    int yo = 2 * (qy0 + qy) + ry;
                    int xo0 = 2 * (qx0 + 0) + rx;
                    int xo1 = 2 * (qx0 + 1) + rx;
                    out_n[co * 4096 + yo * 64 + xo0] = v.x;
                    out_n[co * 4096 + yo * 64 + xo1] = v.y;
                }
}

// -----------------------------------------------------------------------------------------
extern "C" void kernel_launch(void* const* d_in, const int* in_sizes, int n_in,
                              void* d_out, int out_size) {
    (void)in_sizes; (void)n_in; (void)out_size;
    const float* angles   = (const float*)d_in[0];
    const float* item_rep = (const float*)d_in[1];
    const float* w0       = (const float*)d_in[2];
    const float* b0       = (const float*)d_in[3];
    const float* w1       = (const float*)d_in[4];
    const float* w2       = (const float*)d_in[5];
    const float* w3       = (const float*)d_in[6];
    float* out = (float*)d_out;

    float *p_item, *p_h2;
    cudaGetSymbolAddress((void**)&p_item, g_item);
    cudaGetSymbolAddress((void**)&p_h2, g_h2);
    __nv_bfloat16 *p_h0hi, *p_h0lo, *p_h1hi, *p_h1lo;
    cudaGetSymbolAddress((void**)&p_h0hi, g_h0hi);
    cudaGetSymbolAddress((void**)&p_h0lo, g_h0lo);
    cudaGetSymbolAddress((void**)&p_h1hi, g_h1hi);
    cudaGetSymbolAddress((void**)&p_h1lo, g_h1lo);
    __nv_bfloat16 *p_w1hi, *p_w1lo, *p_w2hi, *p_w2lo;
    cudaGetSymbolAddress((void**)&p_w1hi, g_w1hi);
    cudaGetSymbolAddress((void**)&p_w1lo, g_w1lo);
    cudaGetSymbolAddress((void**)&p_w2hi, g_w2hi);
    cudaGetSymbolAddress((void**)&p_w2lo, g_w2lo);

    // STAGEB = 2*164*80 + 2*128*272 = 95872 ; x2 buffers
    constexpr int SMEMD = 2 * (2 * 164 * 80 + 2 * 128 * 272);  // 191744
    cudaFuncSetAttribute(deconv_mma_kernel<256, 128, 8, false, true>,
                         cudaFuncAttributeMaxDynamicSharedMemorySize, SMEMD);
    cudaFuncSetAttribute(deconv_mma_kernel<128, 64, 16, true, false>,
                         cudaFuncAttributeMaxDynamicSharedMemorySize, SMEMD);

    init_jd_kernel<<<1, 288>>>();
    repack_w_kernel<<<(4 * 8 * 128 * 128) / 256, 256>>>(w1, p_w1hi, p_w1lo, 128, 256);
    repack_w_kernel<<<(4 * 4 * 64 * 128) / 256, 256>>>(w2, p_w2hi, p_w2lo, 64, 128);
    wigner_kernel<<<(N_SAMP * REP * 6 + 127) / 128, 128>>>(angles, item_rep);
    dense_kernel<<<dim3(DENSE_N / 64, N_SAMP / 64), 256>>>(p_item, w0, b0, p_h0hi, p_h0lo);
    deconv_mma_kernel<256, 128, 8, false, true><<<dim3(1024, 4), 256, SMEMD>>>(
        p_h0hi, p_h0lo, p_w1hi, p_w1lo, p_h1hi, p_h1lo, nullptr);
    deconv_mma_kernel<128, 64, 16, true, false><<<dim3(4096, 2), 256, SMEMD>>>(
        p_h1hi, p_h1lo, p_w2hi, p_w2lo, nullptr, nullptr, p_h2);
    deconv3_kernel<<<N_SAMP, 256>>>(p_h2, w3, out);
}

// round 8
// speedup vs baseline: 1.2869x; 1.2121x over previous
#include <cuda_runtime.h>
#include <cuda_bf16.h>
#include <math.h>
#include <stdint.h>

typedef unsigned int u32;
typedef unsigned long long u64;

#define N_SAMP 2048
#define MDIMS  36
#define REP    10
#define FEAT   360
#define DENSE_N 16384        // 256*8*8

// ---------------- packed f32x2 helpers ----------------
__device__ __forceinline__ u64 fma2(u64 a, u64 b, u64 c) {
    u64 d;
    asm("fma.rn.f32x2 %0, %1, %2, %3;" : "=l"(d) : "l"(a), "l"(b), "l"(c));
    return d;
}
__device__ __forceinline__ u64 pack2(float lo, float hi) {
    u64 r; unsigned a = __float_as_uint(lo), b = __float_as_uint(hi);
    asm("mov.b64 %0, {%1, %2};" : "=l"(r) : "r"(a), "r"(b));
    return r;
}
__device__ __forceinline__ float2 unpk2(u64 p) {
    unsigned lo, hi;
    asm("mov.b64 {%0, %1}, %2;" : "=r"(lo), "=r"(hi) : "l"(p));
    return make_float2(__uint_as_float(lo), __uint_as_float(hi));
}

// ---------------- bf16 pack/unpack ----------------
__device__ __forceinline__ u32 bf16pack(float lo, float hi) {
    u32 r;
    asm("cvt.rn.satfinite.bf16x2.f32 %0, %1, %2;" : "=r"(r) : "f"(hi), "f"(lo));
    return r;
}
__device__ __forceinline__ float2 bf16unpk(u32 u) {
    __nv_bfloat162 h = *reinterpret_cast<__nv_bfloat162*>(&u);
    return __bfloat1622float2(h);
}

// ---------------- warp MMA + cp.async helpers ----------------
__device__ __forceinline__ u32 smem_to_u32(const void* p) {
    u32 a;
    asm("{ .reg .u64 t; cvta.to.shared.u64 t, %1; cvt.u32.u64 %0, t; }" : "=r"(a) : "l"(p));
    return a;
}
__device__ __forceinline__ void ldsm4(u32* r, u32 addr) {
    asm volatile("ldmatrix.sync.aligned.m8n8.x4.shared.b16 {%0,%1,%2,%3}, [%4];"
                 : "=r"(r[0]), "=r"(r[1]), "=r"(r[2]), "=r"(r[3]) : "r"(addr));
}
__device__ __forceinline__ void mma16816(float* d, const u32* a, u32 b0, u32 b1) {
    asm volatile(
        "mma.sync.aligned.m16n8k16.row.col.f32.bf16.bf16.f32 "
        "{%0,%1,%2,%3}, {%4,%5,%6,%7}, {%8,%9}, {%0,%1,%2,%3};"
        : "+f"(d[0]), "+f"(d[1]), "+f"(d[2]), "+f"(d[3])
        : "r"(a[0]), "r"(a[1]), "r"(a[2]), "r"(a[3]), "r"(b0), "r"(b1));
}
__device__ __forceinline__ void cp16(u32 dst, const void* src, bool p) {
    asm volatile("cp.async.cg.shared.global [%0], [%1], 16, %2;"
                 :: "r"(dst), "l"(src), "r"(p ? 16 : 0) : "memory");
}
__device__ __forceinline__ void cp_commit() {
    asm volatile("cp.async.commit_group;" ::: "memory");
}
__device__ __forceinline__ void cp_wait1() {
    asm volatile("cp.async.wait_group 1;" ::: "memory");
}
__device__ __forceinline__ void cp_wait0() {
    asm volatile("cp.async.wait_group 0;" ::: "memory");
}

// ---------------- scratch ----------------
__device__ float g_JD[286];
__device__ __align__(16) __nv_bfloat16 g_itemhi[N_SAMP * FEAT];
__device__ __align__(16) __nv_bfloat16 g_itemlo[N_SAMP * FEAT];
__device__ __align__(16) __nv_bfloat16 g_h0hi[N_SAMP * 16384];      // NHWC [n,8,8,256]
__device__ __align__(16) __nv_bfloat16 g_h0lo[N_SAMP * 16384];
__device__ __align__(16) __nv_bfloat16 g_h1hi[N_SAMP * 256 * 128];  // NHWC [n,16,16,128]
__device__ __align__(16) __nv_bfloat16 g_h1lo[N_SAMP * 256 * 128];
__device__ __align__(16) float g_h2[N_SAMP * 1024 * 64];            // NHWC [n,32,32,64] fp32
__device__ __align__(16) __nv_bfloat16 g_w1hi[4 * 128 * 1024];      // [par][chunk][co][tap*32+ci]
__device__ __align__(16) __nv_bfloat16 g_w1lo[4 * 128 * 1024];
__device__ __align__(16) __nv_bfloat16 g_w2hi[4 * 64 * 512];
__device__ __align__(16) __nv_bfloat16 g_w2lo[4 * 64 * 512];
__device__ __align__(16) __nv_bfloat16 g_w0hi[DENSE_N * FEAT];      // [j'=pix*256+c][k]
__device__ __align__(16) __nv_bfloat16 g_w0lo[DENSE_N * FEAT];
__device__ __align__(16) float g_b0r[DENSE_N];

__device__ __constant__ int c_off[7] = {0, 1, 10, 35, 84, 165, 286};

// ---------------- J_l init ----------------
__device__ double dfact(int n) { double r = 1.0; for (int i = 2; i <= n; i++) r *= (double)i; return r; }

__device__ double small_d(int l, int mp, int m) {
    const double ch = 0.70710678118654752440, sh = 0.70710678118654752440;
    double pref = sqrt(dfact(l + mp) * dfact(l - mp) * dfact(l + m) * dfact(l - m));
    int smin = max(0, m - mp), smax = min(l + m, l - mp);
    double tot = 0.0;
    for (int s = smin; s <= smax; s++) {
        double sign = ((mp - m + s) & 1) ? -1.0 : 1.0;
        double denom = dfact(l + m - s) * dfact(s) * dfact(mp - m + s) * dfact(l - mp - s);
        tot += sign / denom * pow(ch, (double)(2 * l + m - mp - 2 * s)) * pow(sh, (double)(mp - m + 2 * s));
    }
    return pref * tot;
}

__device__ void c2r_row(int l, int i, int* col, double* re, double* im, int* cnt) {
    int m = i - l;
    const double s = 0.70710678118654752440;
    if (m < 0) {
        double sgn = (m & 1) ? -1.0 : 1.0;
        col[0] = l + m; re[0] = 0.0; im[0] = s;
        col[1] = l - m; re[1] = 0.0; im[1] = -sgn * s;
        *cnt = 2;
    } else if (m == 0) {
        col[0] = l; re[0] = 1.0; im[0] = 0.0; *cnt = 1;
    } else {
        double sgn = (m & 1) ? -1.0 : 1.0;
        col[0] = l - m; re[0] = s;        im[0] = 0.0;
        col[1] = l + m; re[1] = sgn * s;  im[1] = 0.0;
        *cnt = 2;
    }
}

__global__ void init_jd_kernel() {
    int idx = threadIdx.x;
    if (idx >= 286) return;
    int l = 0;
    while (idx >= c_off[l + 1]) l++;
    int e = idx - c_off[l];
    int sz = 2 * l + 1;
    int i = e / sz, j = e % sz;
    int ca_c[2], cb_c[2], na, nb;
    double ca_re[2], ca_im[2], cb_re[2], cb_im[2];
    c2r_row(l, i, ca_c, ca_re, ca_im, &na);
    c2r_row(l, j, cb_c, cb_re, cb_im, &nb);
    double acc = 0.0;
    for (int a = 0; a < na; a++)
        for (int b = 0; b < nb; b++) {
            double cross = ca_re[a] * cb_re[b] + ca_im[a] * cb_im[b];
            if (cross != 0.0) acc += cross * small_d(l, ca_c[a] - l, cb_c[b] - l);
        }
    g_JD[idx] = (float)acc;
}

// ---------------- Wigner (parallel over l) -> item bf16 hi/lo ----------------
__device__ __forceinline__ void zrot_apply(const float* v, int sz, int l, float ang, float* out) {
    for (int i = 0; i < sz; i++) {
        float f = (float)(l - i);
        float s, c;
        sincosf(f * ang, &s, &c);
        out[i] = c * v[i] + s * v[sz - 1 - i];
    }
}

__global__ void wigner_kernel(const float* __restrict__ angles, const float* __restrict__ item_rep) {
    int t = blockIdx.x * blockDim.x + threadIdx.x;
    if (t >= N_SAMP * REP * 6) return;
    int l = t % 6;
    int nr = t / 6;
    int n = nr / REP, r = nr % REP;
    float a0 = angles[n * 3 + 0], a1 = angles[n * 3 + 1], a2 = angles[n * 3 + 2];
    float v[11], w[11];
    int sz = 2 * l + 1;
    const float* J = &g_JD[c_off[l]];
    for (int i = 0; i < sz; i++) v[i] = item_rep[(l * l + i) * REP + r];
    zrot_apply(v, sz, l, a2, w);
    for (int i = 0; i < sz; i++) { float s = 0.f; for (int j = 0; j < sz; j++) s += J[i * sz + j] * w[j]; v[i] = s; }
    zrot_apply(v, sz, l, a1, w);
    for (int i = 0; i < sz; i++) { float s = 0.f; for (int j = 0; j < sz; j++) s += J[i * sz + j] * w[j]; v[i] = s; }
    zrot_apply(v, sz, l, a0, w);
    for (int i = 0; i < sz; i++) {
        size_t o = (size_t)n * FEAT + (l * l + i) * REP + r;
        float val = w[i];
        __nv_bfloat16 h = __float2bfloat16(val);
        g_itemhi[o] = h;
        g_itemlo[o] = __float2bfloat16(val - __bfloat162float(h));
    }
}

// ------- combined repack: w1, w2 (tap-major parity slabs) + w0 (NHWC-permuted) + b0 -------
__device__ __forceinline__ void repack_wgt(const float* w, __nv_bfloat16* bhi, __nv_bfloat16* blo,
                                           int i, int COUT, int CIN, int NCHUNK) {
    int cii = i & 31;
    int tap = (i >> 5) & 3;
    int co  = (i >> 7) % COUT;
    int chunk = (i / (128 * COUT)) % NCHUNK;
    int par = i / (128 * COUT * NCHUNK);
    int ci = chunk * 32 + cii;
    int dy = tap >> 1, dx = tap & 1, ry = par >> 1, rx = par & 1;
    float v = w[((co * CIN + ci) * 4 + (2 * dy + ry)) * 4 + (2 * dx + rx)];
    __nv_bfloat16 h = __float2bfloat16(v);
    bhi[i] = h;
    blo[i] = __float2bfloat16(v - __bfloat162float(h));
}

__global__ void repack_all_kernel(const float* __restrict__ w1, const float* __restrict__ w2,
                                  const float* __restrict__ w0, const float* __restrict__ b0) {
    const int T1 = 4 * 8 * 128 * 128;      // 524288
    const int T2 = 4 * 4 * 64 * 128;       // 131072
    const int T0 = DENSE_N * FEAT;         // 5898240
    int idx = blockIdx.x * 256 + threadIdx.x;
    if (idx < T1) {
        repack_wgt(w1, g_w1hi, g_w1lo, idx, 128, 256, 8);
    } else if (idx < T1 + T2) {
        repack_wgt(w2, g_w2hi, g_w2lo, idx - T1, 64, 128, 4);
    } else if (idx < T1 + T2 + T0) {
        int i = idx - T1 - T2;
        int jp = i / FEAT, k = i % FEAT;
        int pix = jp >> 8, c = jp & 255;
        float v = w0[(size_t)k * DENSE_N + c * 64 + pix];
        __nv_bfloat16 h = __float2bfloat16(v);
        g_w0hi[i] = h;
        g_w0lo[i] = __float2bfloat16(v - __bfloat162float(h));
    } else if (idx < T1 + T2 + T0 + DENSE_N) {
        int jp = idx - T1 - T2 - T0;
        g_b0r[jp] = b0[(jp & 255) * 64 + (jp >> 8)];
    }
}

// ---------------- dense HMMA: h0 = relu(item @ w0r + b0r), output IS NHWC ----------------
__global__ __launch_bounds__(256) void dense_mma_kernel(
    const __nv_bfloat16* __restrict__ ahi, const __nv_bfloat16* __restrict__ alo,
    const __nv_bfloat16* __restrict__ bh_, const __nv_bfloat16* __restrict__ bl_,
    const float* __restrict__ biasr,
    __nv_bfloat16* __restrict__ chi, __nv_bfloat16* __restrict__ clo) {
    constexpr int SROW = 80;
    constexpr int SLAB = 128 * SROW;       // 10240
    constexpr int STAGEB = 4 * SLAB;       // 40960
    constexpr int KCH = 12;                // 12 chunks of 32 (360 zero-padded to 384)

    extern __shared__ __align__(16) char smem[];
    const u32 u0 = smem_to_u32(smem);
    const int tid = threadIdx.x;
    const int wid = tid >> 5, lid = tid & 31;
    const int wm = wid >> 1, wn = wid & 1;
    const int nb0 = blockIdx.x * 128;
    const int m0  = blockIdx.y * 128;

    auto load_stage = [&](int s, int buf) {
        const int k0 = s * 32;
        const u32 uAh = u0 + buf * STAGEB;
        const u32 uAl = uAh + SLAB;
        const u32 uBh = uAl + SLAB;
        const u32 uBl = uBh + SLAB;
#pragma unroll
        for (int t = 0; t < 2; t++) {
            int idx = tid + t * 256;
            int row = idx >> 2, qd = idx & 3;
            int k = k0 + qd * 8;
            bool p = k < FEAT;
            int kc = p ? k : (FEAT - 8);
            u32 doff = row * SROW + qd * 16;
            cp16(uAh + doff, &ahi[(size_t)(m0 + row) * FEAT + kc], p);
            cp16(uAl + doff, &alo[(size_t)(m0 + row) * FEAT + kc], p);
            cp16(uBh + doff, &bh_[(size_t)(nb0 + row) * FEAT + kc], p);
            cp16(uBl + doff, &bl_[(size_t)(nb0 + row) * FEAT + kc], p);
        }
        cp_commit();
    };

    const int lrow = lid & 15;
    const int lcol = (lid >> 4) << 4;

    float acc[2][8][4];
#pragma unroll
    for (int t = 0; t < 2; t++)
#pragma unroll
        for (int f = 0; f < 8; f++)
#pragma unroll
            for (int j = 0; j < 4; j++) acc[t][f][j] = 0.f;

    load_stage(0, 0);

    for (int s = 0; s < KCH; s++) {
        const int buf = s & 1;
        if (s + 1 < KCH) { load_stage(s + 1, buf ^ 1); cp_wait1(); }
        else             { cp_wait0(); }
        __syncthreads();
        const u32 uAh = u0 + buf * STAGEB;
        const u32 uAl = uAh + SLAB;
        const u32 uBh = uAl + SLAB;
        const u32 uBl = uBh + SLAB;
#pragma unroll
        for (int ks = 0; ks < 2; ks++) {
            u32 ah[2][4], al[2][4], bh[4][4], bl[4][4];
#pragma unroll
            for (int tm = 0; tm < 2; tm++) {
                u32 aaddr = (u32)((wm * 32 + tm * 16 + lrow) * SROW) + ks * 32 + lcol;
                ldsm4(ah[tm], uAh + aaddr);
                ldsm4(al[tm], uAl + aaddr);
            }
#pragma unroll
            for (int g = 0; g < 4; g++) {
                u32 baddr = (u32)((wn * 64 + g * 16 + lrow) * SROW) + ks * 32 + lcol;
                ldsm4(bh[g], uBh + baddr);
                ldsm4(bl[g], uBl + baddr);
            }
#pragma unroll
            for (int tm = 0; tm < 2; tm++)
#pragma unroll
                for (int g = 0; g < 4; g++)
#pragma unroll
                    for (int h = 0; h < 2; h++)
                        mma16816(acc[tm][g * 2 + h], ah[tm], bh[g][h], bh[g][h + 2]);
#pragma unroll
            for (int tm = 0; tm < 2; tm++)
#pragma unroll
                for (int g = 0; g < 4; g++)
#pragma unroll
                    for (int h = 0; h < 2; h++)
                        mma16816(acc[tm][g * 2 + h], ah[tm], bl[g][h], bl[g][h + 2]);
#pragma unroll
            for (int tm = 0; tm < 2; tm++)
#pragma unroll
                for (int g = 0; g < 4; g++)
#pragma unroll
                    for (int h = 0; h < 2; h++)
                        mma16816(acc[tm][g * 2 + h], al[tm], bh[g][h], bh[g][h + 2]);
        }
        __syncthreads();
    }

    // epilogue: bias + relu + split hi/lo, coalesced NHWC (row-major) stores
#pragma unroll
    for (int tm = 0; tm < 2; tm++) {
#pragma unroll
        for (int rr = 0; rr < 2; rr++) {
            int r = m0 + wm * 32 + tm * 16 + (lid >> 2) + rr * 8;
            size_t obase = (size_t)r * DENSE_N + nb0;
#pragma unroll
            for (int f = 0; f < 8; f++) {
                int jc = wn * 64 + f * 8 + (lid & 3) * 2;
                float v0 = fmaxf(acc[tm][f][rr * 2 + 0] + biasr[nb0 + jc], 0.f);
                float v1 = fmaxf(acc[tm][f][rr * 2 + 1] + biasr[nb0 + jc + 1], 0.f);
                u32 hp = bf16pack(v0, v1);
                float2 hf = bf16unpk(hp);
                u32 lp = bf16pack(v0 - hf.x, v1 - hf.y);
                *(u32*)&chi[obase + jc] = hp;
                *(u32*)&clo[obase + jc] = lp;
            }
        }
    }
}

// ------- HMMA implicit-GEMM deconv with shared halo patch across taps --------
template <int CIN, int COUT, int HIN, bool MERGE_RX, bool OUT_BF16>
__global__ __launch_bounds__(256) void deconv_mma_kernel(
    const __nv_bfloat16* __restrict__ in_hi, const __nv_bfloat16* __restrict__ in_lo,
    const __nv_bfloat16* __restrict__ w_hi,  const __nv_bfloat16* __restrict__ w_lo,
    __nv_bfloat16* __restrict__ out_hi, __nv_bfloat16* __restrict__ out_lo,
    float* __restrict__ out_f) {
    constexpr int NCHUNK = CIN / 32;
    constexpr int HOUT = 2 * HIN;
    constexpr int PIX = HIN * HIN;
    constexpr bool SAMPLE_MODE = (HIN == 8);
    constexpr int PW = SAMPLE_MODE ? 9 : 18;
    constexpr int SLOTS = 162;
    constexpr int SROW = 80;
    constexpr int ABYTES = 164 * SROW;
    constexpr int SROWB = 272;
    constexpr int BROWS = (MERGE_RX ? 2 : 1) * COUT;
    constexpr int BBYTES = BROWS * SROWB;
    constexpr int STAGEB = 2 * ABYTES + 2 * BBYTES;
    constexpr int NPAR = MERGE_RX ? 2 : 1;
    constexpr int NG = COUT / 32;
    constexpr int NF8 = COUT / 16;

    extern __shared__ __align__(16) char smem[];
    const u32 u0 = smem_to_u32(smem);

    const int tid = threadIdx.x;
    const int wid = tid >> 5;
    const int lid = tid & 31;
    const int wm = wid >> 1;
    const int wn = wid & 1;
    const int par = blockIdx.y;
    const int ry = MERGE_RX ? par : (par >> 1);
    const int rx0 = MERGE_RX ? 0 : (par & 1);
    const int m0 = blockIdx.x * 128;
    const int n0 = SAMPLE_MODE ? blockIdx.x * 2 : (m0 >> 8);
    const int qy0 = SAMPLE_MODE ? 0 : ((m0 & 255) >> 4);

    auto load_stage = [&](int s, int buf) {
        const int ci0 = s * 32;
        const u32 uAh = u0 + buf * STAGEB;
        const u32 uAl = uAh + ABYTES;
        const u32 uBh = uAh + 2 * ABYTES;
        const u32 uBl = uBh + BBYTES;
        for (int idx = tid; idx < SLOTS * 4; idx += 256) {
            int slot = idx >> 2, qd = idx & 3;
            int n, y, x;
            if (SAMPLE_MODE) {
                int smp = slot / 81, rr = slot % 81;
                n = n0 + smp;
                y = rr / 9 - 1 + ry;
                x = rr % 9 - 1 + rx0;
            } else {
                n = n0;
                y = slot / 18 + qy0 - 1 + ry;
                x = slot % 18 - 1;
            }
            bool p = (y >= 0) && (y < HIN) && (x >= 0) && (x < HIN);
            int yc = p ? y : 0, xc = p ? x : 0;
            size_t base = (((size_t)n * HIN + yc) * HIN + xc) * CIN + ci0 + qd * 8;
            u32 doff = slot * SROW + qd * 16;
            cp16(uAh + doff, &in_hi[base], p);
            cp16(uAl + doff, &in_lo[base], p);
        }
        for (int idx = tid; idx < BROWS * 16; idx += 256) {
            int row = idx >> 4, qd = idx & 15;
            int co, wpar;
            if (MERGE_RX) { co = row % COUT; wpar = ry * 2 + (row / COUT); }
            else          { co = row;        wpar = par; }
            size_t base = (((size_t)(wpar * NCHUNK + s) * COUT + co) << 7) + qd * 8;
            u32 doff = row * SROWB + qd * 16;
            cp16(uBh + doff, &w_hi[base], true);
            cp16(uBl + doff, &w_lo[base], true);
        }
        cp_commit();
    };

    const int lrow = lid & 15;
    const int lcol = (lid >> 4) << 4;
    int bslot[2];
#pragma unroll
    for (int tm = 0; tm < 2; tm++) {
        int row = wm * 32 + tm * 16 + lrow;
        if (SAMPLE_MODE) {
            int smp = row >> 6, q = row & 63;
            bslot[tm] = smp * 81 + (q >> 3) * 9 + (q & 7);
        } else {
            int q = (m0 + row) & 255;
            bslot[tm] = ((q >> 4) - qy0) * PW + (q & 15);
        }
    }

    float acc[NPAR][2][NF8][4];
#pragma unroll
    for (int p = 0; p < NPAR; p++)
#pragma unroll
        for (int t = 0; t < 2; t++)
#pragma unroll
            for (int f = 0; f < NF8; f++)
#pragma unroll
                for (int j = 0; j < 4; j++) acc[p][t][f][j] = 0.f;

    load_stage(0, 0);

    for (int s = 0; s < NCHUNK; s++) {
        const int buf = s & 1;
        if (s + 1 < NCHUNK) { load_stage(s + 1, buf ^ 1); cp_wait1(); }
        else                { cp_wait0(); }
        __syncthreads();

        const u32 uAh = u0 + buf * STAGEB;
        const u32 uAl = uAh + ABYTES;
        const u32 uBh = uAh + 2 * ABYTES;
        const u32 uBl = uBh + BBYTES;
#pragma unroll
        for (int tap = 0; tap < 4; tap++) {
            const int dy = tap >> 1, dx = tap & 1;
#pragma unroll
            for (int ks = 0; ks < 2; ks++) {
#pragma unroll
                for (int prx = 0; prx < NPAR; prx++) {
                    u32 ah[2][4], al[2][4];
#pragma unroll
                    for (int tm = 0; tm < 2; tm++) {
                        u32 aaddr = (u32)((bslot[tm] + dy * PW + dx + prx) * SROW) + ks * 32 + lcol;
                        ldsm4(ah[tm], uAh + aaddr);
                        ldsm4(al[tm], uAl + aaddr);
                    }
                    u32 bh[NG][4], bl[NG][4];
#pragma unroll
                    for (int g = 0; g < NG; g++) {
                        u32 baddr = (u32)((prx * COUT + wn * (COUT / 2) + g * 16 + lrow) * SROWB)
                                    + tap * 64 + ks * 32 + lcol;
                        ldsm4(bh[g], uBh + baddr);
                        ldsm4(bl[g], uBl + baddr);
                    }
#pragma unroll
                    for (int tm = 0; tm < 2; tm++)
#pragma unroll
                        for (int g = 0; g < NG; g++)
#pragma unroll
                            for (int h = 0; h < 2; h++)
                                mma16816(acc[prx][tm][g * 2 + h], ah[tm], bh[g][h], bh[g][h + 2]);
#pragma unroll
                    for (int tm = 0; tm < 2; tm++)
#pragma unroll
                        for (int g = 0; g < NG; g++)
#pragma unroll
                            for (int h = 0; h < 2; h++)
                                mma16816(acc[prx][tm][g * 2 + h], ah[tm], bl[g][h], bl[g][h + 2]);
#pragma unroll
                    for (int tm = 0; tm < 2; tm++)
#pragma unroll
                        for (int g = 0; g < NG; g++)
#pragma unroll
                            for (int h = 0; h < 2; h++)
                                mma16816(acc[prx][tm][g * 2 + h], al[tm], bh[g][h], bh[g][h + 2]);
                }
            }
        }
        __syncthreads();
    }

#pragma unroll
    for (int prx = 0; prx < NPAR; prx++) {
        const int rx = MERGE_RX ? prx : rx0;
#pragma unroll
        for (int tm = 0; tm < 2; tm++) {
            int r0 = wm * 32 + tm * 16 + (lid >> 2);
#pragma unroll
            for (int rr = 0; rr < 2; rr++) {
                int r = r0 + rr * 8;
                int n, yo, xo;
                if (SAMPLE_MODE) {
                    n = n0 + (r >> 6);
                    int q = r & 63;
                    yo = 2 * (q >> 3) + ry;
                    xo = 2 * (q & 7) + rx;
                } else {
                    int R = m0 + r;
                    n = R >> 8;
                    int q = R & 255;
                    yo = 2 * (q >> 4) + ry;
                    xo = 2 * (q & 15) + rx;
                }
                size_t obase = (((size_t)n * HOUT + yo) * HOUT + xo) * COUT;
#pragma unroll
                for (int f = 0; f < NF8; f++) {
                    int ch = wn * (COUT / 2) + f * 8 + (lid & 3) * 2;
                    float v0 = fmaxf(acc[prx][tm][f][rr * 2 + 0], 0.f);
                    float v1 = fmaxf(acc[prx][tm][f][rr * 2 + 1], 0.f);
                    if (OUT_BF16) {
                        u32 hp = bf16pack(v0, v1);
                        float2 hf = bf16unpk(hp);
                        u32 lp = bf16pack(v0 - hf.x, v1 - hf.y);
                        *(u32*)&out_hi[obase + ch] = hp;
                        *(u32*)&out_lo[obase + ch] = lp;
                    } else {
                        *(float2*)&out_f[obase + ch] = make_float2(v0, v1);
                    }
                }
            }
        }
    }
}

// ---------------- deconv3: 64 -> 3, NHWC fp32 input, NCHW output ----------------
__global__ __launch_bounds__(256) void deconv3_kernel(const float* __restrict__ in,
                                                      const float* __restrict__ wgt,
                                                      float* __restrict__ out) {
    int n = blockIdx.x;
    __shared__ float sin_[34 * 34 * 4];
    __shared__ float wsm[3 * 64 * 16 * 2];
    int tid = threadIdx.x;

    for (int idx = tid; idx < 3072; idx += 256) {
        int tap = idx & 15;
        int cc = idx >> 4;
        int co = cc % 3, ci = cc / 3;
        float w = wgt[(co * 64 + ci) * 16 + tap];
        wsm[((ci * 3 + co) * 16 + tap) * 2 + 0] = w;
        wsm[((ci * 3 + co) * 16 + tap) * 2 + 1] = w;
    }

    int qy0 = (tid >> 4) * 2;
    int qx0 = (tid & 15) * 2;
    u64 accp[3][8];
#pragma unroll
    for (int c = 0; c < 3; c++)
#pragma unroll
        for (int i = 0; i < 8; i++) accp[c][i] = 0ull;

    const float* in_n = in + (size_t)n * 1024 * 64;
    for (int ci0 = 0; ci0 < 64; ci0 += 4) {
        __syncthreads();
        for (int idx = tid; idx < 1156; idx += 256) {
            int py = idx / 34, px = idx % 34;
            int y = py - 1, x = px - 1;
            float4 v = make_float4(0.f, 0.f, 0.f, 0.f);
            if (y >= 0 && y < 32 && x >= 0 && x < 32)
                v = *(const float4*)&in_n[(y * 32 + x) * 64 + ci0];
            *(float4*)&sin_[idx * 4] = v;
        }
        __syncthreads();
#pragma unroll 1
        for (int ci = 0; ci < 4; ci++) {
            float iv[4][4];
#pragma unroll
            for (int yy = 0; yy < 4; yy++)
#pragma unroll
                for (int xx = 0; xx < 4; xx++)
                    iv[yy][xx] = sin_[((qy0 + yy) * 34 + qx0 + xx) * 4 + ci];
            u64 ivp2[4][3];
#pragma unroll
            for (int yy = 0; yy < 4; yy++)
#pragma unroll
                for (int xx = 0; xx < 3; xx++)
                    ivp2[yy][xx] = pack2(iv[yy][xx], iv[yy][xx + 1]);
#pragma unroll
            for (int co = 0; co < 3; co++) {
#pragma unroll
                for (int tap = 0; tap < 16; tap++) {
                    const int ky = tap >> 2, kx = tap & 3;
                    const int ry = ky & 1, dy = ky >> 1;
                    const int rx = kx & 1, dx = kx >> 1;
                    u64 wp = *(const u64*)&wsm[(((ci0 + ci) * 3 + co) * 16 + tap) * 2];
#pragma unroll
                    for (int qy = 0; qy < 2; qy++) {
                        const int o = qy * 4 + ry * 2 + rx;
                        accp[co][o] = fma2(wp, ivp2[qy + dy + ry][dx + rx], accp[co][o]);
                    }
                }
            }
        }
    }
    float* out_n = out + (size_t)n * 3 * 4096;
#pragma unroll
    for (int co = 0; co < 3; co++)
#pragma unroll
        for (int qy = 0; qy < 2; qy++)
#pragma unroll
            for (int ry = 0; ry < 2; ry++)
#pragma unroll
                for (int rx = 0; rx < 2; rx++) {
                    float2 v = unpk2(accp[co][qy * 4 + ry * 2 + rx]);
                    int yo = 2 * (qy0 + qy) + ry;
                    int xo0 = 2 * (qx0 + 0) + rx;
                    int xo1 = 2 * (qx0 + 1) + rx;
                    out_n[co * 4096 + yo * 64 + xo0] = v.x;
                    out_n[co * 4096 + yo * 64 + xo1] = v.y;
                }
}

// -----------------------------------------------------------------------------------------
extern "C" void kernel_launch(void* const* d_in, const int* in_sizes, int n_in,
                              void* d_out, int out_size) {
    (void)in_sizes; (void)n_in; (void)out_size;
    const float* angles   = (const float*)d_in[0];
    const float* item_rep = (const float*)d_in[1];
    const float* w0       = (const float*)d_in[2];
    const float* b0       = (const float*)d_in[3];
    const float* w1       = (const float*)d_in[4];
    const float* w2       = (const float*)d_in[5];
    const float* w3       = (const float*)d_in[6];
    float* out = (float*)d_out;

    float *p_h2, *p_b0r;
    cudaGetSymbolAddress((void**)&p_h2, g_h2);
    cudaGetSymbolAddress((void**)&p_b0r, g_b0r);
    __nv_bfloat16 *p_ithi, *p_itlo, *p_w0hi, *p_w0lo;
    cudaGetSymbolAddress((void**)&p_ithi, g_itemhi);
    cudaGetSymbolAddress((void**)&p_itlo, g_itemlo);
    cudaGetSymbolAddress((void**)&p_w0hi, g_w0hi);
    cudaGetSymbolAddress((void**)&p_w0lo, g_w0lo);
    __nv_bfloat16 *p_h0hi, *p_h0lo, *p_h1hi, *p_h1lo;
    cudaGetSymbolAddress((void**)&p_h0hi, g_h0hi);
    cudaGetSymbolAddress((void**)&p_h0lo, g_h0lo);
    cudaGetSymbolAddress((void**)&p_h1hi, g_h1hi);
    cudaGetSymbolAddress((void**)&p_h1lo, g_h1lo);
    __nv_bfloat16 *p_w1hi, *p_w1lo, *p_w2hi, *p_w2lo;
    cudaGetSymbolAddress((void**)&p_w1hi, g_w1hi);
    cudaGetSymbolAddress((void**)&p_w1lo, g_w1lo);
    cudaGetSymbolAddress((void**)&p_w2hi, g_w2hi);
    cudaGetSymbolAddress((void**)&p_w2lo, g_w2lo);

    constexpr int SMEMD = 2 * (2 * 164 * 80 + 2 * 128 * 272);  // 191744
    constexpr int SMEMG = 2 * 4 * 128 * 80;                    // 81920
    cudaFuncSetAttribute(deconv_mma_kernel<256, 128, 8, false, true>,
                         cudaFuncAttributeMaxDynamicSharedMemorySize, SMEMD);
    cudaFuncSetAttribute(deconv_mma_kernel<128, 64, 16, true, false>,
                         cudaFuncAttributeMaxDynamicSharedMemorySize, SMEMD);
    cudaFuncSetAttribute(dense_mma_kernel,
                         cudaFuncAttributeMaxDynamicSharedMemorySize, SMEMG);

    const int REPACK_TOTAL = 4 * 8 * 128 * 128 + 4 * 4 * 64 * 128 + DENSE_N * FEAT + DENSE_N;
    init_jd_kernel<<<1, 288>>>();
    repack_all_kernel<<<(REPACK_TOTAL + 255) / 256, 256>>>(w1, w2, w0, b0);
    wigner_kernel<<<(N_SAMP * REP * 6 + 127) / 128, 128>>>(angles, item_rep);
    dense_mma_kernel<<<dim3(DENSE_N / 128, N_SAMP / 128), 256, SMEMG>>>(
        p_ithi, p_itlo, p_w0hi, p_w0lo, p_b0r, p_h0hi, p_h0lo);
    deconv_mma_kernel<256, 128, 8, false, true><<<dim3(1024, 4), 256, SMEMD>>>(
        p_h0hi, p_h0lo, p_w1hi, p_w1lo, p_h1hi, p_h1lo, nullptr);
    deconv_mma_kernel<128, 64, 16, true, false><<<dim3(4096, 2), 256, SMEMD>>>(
        p_h1hi, p_h1lo, p_w2hi, p_w2lo, nullptr, nullptr, p_h2);
    deconv3_kernel<<<N_SAMP, 256>>>(p_h2, w3, out);
}

// round 9
// speedup vs baseline: 1.2977x; 1.0084x over previous
#include <cuda_runtime.h>
#include <cuda_bf16.h>
#include <math.h>
#include <stdint.h>

typedef unsigned int u32;
typedef unsigned long long u64;

#define N_SAMP 2048
#define MDIMS  36
#define REP    10
#define FEAT   360
#define DENSE_N 16384        // 256*8*8

// ---------------- packed f32x2 helpers ----------------
__device__ __forceinline__ u64 fma2(u64 a, u64 b, u64 c) {
    u64 d;
    asm("fma.rn.f32x2 %0, %1, %2, %3;" : "=l"(d) : "l"(a), "l"(b), "l"(c));
    return d;
}
__device__ __forceinline__ u64 pack2(float lo, float hi) {
    u64 r; unsigned a = __float_as_uint(lo), b = __float_as_uint(hi);
    asm("mov.b64 %0, {%1, %2};" : "=l"(r) : "r"(a), "r"(b));
    return r;
}
__device__ __forceinline__ float2 unpk2(u64 p) {
    unsigned lo, hi;
    asm("mov.b64 {%0, %1}, %2;" : "=r"(lo), "=r"(hi) : "l"(p));
    return make_float2(__uint_as_float(lo), __uint_as_float(hi));
}

// ---------------- bf16 pack/unpack ----------------
__device__ __forceinline__ u32 bf16pack(float lo, float hi) {
    u32 r;
    asm("cvt.rn.satfinite.bf16x2.f32 %0, %1, %2;" : "=r"(r) : "f"(hi), "f"(lo));
    return r;
}
__device__ __forceinline__ float2 bf16unpk(u32 u) {
    __nv_bfloat162 h = *reinterpret_cast<__nv_bfloat162*>(&u);
    return __bfloat1622float2(h);
}

// ---------------- warp MMA + cp.async helpers ----------------
__device__ __forceinline__ u32 smem_to_u32(const void* p) {
    u32 a;
    asm("{ .reg .u64 t; cvta.to.shared.u64 t, %1; cvt.u32.u64 %0, t; }" : "=r"(a) : "l"(p));
    return a;
}
__device__ __forceinline__ void ldsm4(u32* r, u32 addr) {
    asm volatile("ldmatrix.sync.aligned.m8n8.x4.shared.b16 {%0,%1,%2,%3}, [%4];"
                 : "=r"(r[0]), "=r"(r[1]), "=r"(r[2]), "=r"(r[3]) : "r"(addr));
}
__device__ __forceinline__ void mma16816(float* d, const u32* a, u32 b0, u32 b1) {
    asm volatile(
        "mma.sync.aligned.m16n8k16.row.col.f32.bf16.bf16.f32 "
        "{%0,%1,%2,%3}, {%4,%5,%6,%7}, {%8,%9}, {%0,%1,%2,%3};"
        : "+f"(d[0]), "+f"(d[1]), "+f"(d[2]), "+f"(d[3])
        : "r"(a[0]), "r"(a[1]), "r"(a[2]), "r"(a[3]), "r"(b0), "r"(b1));
}
__device__ __forceinline__ void cp16(u32 dst, const void* src, bool p) {
    asm volatile("cp.async.cg.shared.global [%0], [%1], 16, %2;"
                 :: "r"(dst), "l"(src), "r"(p ? 16 : 0) : "memory");
}
__device__ __forceinline__ void cp_commit() {
    asm volatile("cp.async.commit_group;" ::: "memory");
}
__device__ __forceinline__ void cp_wait1() {
    asm volatile("cp.async.wait_group 1;" ::: "memory");
}
__device__ __forceinline__ void cp_wait0() {
    asm volatile("cp.async.wait_group 0;" ::: "memory");
}

// ---------------- scratch ----------------
__device__ float g_JD[286];
__device__ __align__(16) __nv_bfloat16 g_itemhi[N_SAMP * FEAT];
__device__ __align__(16) __nv_bfloat16 g_itemlo[N_SAMP * FEAT];
__device__ __align__(16) __nv_bfloat16 g_h0hi[N_SAMP * 16384];      // NHWC [n,8,8,256]
__device__ __align__(16) __nv_bfloat16 g_h0lo[N_SAMP * 16384];
__device__ __align__(16) __nv_bfloat16 g_h1hi[N_SAMP * 256 * 128];  // NHWC [n,16,16,128]
__device__ __align__(16) __nv_bfloat16 g_h1lo[N_SAMP * 256 * 128];
__device__ __align__(16) float g_h2[N_SAMP * 1024 * 64];            // NHWC [n,32,32,64] fp32
__device__ __align__(16) __nv_bfloat16 g_w1hi[4 * 128 * 1024];      // [par][chunk][co][tap*32+ci]
__device__ __align__(16) __nv_bfloat16 g_w1lo[4 * 128 * 1024];
__device__ __align__(16) __nv_bfloat16 g_w2hi[4 * 64 * 512];
__device__ __align__(16) __nv_bfloat16 g_w2lo[4 * 64 * 512];
__device__ __align__(16) __nv_bfloat16 g_w0hi[DENSE_N * FEAT];      // [j'=pix*256+c][k]
__device__ __align__(16) __nv_bfloat16 g_w0lo[DENSE_N * FEAT];
__device__ __align__(16) float g_b0r[DENSE_N];

__device__ __constant__ int c_off[7] = {0, 1, 10, 35, 84, 165, 286};

// ---------------- J_l init ----------------
__device__ double dfact(int n) { double r = 1.0; for (int i = 2; i <= n; i++) r *= (double)i; return r; }

__device__ double small_d(int l, int mp, int m) {
    const double ch = 0.70710678118654752440, sh = 0.70710678118654752440;
    double pref = sqrt(dfact(l + mp) * dfact(l - mp) * dfact(l + m) * dfact(l - m));
    int smin = max(0, m - mp), smax = min(l + m, l - mp);
    double tot = 0.0;
    for (int s = smin; s <= smax; s++) {
        double sign = ((mp - m + s) & 1) ? -1.0 : 1.0;
        double denom = dfact(l + m - s) * dfact(s) * dfact(mp - m + s) * dfact(l - mp - s);
        tot += sign / denom * pow(ch, (double)(2 * l + m - mp - 2 * s)) * pow(sh, (double)(mp - m + 2 * s));
    }
    return pref * tot;
}

__device__ void c2r_row(int l, int i, int* col, double* re, double* im, int* cnt) {
    int m = i - l;
    const double s = 0.70710678118654752440;
    if (m < 0) {
        double sgn = (m & 1) ? -1.0 : 1.0;
        col[0] = l + m; re[0] = 0.0; im[0] = s;
        col[1] = l - m; re[1] = 0.0; im[1] = -sgn * s;
        *cnt = 2;
    } else if (m == 0) {
        col[0] = l; re[0] = 1.0; im[0] = 0.0; *cnt = 1;
    } else {
        double sgn = (m & 1) ? -1.0 : 1.0;
        col[0] = l - m; re[0] = s;        im[0] = 0.0;
        col[1] = l + m; re[1] = sgn * s;  im[1] = 0.0;
        *cnt = 2;
    }
}

__global__ void init_jd_kernel() {
    int idx = threadIdx.x;
    if (idx >= 286) return;
    int l = 0;
    while (idx >= c_off[l + 1]) l++;
    int e = idx - c_off[l];
    int sz = 2 * l + 1;
    int i = e / sz, j = e % sz;
    int ca_c[2], cb_c[2], na, nb;
    double ca_re[2], ca_im[2], cb_re[2], cb_im[2];
    c2r_row(l, i, ca_c, ca_re, ca_im, &na);
    c2r_row(l, j, cb_c, cb_re, cb_im, &nb);
    double acc = 0.0;
    for (int a = 0; a < na; a++)
        for (int b = 0; b < nb; b++) {
            double cross = ca_re[a] * cb_re[b] + ca_im[a] * cb_im[b];
            if (cross != 0.0) acc += cross * small_d(l, ca_c[a] - l, cb_c[b] - l);
        }
    g_JD[idx] = (float)acc;
}

// ---------------- Wigner (parallel over l) -> item bf16 hi/lo ----------------
__device__ __forceinline__ void zrot_apply(const float* v, int sz, int l, float ang, float* out) {
    for (int i = 0; i < sz; i++) {
        float f = (float)(l - i);
        float s, c;
        sincosf(f * ang, &s, &c);
        out[i] = c * v[i] + s * v[sz - 1 - i];
    }
}

__global__ void wigner_kernel(const float* __restrict__ angles, const float* __restrict__ item_rep) {
    int t = blockIdx.x * blockDim.x + threadIdx.x;
    if (t >= N_SAMP * REP * 6) return;
    int l = t % 6;
    int nr = t / 6;
    int n = nr / REP, r = nr % REP;
    float a0 = angles[n * 3 + 0], a1 = angles[n * 3 + 1], a2 = angles[n * 3 + 2];
    float v[11], w[11];
    int sz = 2 * l + 1;
    const float* J = &g_JD[c_off[l]];
    for (int i = 0; i < sz; i++) v[i] = item_rep[(l * l + i) * REP + r];
    zrot_apply(v, sz, l, a2, w);
    for (int i = 0; i < sz; i++) { float s = 0.f; for (int j = 0; j < sz; j++) s += J[i * sz + j] * w[j]; v[i] = s; }
    zrot_apply(v, sz, l, a1, w);
    for (int i = 0; i < sz; i++) { float s = 0.f; for (int j = 0; j < sz; j++) s += J[i * sz + j] * w[j]; v[i] = s; }
    zrot_apply(v, sz, l, a0, w);
    for (int i = 0; i < sz; i++) {
        size_t o = (size_t)n * FEAT + (l * l + i) * REP + r;
        float val = w[i];
        __nv_bfloat16 h = __float2bfloat16(val);
        g_itemhi[o] = h;
        g_itemlo[o] = __float2bfloat16(val - __bfloat162float(h));
    }
}

// ------- combined repack: w1, w2 (tap-major parity slabs) + w0 (NHWC-permuted) + b0 -------
__device__ __forceinline__ void repack_wgt(const float* w, __nv_bfloat16* bhi, __nv_bfloat16* blo,
                                           int i, int COUT, int CIN, int NCHUNK) {
    int cii = i & 31;
    int tap = (i >> 5) & 3;
    int co  = (i >> 7) % COUT;
    int chunk = (i / (128 * COUT)) % NCHUNK;
    int par = i / (128 * COUT * NCHUNK);
    int ci = chunk * 32 + cii;
    int dy = tap >> 1, dx = tap & 1, ry = par >> 1, rx = par & 1;
    float v = w[((co * CIN + ci) * 4 + (2 * dy + ry)) * 4 + (2 * dx + rx)];
    __nv_bfloat16 h = __float2bfloat16(v);
    bhi[i] = h;
    blo[i] = __float2bfloat16(v - __bfloat162float(h));
}

__global__ void repack_all_kernel(const float* __restrict__ w1, const float* __restrict__ w2,
                                  const float* __restrict__ w0, const float* __restrict__ b0) {
    const int T1 = 4 * 8 * 128 * 128;      // 524288
    const int T2 = 4 * 4 * 64 * 128;       // 131072
    const int T0 = DENSE_N * FEAT;         // 5898240
    int idx = blockIdx.x * 256 + threadIdx.x;
    if (idx < T1) {
        repack_wgt(w1, g_w1hi, g_w1lo, idx, 128, 256, 8);
    } else if (idx < T1 + T2) {
        repack_wgt(w2, g_w2hi, g_w2lo, idx - T1, 64, 128, 4);
    } else if (idx < T1 + T2 + T0) {
        int i = idx - T1 - T2;
        int jp = i / FEAT, k = i % FEAT;
        int pix = jp >> 8, c = jp & 255;
        float v = w0[(size_t)k * DENSE_N + c * 64 + pix];
        __nv_bfloat16 h = __float2bfloat16(v);
        g_w0hi[i] = h;
        g_w0lo[i] = __float2bfloat16(v - __bfloat162float(h));
    } else if (idx < T1 + T2 + T0 + DENSE_N) {
        int jp = idx - T1 - T2 - T0;
        g_b0r[jp] = b0[(jp & 255) * 64 + (jp >> 8)];
    }
}

// ---------------- dense HMMA: h0 = relu(item @ w0r + b0r), output IS NHWC ----------------
__global__ __launch_bounds__(256) void dense_mma_kernel(
    const __nv_bfloat16* __restrict__ ahi, const __nv_bfloat16* __restrict__ alo,
    const __nv_bfloat16* __restrict__ bh_, const __nv_bfloat16* __restrict__ bl_,
    const float* __restrict__ biasr,
    __nv_bfloat16* __restrict__ chi, __nv_bfloat16* __restrict__ clo) {
    constexpr int SROW = 80;
    constexpr int SLAB = 128 * SROW;       // 10240
    constexpr int STAGEB = 4 * SLAB;       // 40960
    constexpr int KCH = 12;                // 12 chunks of 32 (360 zero-padded to 384)

    extern __shared__ __align__(16) char smem[];
    const u32 u0 = smem_to_u32(smem);
    const int tid = threadIdx.x;
    const int wid = tid >> 5, lid = tid & 31;
    const int wm = wid >> 1, wn = wid & 1;
    const int nb0 = blockIdx.x * 128;
    const int m0  = blockIdx.y * 128;

    auto load_stage = [&](int s, int buf) {
        const int k0 = s * 32;
        const u32 uAh = u0 + buf * STAGEB;
        const u32 uAl = uAh + SLAB;
        const u32 uBh = uAl + SLAB;
        const u32 uBl = uBh + SLAB;
#pragma unroll
        for (int t = 0; t < 2; t++) {
            int idx = tid + t * 256;
            int row = idx >> 2, qd = idx & 3;
            int k = k0 + qd * 8;
            bool p = k < FEAT;
            int kc = p ? k : (FEAT - 8);
            u32 doff = row * SROW + qd * 16;
            cp16(uAh + doff, &ahi[(size_t)(m0 + row) * FEAT + kc], p);
            cp16(uAl + doff, &alo[(size_t)(m0 + row) * FEAT + kc], p);
            cp16(uBh + doff, &bh_[(size_t)(nb0 + row) * FEAT + kc], p);
            cp16(uBl + doff, &bl_[(size_t)(nb0 + row) * FEAT + kc], p);
        }
        cp_commit();
    };

    const int lrow = lid & 15;
    const int lcol = (lid >> 4) << 4;

    float acc[2][8][4];
#pragma unroll
    for (int t = 0; t < 2; t++)
#pragma unroll
        for (int f = 0; f < 8; f++)
#pragma unroll
            for (int j = 0; j < 4; j++) acc[t][f][j] = 0.f;

    load_stage(0, 0);

    for (int s = 0; s < KCH; s++) {
        const int buf = s & 1;
        if (s + 1 < KCH) { load_stage(s + 1, buf ^ 1); cp_wait1(); }
        else             { cp_wait0(); }
        __syncthreads();
        const u32 uAh = u0 + buf * STAGEB;
        const u32 uAl = uAh + SLAB;
        const u32 uBh = uAl + SLAB;
        const u32 uBl = uBh + SLAB;
#pragma unroll
        for (int ks = 0; ks < 2; ks++) {
            u32 ah[2][4], al[2][4], bh[4][4], bl[4][4];
#pragma unroll
            for (int tm = 0; tm < 2; tm++) {
                u32 aaddr = (u32)((wm * 32 + tm * 16 + lrow) * SROW) + ks * 32 + lcol;
                ldsm4(ah[tm], uAh + aaddr);
                ldsm4(al[tm], uAl + aaddr);
            }
#pragma unroll
            for (int g = 0; g < 4; g++) {
                u32 baddr = (u32)((wn * 64 + g * 16 + lrow) * SROW) + ks * 32 + lcol;
                ldsm4(bh[g], uBh + baddr);
                ldsm4(bl[g], uBl + baddr);
            }
#pragma unroll
            for (int tm = 0; tm < 2; tm++)
#pragma unroll
                for (int g = 0; g < 4; g++)
#pragma unroll
                    for (int h = 0; h < 2; h++)
                        mma16816(acc[tm][g * 2 + h], ah[tm], bh[g][h], bh[g][h + 2]);
#pragma unroll
            for (int tm = 0; tm < 2; tm++)
#pragma unroll
                for (int g = 0; g < 4; g++)
#pragma unroll
                    for (int h = 0; h < 2; h++)
                        mma16816(acc[tm][g * 2 + h], ah[tm], bl[g][h], bl[g][h + 2]);
#pragma unroll
            for (int tm = 0; tm < 2; tm++)
#pragma unroll
                for (int g = 0; g < 4; g++)
#pragma unroll
                    for (int h = 0; h < 2; h++)
                        mma16816(acc[tm][g * 2 + h], al[tm], bh[g][h], bh[g][h + 2]);
        }
        __syncthreads();
    }

#pragma unroll
    for (int tm = 0; tm < 2; tm++) {
#pragma unroll
        for (int rr = 0; rr < 2; rr++) {
            int r = m0 + wm * 32 + tm * 16 + (lid >> 2) + rr * 8;
            size_t obase = (size_t)r * DENSE_N + nb0;
#pragma unroll
            for (int f = 0; f < 8; f++) {
                int jc = wn * 64 + f * 8 + (lid & 3) * 2;
                float v0 = fmaxf(acc[tm][f][rr * 2 + 0] + biasr[nb0 + jc], 0.f);
                float v1 = fmaxf(acc[tm][f][rr * 2 + 1] + biasr[nb0 + jc + 1], 0.f);
                u32 hp = bf16pack(v0, v1);
                float2 hf = bf16unpk(hp);
                u32 lp = bf16pack(v0 - hf.x, v1 - hf.y);
                *(u32*)&chi[obase + jc] = hp;
                *(u32*)&clo[obase + jc] = lp;
            }
        }
    }
}

// ------- HMMA implicit-GEMM deconv, M=256/CTA, fused hi/lo smem rows --------
// SAMPLE_MODE (HIN==8): CTA = 4 samples, parity = blockIdx.y (0..3).
// RowMode (HIN==16, MERGE_RX): CTA = 1 full sample, ry = blockIdx.y (0..1),
//   both rx parities from one patch.
template <int CIN, int COUT, int HIN, bool MERGE_RX, bool OUT_BF16>
__global__ __launch_bounds__(512) void deconv_mma_kernel(
    const __nv_bfloat16* __restrict__ in_hi, const __nv_bfloat16* __restrict__ in_lo,
    const __nv_bfloat16* __restrict__ w_hi,  const __nv_bfloat16* __restrict__ w_lo,
    __nv_bfloat16* __restrict__ out_hi, __nv_bfloat16* __restrict__ out_lo,
    float* __restrict__ out_f) {
    constexpr int NCHUNK = CIN / 32;
    constexpr int HOUT = 2 * HIN;
    constexpr bool SAMPLE_MODE = (HIN == 8);
    constexpr int PW = SAMPLE_MODE ? 9 : 18;
    constexpr int SLOTS = 324;             // 4*81 or 18*18
    constexpr int SROW = 144;              // [64B hi][64B lo][16 pad]
    constexpr int ABYTES = SLOTS * SROW;   // 46656
    constexpr int SROWB = 528;             // [256B hi][256B lo][16 pad]
    constexpr int BROWS = 128;             // 128 co | 2par x 64 co
    constexpr int BBYTES = BROWS * SROWB;  // 67584
    constexpr int STAGEB = ABYTES + BBYTES;// 114240
    constexpr int NPAR = MERGE_RX ? 2 : 1;
    constexpr int NG = COUT / 32;          // 4 | 2
    constexpr int NF8 = COUT / 16;         // 8 | 4

    extern __shared__ __align__(16) char smem[];
    const u32 u0 = smem_to_u32(smem);

    const int tid = threadIdx.x;
    const int wid = tid >> 5;
    const int lid = tid & 31;
    const int wm = wid >> 1;               // 0..7, m32 tiles
    const int wn = wid & 1;
    const int par = blockIdx.y;
    const int ry = MERGE_RX ? par : (par >> 1);
    const int rx0 = MERGE_RX ? 0 : (par & 1);
    const int n0 = SAMPLE_MODE ? blockIdx.x * 4 : blockIdx.x;

    auto load_stage = [&](int s, int buf) {
        const int ci0 = s * 32;
        const u32 uA = u0 + buf * STAGEB;
        const u32 uB = uA + ABYTES;
        for (int idx = tid; idx < SLOTS * 4; idx += 512) {
            int slot = idx >> 2, qd = idx & 3;
            int n, y, x;
            if (SAMPLE_MODE) {
                int smp = slot / 81, rr = slot % 81;
                n = n0 + smp;
                y = rr / 9 - 1 + ry;
                x = rr % 9 - 1 + rx0;
            } else {
                n = n0;
                y = slot / 18 - 1 + ry;
                x = slot % 18 - 1;
            }
            bool p = (y >= 0) && (y < HIN) && (x >= 0) && (x < HIN);
            int yc = p ? y : 0, xc = p ? x : 0;
            size_t base = (((size_t)n * HIN + yc) * HIN + xc) * CIN + ci0 + qd * 8;
            u32 doff = slot * SROW + qd * 16;
            cp16(uA + doff,      &in_hi[base], p);
            cp16(uA + doff + 64, &in_lo[base], p);
        }
        for (int idx = tid; idx < BROWS * 16; idx += 512) {
            int row = idx >> 4, qd = idx & 15;
            int co, wpar;
            if (MERGE_RX) { co = row & 63; wpar = ry * 2 + (row >> 6); }
            else          { co = row;      wpar = par; }
            size_t base = (((size_t)(wpar * NCHUNK + s) * COUT + co) << 7) + qd * 8;
            u32 doff = row * SROWB + qd * 16;
            cp16(uB + doff,       &w_hi[base], true);
            cp16(uB + doff + 256, &w_lo[base], true);
        }
        cp_commit();
    };

    const int lrow = lid & 15;
    const int lcol = (lid >> 4) << 4;
    int bslot[2];
#pragma unroll
    for (int tm = 0; tm < 2; tm++) {
        int row = wm * 32 + tm * 16 + lrow;
        if (SAMPLE_MODE) {
            int smp = row >> 6, q = row & 63;
            bslot[tm] = smp * 81 + (q >> 3) * 9 + (q & 7);
        } else {
            bslot[tm] = (row >> 4) * 18 + (row & 15);
        }
    }

    float acc[NPAR][2][NF8][4];
#pragma unroll
    for (int p = 0; p < NPAR; p++)
#pragma unroll
        for (int t = 0; t < 2; t++)
#pragma unroll
            for (int f = 0; f < NF8; f++)
#pragma unroll
                for (int j = 0; j < 4; j++) acc[p][t][f][j] = 0.f;

    load_stage(0, 0);

    for (int s = 0; s < NCHUNK; s++) {
        const int buf = s & 1;
        if (s + 1 < NCHUNK) { load_stage(s + 1, buf ^ 1); cp_wait1(); }
        else                { cp_wait0(); }
        __syncthreads();

        const u32 uA = u0 + buf * STAGEB;
        const u32 uB = uA + ABYTES;
#pragma unroll
        for (int tap = 0; tap < 4; tap++) {
            const int dy = tap >> 1, dx = tap & 1;
#pragma unroll
            for (int ks = 0; ks < 2; ks++) {
#pragma unroll
                for (int prx = 0; prx < NPAR; prx++) {
                    u32 ah[2][4], al[2][4];
#pragma unroll
                    for (int tm = 0; tm < 2; tm++) {
                        u32 aaddr = (u32)((bslot[tm] + dy * PW + dx + prx) * SROW) + ks * 32 + lcol;
                        ldsm4(ah[tm], uA + aaddr);
                        ldsm4(al[tm], uA + aaddr + 64);
                    }
#pragma unroll
                    for (int g = 0; g < NG; g++) {
                        u32 bh[4], bl[4];
                        u32 baddr = (u32)((prx * COUT + wn * (COUT / 2) + g * 16 + lrow) * SROWB)
                                    + tap * 64 + ks * 32 + lcol;
                        ldsm4(bh, uB + baddr);
                        ldsm4(bl, uB + baddr + 256);
#pragma unroll
                        for (int tm = 0; tm < 2; tm++) {
                            mma16816(acc[prx][tm][g * 2 + 0], ah[tm], bh[0], bh[2]);
                            mma16816(acc[prx][tm][g * 2 + 1], ah[tm], bh[1], bh[3]);
                        }
#pragma unroll
                        for (int tm = 0; tm < 2; tm++) {
                            mma16816(acc[prx][tm][g * 2 + 0], ah[tm], bl[0], bl[2]);
                            mma16816(acc[prx][tm][g * 2 + 1], ah[tm], bl[1], bl[3]);
                        }
#pragma unroll
                        for (int tm = 0; tm < 2; tm++) {
                            mma16816(acc[prx][tm][g * 2 + 0], al[tm], bh[0], bh[2]);
                            mma16816(acc[prx][tm][g * 2 + 1], al[tm], bh[1], bh[3]);
                        }
                    }
                }
            }
        }
        __syncthreads();
    }

    // ---- epilogue: ReLU + NHWC store ----
#pragma unroll
    for (int prx = 0; prx < NPAR; prx++) {
        const int rx = MERGE_RX ? prx : rx0;
#pragma unroll
        for (int tm = 0; tm < 2; tm++) {
            int r0 = wm * 32 + tm * 16 + (lid >> 2);
#pragma unroll
            for (int rr = 0; rr < 2; rr++) {
                int r = r0 + rr * 8;
                int n, yo, xo;
                if (SAMPLE_MODE) {
                    n = n0 + (r >> 6);
                    int q = r & 63;
                    yo = 2 * (q >> 3) + ry;
                    xo = 2 * (q & 7) + rx;
                } else {
                    n = n0;
                    yo = 2 * (r >> 4) + ry;
                    xo = 2 * (r & 15) + rx;
                }
                size_t obase = (((size_t)n * HOUT + yo) * HOUT + xo) * COUT;
#pragma unroll
                for (int f = 0; f < NF8; f++) {
                    int ch = wn * (COUT / 2) + f * 8 + (lid & 3) * 2;
                    float v0 = fmaxf(acc[prx][tm][f][rr * 2 + 0], 0.f);
                    float v1 = fmaxf(acc[prx][tm][f][rr * 2 + 1], 0.f);
                    if (OUT_BF16) {
                        u32 hp = bf16pack(v0, v1);
                        float2 hf = bf16unpk(hp);
                        u32 lp = bf16pack(v0 - hf.x, v1 - hf.y);
                        *(u32*)&out_hi[obase + ch] = hp;
                        *(u32*)&out_lo[obase + ch] = lp;
                    } else {
                        *(float2*)&out_f[obase + ch] = make_float2(v0, v1);
                    }
                }
            }
        }
    }
}

// ---------------- deconv3: 64 -> 3, NHWC fp32 input, NCHW output ----------------
__global__ __launch_bounds__(256) void deconv3_kernel(const float* __restrict__ in,
                                                      const float* __restrict__ wgt,
                                                      float* __restrict__ out) {
    int n = blockIdx.x;
    __shared__ float sin_[34 * 34 * 4];
    __shared__ float wsm[3 * 64 * 16 * 2];
    int tid = threadIdx.x;

    for (int idx = tid; idx < 3072; idx += 256) {
        int tap = idx & 15;
        int cc = idx >> 4;
        int co = cc % 3, ci = cc / 3;
        float w = wgt[(co * 64 + ci) * 16 + tap];
        wsm[((ci * 3 + co) * 16 + tap) * 2 + 0] = w;
        wsm[((ci * 3 + co) * 16 + tap) * 2 + 1] = w;
    }

    int qy0 = (tid >> 4) * 2;
    int qx0 = (tid & 15) * 2;
    u64 accp[3][8];
#pragma unroll
    for (int c = 0; c < 3; c++)
#pragma unroll
        for (int i = 0; i < 8; i++) accp[c][i] = 0ull;

    const float* in_n = in + (size_t)n * 1024 * 64;
    for (int ci0 = 0; ci0 < 64; ci0 += 4) {
        __syncthreads();
        for (int idx = tid; idx < 1156; idx += 256) {
            int py = idx / 34, px = idx % 34;
            int y = py - 1, x = px - 1;
            float4 v = make_float4(0.f, 0.f, 0.f, 0.f);
            if (y >= 0 && y < 32 && x >= 0 && x < 32)
                v = *(const float4*)&in_n[(y * 32 + x) * 64 + ci0];
            *(float4*)&sin_[idx * 4] = v;
        }
        __syncthreads();
#pragma unroll 1
        for (int ci = 0; ci < 4; ci++) {
            float iv[4][4];
#pragma unroll
            for (int yy = 0; yy < 4; yy++)
#pragma unroll
                for (int xx = 0; xx < 4; xx++)
                    iv[yy][xx] = sin_[((qy0 + yy) * 34 + qx0 + xx) * 4 + ci];
            u64 ivp2[4][3];
#pragma unroll
            for (int yy = 0; yy < 4; yy++)
#pragma unroll
                for (int xx = 0; xx < 3; xx++)
                    ivp2[yy][xx] = pack2(iv[yy][xx], iv[yy][xx + 1]);
#pragma unroll
            for (int co = 0; co < 3; co++) {
#pragma unroll
                for (int tap = 0; tap < 16; tap++) {
                    const int ky = tap >> 2, kx = tap & 3;
                    const int ry = ky & 1, dy = ky >> 1;
                    const int rx = kx & 1, dx = kx >> 1;
                    u64 wp = *(const u64*)&wsm[(((ci0 + ci) * 3 + co) * 16 + tap) * 2];
#pragma unroll
                    for (int qy = 0; qy < 2; qy++) {
                        const int o = qy * 4 + ry * 2 + rx;
                        accp[co][o] = fma2(wp, ivp2[qy + dy + ry][dx + rx], accp[co][o]);
                    }
                }
            }
        }
    }
    float* out_n = out + (size_t)n * 3 * 4096;
#pragma unroll
    for (int co = 0; co < 3; co++)
#pragma unroll
        for (int qy = 0; qy < 2; qy++)
#pragma unroll
            for (int ry = 0; ry < 2; ry++)
#pragma unroll
                for (int rx = 0; rx < 2; rx++) {
                    float2 v = unpk2(accp[co][qy * 4 + ry * 2 + rx]);
                    int yo = 2 * (qy0 + qy) + ry;
                    int xo0 = 2 * (qx0 + 0) + rx;
                    int xo1 = 2 * (qx0 + 1) + rx;
                    out_n[co * 4096 + yo * 64 + xo0] = v.x;
                    out_n[co * 4096 + yo * 64 + xo1] = v.y;
                }
}

// -----------------------------------------------------------------------------------------
extern "C" void kernel_launch(void* const* d_in, const int* in_sizes, int n_in,
                              void* d_out, int out_size) {
    (void)in_sizes; (void)n_in; (void)out_size;
    const float* angles   = (const float*)d_in[0];
    const float* item_rep = (const float*)d_in[1];
    const float* w0       = (const float*)d_in[2];
    const float* b0       = (const float*)d_in[3];
    const float* w1       = (const float*)d_in[4];
    const float* w2       = (const float*)d_in[5];
    const float* w3       = (const float*)d_in[6];
    float* out = (float*)d_out;

    float *p_h2, *p_b0r;
    cudaGetSymbolAddress((void**)&p_h2, g_h2);
    cudaGetSymbolAddress((void**)&p_b0r, g_b0r);
    __nv_bfloat16 *p_ithi, *p_itlo, *p_w0hi, *p_w0lo;
    cudaGetSymbolAddress((void**)&p_ithi, g_itemhi);
    cudaGetSymbolAddress((void**)&p_itlo, g_itemlo);
    cudaGetSymbolAddress((void**)&p_w0hi, g_w0hi);
    cudaGetSymbolAddress((void**)&p_w0lo, g_w0lo);
    __nv_bfloat16 *p_h0hi, *p_h0lo, *p_h1hi, *p_h1lo;
    cudaGetSymbolAddress((void**)&p_h0hi, g_h0hi);
    cudaGetSymbolAddress((void**)&p_h0lo, g_h0lo);
    cudaGetSymbolAddress((void**)&p_h1hi, g_h1hi);
    cudaGetSymbolAddress((void**)&p_h1lo, g_h1lo);
    __nv_bfloat16 *p_w1hi, *p_w1lo, *p_w2hi, *p_w2lo;
    cudaGetSymbolAddress((void**)&p_w1hi, g_w1hi);
    cudaGetSymbolAddress((void**)&p_w1lo, g_w1lo);
    cudaGetSymbolAddress((void**)&p_w2hi, g_w2hi);
    cudaGetSymbolAddress((void**)&p_w2lo, g_w2lo);

    constexpr int SMEMD = 2 * (324 * 144 + 128 * 528);  // 228480
    constexpr int SMEMG = 2 * 4 * 128 * 80;             // 81920
    cudaFuncSetAttribute(deconv_mma_kernel<256, 128, 8, false, true>,
                         cudaFuncAttributeMaxDynamicSharedMemorySize, SMEMD);
    cudaFuncSetAttribute(deconv_mma_kernel<128, 64, 16, true, false>,
                         cudaFuncAttributeMaxDynamicSharedMemorySize, SMEMD);
    cudaFuncSetAttribute(dense_mma_kernel,
                         cudaFuncAttributeMaxDynamicSharedMemorySize, SMEMG);

    const int REPACK_TOTAL = 4 * 8 * 128 * 128 + 4 * 4 * 64 * 128 + DENSE_N * FEAT + DENSE_N;
    init_jd_kernel<<<1, 288>>>();
    repack_all_kernel<<<(REPACK_TOTAL + 255) / 256, 256>>>(w1, w2, w0, b0);
    wigner_kernel<<<(N_SAMP * REP * 6 + 127) / 128, 128>>>(angles, item_rep);
    dense_mma_kernel<<<dim3(DENSE_N / 128, N_SAMP / 128), 256, SMEMG>>>(
        p_ithi, p_itlo, p_w0hi, p_w0lo, p_b0r, p_h0hi, p_h0lo);
    deconv_mma_kernel<256, 128, 8, false, true><<<dim3(512, 4), 512, SMEMD>>>(
        p_h0hi, p_h0lo, p_w1hi, p_w1lo, p_h1hi, p_h1lo, nullptr);
    deconv_mma_kernel<128, 64, 16, true, false><<<dim3(2048, 2), 512, SMEMD>>>(
        p_h1hi, p_h1lo, p_w2hi, p_w2lo, nullptr, nullptr, p_h2);
    deconv3_kernel<<<N_SAMP, 256>>>(p_h2, w3, out);
}

// round 10
// speedup vs baseline: 1.6315x; 1.2572x over previous
#include <cuda_runtime.h>
#include <cuda_fp16.h>
#include <math.h>
#include <stdint.h>

typedef unsigned int u32;
typedef unsigned long long u64;

#define N_SAMP 2048
#define MDIMS  36
#define REP    10
#define FEAT   360
#define DENSE_N 16384        // 256*8*8

// ---------------- packed f32x2 helpers ----------------
__device__ __forceinline__ u64 fma2(u64 a, u64 b, u64 c) {
    u64 d;
    asm("fma.rn.f32x2 %0, %1, %2, %3;" : "=l"(d) : "l"(a), "l"(b), "l"(c));
    return d;
}
__device__ __forceinline__ u64 pack2(float lo, float hi) {
    u64 r; unsigned a = __float_as_uint(lo), b = __float_as_uint(hi);
    asm("mov.b64 %0, {%1, %2};" : "=l"(r) : "r"(a), "r"(b));
    return r;
}
__device__ __forceinline__ float2 unpk2(u64 p) {
    unsigned lo, hi;
    asm("mov.b64 {%0, %1}, %2;" : "=r"(lo), "=r"(hi) : "l"(p));
    return make_float2(__uint_as_float(lo), __uint_as_float(hi));
}

// ---------------- fp16 pack/unpack ----------------
__device__ __forceinline__ u32 f16pack(float lo, float hi) {
    u32 r;
    asm("cvt.rn.f16x2.f32 %0, %1, %2;" : "=r"(r) : "f"(hi), "f"(lo));
    return r;
}
__device__ __forceinline__ float2 f16unpk(u32 u) {
    __half2 h = *reinterpret_cast<__half2*>(&u);
    return __half22float2(h);
}

// ---------------- warp MMA + cp.async helpers ----------------
__device__ __forceinline__ u32 smem_to_u32(const void* p) {
    u32 a;
    asm("{ .reg .u64 t; cvta.to.shared.u64 t, %1; cvt.u32.u64 %0, t; }" : "=r"(a) : "l"(p));
    return a;
}
__device__ __forceinline__ void ldsm4(u32* r, u32 addr) {
    asm volatile("ldmatrix.sync.aligned.m8n8.x4.shared.b16 {%0,%1,%2,%3}, [%4];"
                 : "=r"(r[0]), "=r"(r[1]), "=r"(r[2]), "=r"(r[3]) : "r"(addr));
}
__device__ __forceinline__ void mma16816f(float* d, const u32* a, u32 b0, u32 b1) {
    asm volatile(
        "mma.sync.aligned.m16n8k16.row.col.f32.f16.f16.f32 "
        "{%0,%1,%2,%3}, {%4,%5,%6,%7}, {%8,%9}, {%0,%1,%2,%3};"
        : "+f"(d[0]), "+f"(d[1]), "+f"(d[2]), "+f"(d[3])
        : "r"(a[0]), "r"(a[1]), "r"(a[2]), "r"(a[3]), "r"(b0), "r"(b1));
}
__device__ __forceinline__ void cp16(u32 dst, const void* src, bool p) {
    asm volatile("cp.async.cg.shared.global [%0], [%1], 16, %2;"
                 :: "r"(dst), "l"(src), "r"(p ? 16 : 0) : "memory");
}
__device__ __forceinline__ void cp_commit() {
    asm volatile("cp.async.commit_group;" ::: "memory");
}
__device__ __forceinline__ void cp_wait1() {
    asm volatile("cp.async.wait_group 1;" ::: "memory");
}
__device__ __forceinline__ void cp_wait0() {
    asm volatile("cp.async.wait_group 0;" ::: "memory");
}

// ---------------- scratch ----------------
__device__ float g_JD[286];
__device__ __align__(16) __half g_itemhi[N_SAMP * FEAT];
__device__ __align__(16) __half g_itemlo[N_SAMP * FEAT];
__device__ __align__(16) __half g_h0hi[N_SAMP * 16384];      // NHWC [n,8,8,256]
__device__ __align__(16) __half g_h0lo[N_SAMP * 16384];
__device__ __align__(16) __half g_h1hi[N_SAMP * 256 * 128];  // NHWC [n,16,16,128]
__device__ __align__(16) __half g_h1lo[N_SAMP * 256 * 128];
__device__ __align__(16) float g_h2[N_SAMP * 1024 * 64];     // NHWC [n,32,32,64] fp32
__device__ __align__(16) __half g_w1h[4 * 128 * 1024];       // [par][chunk][co][tap*32+ci]
__device__ __align__(16) __half g_w2h[4 * 64 * 512];
__device__ __align__(16) __half g_w0h[DENSE_N * FEAT];       // [j'=pix*256+c][k]
__device__ __align__(16) float g_b0r[DENSE_N];

__device__ __constant__ int c_off[7] = {0, 1, 10, 35, 84, 165, 286};

// ---------------- J_l math ----------------
__device__ double dfact(int n) { double r = 1.0; for (int i = 2; i <= n; i++) r *= (double)i; return r; }

__device__ double small_d(int l, int mp, int m) {
    const double ch = 0.70710678118654752440, sh = 0.70710678118654752440;
    double pref = sqrt(dfact(l + mp) * dfact(l - mp) * dfact(l + m) * dfact(l - m));
    int smin = max(0, m - mp), smax = min(l + m, l - mp);
    double tot = 0.0;
    for (int s = smin; s <= smax; s++) {
        double sign = ((mp - m + s) & 1) ? -1.0 : 1.0;
        double denom = dfact(l + m - s) * dfact(s) * dfact(mp - m + s) * dfact(l - mp - s);
        tot += sign / denom * pow(ch, (double)(2 * l + m - mp - 2 * s)) * pow(sh, (double)(mp - m + 2 * s));
    }
    return pref * tot;
}

__device__ void c2r_row(int l, int i, int* col, double* re, double* im, int* cnt) {
    int m = i - l;
    const double s = 0.70710678118654752440;
    if (m < 0) {
        double sgn = (m & 1) ? -1.0 : 1.0;
        col[0] = l + m; re[0] = 0.0; im[0] = s;
        col[1] = l - m; re[1] = 0.0; im[1] = -sgn * s;
        *cnt = 2;
    } else if (m == 0) {
        col[0] = l; re[0] = 1.0; im[0] = 0.0; *cnt = 1;
    } else {
        double sgn = (m & 1) ? -1.0 : 1.0;
        col[0] = l - m; re[0] = s;        im[0] = 0.0;
        col[1] = l + m; re[1] = sgn * s;  im[1] = 0.0;
        *cnt = 2;
    }
}

__device__ void jd_entry(int idx) {
    int l = 0;
    while (idx >= c_off[l + 1]) l++;
    int e = idx - c_off[l];
    int sz = 2 * l + 1;
    int i = e / sz, j = e % sz;
    int ca_c[2], cb_c[2], na, nb;
    double ca_re[2], ca_im[2], cb_re[2], cb_im[2];
    c2r_row(l, i, ca_c, ca_re, ca_im, &na);
    c2r_row(l, j, cb_c, cb_re, cb_im, &nb);
    double acc = 0.0;
    for (int a = 0; a < na; a++)
        for (int b = 0; b < nb; b++) {
            double cross = ca_re[a] * cb_re[b] + ca_im[a] * cb_im[b];
            if (cross != 0.0) acc += cross * small_d(l, ca_c[a] - l, cb_c[b] - l);
        }
    g_JD[idx] = (float)acc;
}

// ------- combined setup kernel: w1, w2, w0(permuted), b0(permuted), J_l -------
__device__ __forceinline__ void repack_wgt(const float* w, __half* bh,
                                           int i, int COUT, int CIN, int NCHUNK) {
    int cii = i & 31;
    int tap = (i >> 5) & 3;
    int co  = (i >> 7) % COUT;
    int chunk = (i / (128 * COUT)) % NCHUNK;
    int par = i / (128 * COUT * NCHUNK);
    int ci = chunk * 32 + cii;
    int dy = tap >> 1, dx = tap & 1, ry = par >> 1, rx = par & 1;
    float v = w[((co * CIN + ci) * 4 + (2 * dy + ry)) * 4 + (2 * dx + rx)];
    bh[i] = __float2half(v);
}

__global__ void setup_kernel(const float* __restrict__ w1, const float* __restrict__ w2,
                             const float* __restrict__ w0, const float* __restrict__ b0) {
    const int T1 = 4 * 8 * 128 * 128;      // 524288
    const int T2 = 4 * 4 * 64 * 128;       // 131072
    const int T0 = DENSE_N * FEAT;         // 5898240
    int idx = blockIdx.x * 256 + threadIdx.x;
    if (idx < T1) {
        repack_wgt(w1, g_w1h, idx, 128, 256, 8);
    } else if (idx < T1 + T2) {
        repack_wgt(w2, g_w2h, idx - T1, 64, 128, 4);
    } else if (idx < T1 + T2 + T0) {
        int i = idx - T1 - T2;
        int jp = i / FEAT, k = i % FEAT;
        int pix = jp >> 8, c = jp & 255;
        g_w0h[i] = __float2half(w0[(size_t)k * DENSE_N + c * 64 + pix]);
    } else if (idx < T1 + T2 + T0 + DENSE_N) {
        int jp = idx - T1 - T2 - T0;
        g_b0r[jp] = b0[(jp & 255) * 64 + (jp >> 8)];
    } else if (idx < T1 + T2 + T0 + DENSE_N + 286) {
        jd_entry(idx - T1 - T2 - T0 - DENSE_N);
    }
}

// ---------------- Wigner (parallel over l) -> item fp16 hi/lo ----------------
__device__ __forceinline__ void zrot_apply(const float* v, int sz, int l, float ang, float* out) {
    for (int i = 0; i < sz; i++) {
        float f = (float)(l - i);
        float s, c;
        sincosf(f * ang, &s, &c);
        out[i] = c * v[i] + s * v[sz - 1 - i];
    }
}

__global__ void wigner_kernel(const float* __restrict__ angles, const float* __restrict__ item_rep) {
    int t = blockIdx.x * blockDim.x + threadIdx.x;
    if (t >= N_SAMP * REP * 6) return;
    int l = t % 6;
    int nr = t / 6;
    int n = nr / REP, r = nr % REP;
    float a0 = angles[n * 3 + 0], a1 = angles[n * 3 + 1], a2 = angles[n * 3 + 2];
    float v[11], w[11];
    int sz = 2 * l + 1;
    const float* J = &g_JD[c_off[l]];
    for (int i = 0; i < sz; i++) v[i] = item_rep[(l * l + i) * REP + r];
    zrot_apply(v, sz, l, a2, w);
    for (int i = 0; i < sz; i++) { float s = 0.f; for (int j = 0; j < sz; j++) s += J[i * sz + j] * w[j]; v[i] = s; }
    zrot_apply(v, sz, l, a1, w);
    for (int i = 0; i < sz; i++) { float s = 0.f; for (int j = 0; j < sz; j++) s += J[i * sz + j] * w[j]; v[i] = s; }
    zrot_apply(v, sz, l, a0, w);
    for (int i = 0; i < sz; i++) {
        size_t o = (size_t)n * FEAT + (l * l + i) * REP + r;
        float val = w[i];
        __half h = __float2half(val);
        g_itemhi[o] = h;
        g_itemlo[o] = __float2half(val - __half2float(h));
    }
}

// ---------------- dense HMMA: h0 = relu(item @ w0r + b0r), output IS NHWC ----------------
// A fp16-split (exact), B single fp16 -> 2 MMA terms.
__global__ __launch_bounds__(256) void dense_mma_kernel(
    const __half* __restrict__ ahi, const __half* __restrict__ alo,
    const __half* __restrict__ bh_, const float* __restrict__ biasr,
    __half* __restrict__ chi, __half* __restrict__ clo) {
    constexpr int SROW = 80;
    constexpr int SLAB = 128 * SROW;       // 10240
    constexpr int STAGEB = 3 * SLAB;       // 30720
    constexpr int KCH = 12;                // 12 chunks of 32 (360 zero-padded to 384)

    extern __shared__ __align__(16) char smem[];
    const u32 u0 = smem_to_u32(smem);
    const int tid = threadIdx.x;
    const int wid = tid >> 5, lid = tid & 31;
    const int wm = wid >> 1, wn = wid & 1;
    const int nb0 = blockIdx.x * 128;
    const int m0  = blockIdx.y * 128;

    auto load_stage = [&](int s, int buf) {
        const int k0 = s * 32;
        const u32 uAh = u0 + buf * STAGEB;
        const u32 uAl = uAh + SLAB;
        const u32 uB  = uAl + SLAB;
#pragma unroll
        for (int t = 0; t < 2; t++) {
            int idx = tid + t * 256;
            int row = idx >> 2, qd = idx & 3;
            int k = k0 + qd * 8;
            bool p = k < FEAT;
            int kc = p ? k : (FEAT - 8);
            u32 doff = row * SROW + qd * 16;
            cp16(uAh + doff, &ahi[(size_t)(m0 + row) * FEAT + kc], p);
            cp16(uAl + doff, &alo[(size_t)(m0 + row) * FEAT + kc], p);
            cp16(uB  + doff, &bh_[(size_t)(nb0 + row) * FEAT + kc], p);
        }
        cp_commit();
    };

    const int lrow = lid & 15;
    const int lcol = (lid >> 4) << 4;

    float acc[2][8][4];
#pragma unroll
    for (int t = 0; t < 2; t++)
#pragma unroll
        for (int f = 0; f < 8; f++)
#pragma unroll
            for (int j = 0; j < 4; j++) acc[t][f][j] = 0.f;

    load_stage(0, 0);

    for (int s = 0; s < KCH; s++) {
        const int buf = s & 1;
        if (s + 1 < KCH) { load_stage(s + 1, buf ^ 1); cp_wait1(); }
        else             { cp_wait0(); }
        __syncthreads();
        const u32 uAh = u0 + buf * STAGEB;
        const u32 uAl = uAh + SLAB;
        const u32 uB  = uAl + SLAB;
#pragma unroll
        for (int ks = 0; ks < 2; ks++) {
            u32 ah[2][4], al[2][4], bh[4][4];
#pragma unroll
            for (int tm = 0; tm < 2; tm++) {
                u32 aaddr = (u32)((wm * 32 + tm * 16 + lrow) * SROW) + ks * 32 + lcol;
                ldsm4(ah[tm], uAh + aaddr);
                ldsm4(al[tm], uAl + aaddr);
            }
#pragma unroll
            for (int g = 0; g < 4; g++) {
                u32 baddr = (u32)((wn * 64 + g * 16 + lrow) * SROW) + ks * 32 + lcol;
                ldsm4(bh[g], uB + baddr);
            }
#pragma unroll
            for (int tm = 0; tm < 2; tm++)
#pragma unroll
                for (int g = 0; g < 4; g++)
#pragma unroll
                    for (int h = 0; h < 2; h++)
                        mma16816f(acc[tm][g * 2 + h], ah[tm], bh[g][h], bh[g][h + 2]);
#pragma unroll
            for (int tm = 0; tm < 2; tm++)
#pragma unroll
                for (int g = 0; g < 4; g++)
#pragma unroll
                    for (int h = 0; h < 2; h++)
                        mma16816f(acc[tm][g * 2 + h], al[tm], bh[g][h], bh[g][h + 2]);
        }
        __syncthreads();
    }

#pragma unroll
    for (int tm = 0; tm < 2; tm++) {
#pragma unroll
        for (int rr = 0; rr < 2; rr++) {
            int r = m0 + wm * 32 + tm * 16 + (lid >> 2) + rr * 8;
            size_t obase = (size_t)r * DENSE_N + nb0;
#pragma unroll
            for (int f = 0; f < 8; f++) {
                int jc = wn * 64 + f * 8 + (lid & 3) * 2;
                float v0 = fmaxf(acc[tm][f][rr * 2 + 0] + biasr[nb0 + jc], 0.f);
                float v1 = fmaxf(acc[tm][f][rr * 2 + 1] + biasr[nb0 + jc + 1], 0.f);
                u32 hp = f16pack(v0, v1);
                float2 hf = f16unpk(hp);
                u32 lp = f16pack(v0 - hf.x, v1 - hf.y);
                *(u32*)&chi[obase + jc] = hp;
                *(u32*)&clo[obase + jc] = lp;
            }
        }
    }
}

// ------- HMMA implicit-GEMM deconv, M=256/CTA, fused A hi/lo rows, B single fp16 --------
template <int CIN, int COUT, int HIN, bool MERGE_RX, bool OUT_F16>
__global__ __launch_bounds__(512) void deconv_mma_kernel(
    const __half* __restrict__ in_hi, const __half* __restrict__ in_lo,
    const __half* __restrict__ w_h,
    __half* __restrict__ out_hi, __half* __restrict__ out_lo,
    float* __restrict__ out_f) {
    constexpr int NCHUNK = CIN / 32;
    constexpr int HOUT = 2 * HIN;
    constexpr bool SAMPLE_MODE = (HIN == 8);
    constexpr int PW = SAMPLE_MODE ? 9 : 18;
    constexpr int SLOTS = 324;             // 4*81 or 18*18
    constexpr int SROW = 144;              // [64B hi][64B lo][16 pad]
    constexpr int ABYTES = SLOTS * SROW;   // 46656
    constexpr int SROWB = 272;             // [256B w][16 pad]
    constexpr int BROWS = 128;             // 128 co | 2par x 64 co
    constexpr int BBYTES = BROWS * SROWB;  // 34816
    constexpr int STAGEB = ABYTES + BBYTES;// 81472
    constexpr int NPAR = MERGE_RX ? 2 : 1;
    constexpr int NG = COUT / 32;          // 4 | 2
    constexpr int NF8 = COUT / 16;         // 8 | 4

    extern __shared__ __align__(16) char smem[];
    const u32 u0 = smem_to_u32(smem);

    const int tid = threadIdx.x;
    const int wid = tid >> 5;
    const int lid = tid & 31;
    const int wm = wid >> 1;               // 0..7, m32 tiles
    const int wn = wid & 1;
    const int par = blockIdx.y;
    const int ry = MERGE_RX ? par : (par >> 1);
    const int rx0 = MERGE_RX ? 0 : (par & 1);
    const int n0 = SAMPLE_MODE ? blockIdx.x * 4 : blockIdx.x;

    auto load_stage = [&](int s, int buf) {
        const int ci0 = s * 32;
        const u32 uA = u0 + buf * STAGEB;
        const u32 uB = uA + ABYTES;
        for (int idx = tid; idx < SLOTS * 4; idx += 512) {
            int slot = idx >> 2, qd = idx & 3;
            int n, y, x;
            if (SAMPLE_MODE) {
                int smp = slot / 81, rr = slot % 81;
                n = n0 + smp;
                y = rr / 9 - 1 + ry;
                x = rr % 9 - 1 + rx0;
            } else {
                n = n0;
                y = slot / 18 - 1 + ry;
                x = slot % 18 - 1;
            }
            bool p = (y >= 0) && (y < HIN) && (x >= 0) && (x < HIN);
            int yc = p ? y : 0, xc = p ? x : 0;
            size_t base = (((size_t)n * HIN + yc) * HIN + xc) * CIN + ci0 + qd * 8;
            u32 doff = slot * SROW + qd * 16;
            cp16(uA + doff,      &in_hi[base], p);
            cp16(uA + doff + 64, &in_lo[base], p);
        }
        for (int idx = tid; idx < BROWS * 16; idx += 512) {
            int row = idx >> 4, qd = idx & 15;
            int co, wpar;
            if (MERGE_RX) { co = row & 63; wpar = ry * 2 + (row >> 6); }
            else          { co = row;      wpar = par; }
            size_t base = (((size_t)(wpar * NCHUNK + s) * COUT + co) << 7) + qd * 8;
            cp16(uB + row * SROWB + qd * 16, &w_h[base], true);
        }
        cp_commit();
    };

    const int lrow = lid & 15;
    const int lcol = (lid >> 4) << 4;
    int bslot[2];
#pragma unroll
    for (int tm = 0; tm < 2; tm++) {
        int row = wm * 32 + tm * 16 + lrow;
        if (SAMPLE_MODE) {
            int smp = row >> 6, q = row & 63;
            bslot[tm] = smp * 81 + (q >> 3) * 9 + (q & 7);
        } else {
            bslot[tm] = (row >> 4) * 18 + (row & 15);
        }
    }

    float acc[NPAR][2][NF8][4];
#pragma unroll
    for (int p = 0; p < NPAR; p++)
#pragma unroll
        for (int t = 0; t < 2; t++)
#pragma unroll
            for (int f = 0; f < NF8; f++)
#pragma unroll
                for (int j = 0; j < 4; j++) acc[p][t][f][j] = 0.f;

    load_stage(0, 0);

    for (int s = 0; s < NCHUNK; s++) {
        const int buf = s & 1;
        if (s + 1 < NCHUNK) { load_stage(s + 1, buf ^ 1); cp_wait1(); }
        else                { cp_wait0(); }
        __syncthreads();

        const u32 uA = u0 + buf * STAGEB;
        const u32 uB = uA + ABYTES;
#pragma unroll
        for (int tap = 0; tap < 4; tap++) {
            const int dy = tap >> 1, dx = tap & 1;
#pragma unroll
            for (int ks = 0; ks < 2; ks++) {
#pragma unroll
                for (int prx = 0; prx < NPAR; prx++) {
                    u32 ah[2][4], al[2][4];
#pragma unroll
                    for (int tm = 0; tm < 2; tm++) {
                        u32 aaddr = (u32)((bslot[tm] + dy * PW + dx + prx) * SROW) + ks * 32 + lcol;
                        ldsm4(ah[tm], uA + aaddr);
                        ldsm4(al[tm], uA + aaddr + 64);
                    }
#pragma unroll
                    for (int g = 0; g < NG; g++) {
                        u32 bh[4];
                        u32 baddr = (u32)((prx * COUT + wn * (COUT / 2) + g * 16 + lrow) * SROWB)
                                    + tap * 64 + ks * 32 + lcol;
                        ldsm4(bh, uB + baddr);
#pragma unroll
                        for (int tm = 0; tm < 2; tm++) {
                            mma16816f(acc[prx][tm][g * 2 + 0], ah[tm], bh[0], bh[2]);
                            mma16816f(acc[prx][tm][g * 2 + 1], ah[tm], bh[1], bh[3]);
                        }
#pragma unroll
                        for (int tm = 0; tm < 2; tm++) {
                            mma16816f(acc[prx][tm][g * 2 + 0], al[tm], bh[0], bh[2]);
                            mma16816f(acc[prx][tm][g * 2 + 1], al[tm], bh[1], bh[3]);
                        }
                    }
                }
            }
        }
        __syncthreads();
    }

    // ---- epilogue: ReLU + NHWC store ----
#pragma unroll
    for (int prx = 0; prx < NPAR; prx++) {
        const int rx = MERGE_RX ? prx : rx0;
#pragma unroll
        for (int tm = 0; tm < 2; tm++) {
            int r0 = wm * 32 + tm * 16 + (lid >> 2);
#pragma unroll
            for (int rr = 0; rr < 2; rr++) {
                int r = r0 + rr * 8;
                int n, yo, xo;
                if (SAMPLE_MODE) {
                    n = n0 + (r >> 6);
                    int q = r & 63;
                    yo = 2 * (q >> 3) + ry;
                    xo = 2 * (q & 7) + rx;
                } else {
                    n = n0;
                    yo = 2 * (r >> 4) + ry;
                    xo = 2 * (r & 15) + rx;
                }
                size_t obase = (((size_t)n * HOUT + yo) * HOUT + xo) * COUT;
#pragma unroll
                for (int f = 0; f < NF8; f++) {
                    int ch = wn * (COUT / 2) + f * 8 + (lid & 3) * 2;
                    float v0 = fmaxf(acc[prx][tm][f][rr * 2 + 0], 0.f);
                    float v1 = fmaxf(acc[prx][tm][f][rr * 2 + 1], 0.f);
                    if (OUT_F16) {
                        u32 hp = f16pack(v0, v1);
                        float2 hf = f16unpk(hp);
                        u32 lp = f16pack(v0 - hf.x, v1 - hf.y);
                        *(u32*)&out_hi[obase + ch] = hp;
                        *(u32*)&out_lo[obase + ch] = lp;
                    } else {
                        *(float2*)&out_f[obase + ch] = make_float2(v0, v1);
                    }
                }
            }
        }
    }
}

// ---------------- deconv3: 64 -> 3, NHWC fp32 input, NCHW output ----------------
__global__ __launch_bounds__(256) void deconv3_kernel(const float* __restrict__ in,
                                                      const float* __restrict__ wgt,
                                                      float* __restrict__ out) {
    int n = blockIdx.x;
    __shared__ float sin_[34 * 34 * 4];
    __shared__ float wsm[3 * 64 * 16 * 2];
    int tid = threadIdx.x;

    for (int idx = tid; idx < 3072; idx += 256) {
        int tap = idx & 15;
        int cc = idx >> 4;
        int co = cc % 3, ci = cc / 3;
        float w = wgt[(co * 64 + ci) * 16 + tap];
        wsm[((ci * 3 + co) * 16 + tap) * 2 + 0] = w;
        wsm[((ci * 3 + co) * 16 + tap) * 2 + 1] = w;
    }

    int qy0 = (tid >> 4) * 2;
    int qx0 = (tid & 15) * 2;
    u64 accp[3][8];
#pragma unroll
    for (int c = 0; c < 3; c++)
#pragma unroll
        for (int i = 0; i < 8; i++) accp[c][i] = 0ull;

    const float* in_n = in + (size_t)n * 1024 * 64;
    for (int ci0 = 0; ci0 < 64; ci0 += 4) {
        __syncthreads();
        for (int idx = tid; idx < 1156; idx += 256) {
            int py = idx / 34, px = idx % 34;
            int y = py - 1, x = px - 1;
            float4 v = make_float4(0.f, 0.f, 0.f, 0.f);
            if (y >= 0 && y < 32 && x >= 0 && x < 32)
                v = *(const float4*)&in_n[(y * 32 + x) * 64 + ci0];
            *(float4*)&sin_[idx * 4] = v;
        }
        __syncthreads();
#pragma unroll 1
        for (int ci = 0; ci < 4; ci++) {
            float iv[4][4];
#pragma unroll
            for (int yy = 0; yy < 4; yy++)
#pragma unroll
                for (int xx = 0; xx < 4; xx++)
                    iv[yy][xx] = sin_[((qy0 + yy) * 34 + qx0 + xx) * 4 + ci];
            u64 ivp2[4][3];
#pragma unroll
            for (int yy = 0; yy < 4; yy++)
#pragma unroll
                for (int xx = 0; xx < 3; xx++)
                    ivp2[yy][xx] = pack2(iv[yy][xx], iv[yy][xx + 1]);
#pragma unroll
            for (int co = 0; co < 3; co++) {
#pragma unroll
                for (int tap = 0; tap < 16; tap++) {
                    const int ky = tap >> 2, kx = tap & 3;
                    const int ry = ky & 1, dy = ky >> 1;
                    const int rx = kx & 1, dx = kx >> 1;
                    u64 wp = *(const u64*)&wsm[(((ci0 + ci) * 3 + co) * 16 + tap) * 2];
#pragma unroll
                    for (int qy = 0; qy < 2; qy++) {
                        const int o = qy * 4 + ry * 2 + rx;
                        accp[co][o] = fma2(wp, ivp2[qy + dy + ry][dx + rx], accp[co][o]);
                    }
                }
            }
        }
    }
    float* out_n = out + (size_t)n * 3 * 4096;
#pragma unroll
    for (int co = 0; co < 3; co++)
#pragma unroll
        for (int qy = 0; qy < 2; qy++)
#pragma unroll
            for (int ry = 0; ry < 2; ry++)
#pragma unroll
                for (int rx = 0; rx < 2; rx++) {
                    float2 v = unpk2(accp[co][qy * 4 + ry * 2 + rx]);
                    int yo = 2 * (qy0 + qy) + ry;
                    int xo0 = 2 * (qx0 + 0) + rx;
                    int xo1 = 2 * (qx0 + 1) + rx;
                    out_n[co * 4096 + yo * 64 + xo0] = v.x;
                    out_n[co * 4096 + yo * 64 + xo1] = v.y;
                }
}

// -----------------------------------------------------------------------------------------
extern "C" void kernel_launch(void* const* d_in, const int* in_sizes, int n_in,
                              void* d_out, int out_size) {
    (void)in_sizes; (void)n_in; (void)out_size;
    const float* angles   = (const float*)d_in[0];
    const float* item_rep = (const float*)d_in[1];
    const float* w0       = (const float*)d_in[2];
    const float* b0       = (const float*)d_in[3];
    const float* w1       = (const float*)d_in[4];
    const float* w2       = (const float*)d_in[5];
    const float* w3       = (const float*)d_in[6];
    float* out = (float*)d_out;

    float *p_h2, *p_b0r;
    cudaGetSymbolAddress((void**)&p_h2, g_h2);
    cudaGetSymbolAddress((void**)&p_b0r, g_b0r);
    __half *p_ithi, *p_itlo, *p_w0h;
    cudaGetSymbolAddress((void**)&p_ithi, g_itemhi);
    cudaGetSymbolAddress((void**)&p_itlo, g_itemlo);
    cudaGetSymbolAddress((void**)&p_w0h, g_w0h);
    __half *p_h0hi, *p_h0lo, *p_h1hi, *p_h1lo;
    cudaGetSymbolAddress((void**)&p_h0hi, g_h0hi);
    cudaGetSymbolAddress((void**)&p_h0lo, g_h0lo);
    cudaGetSymbolAddress((void**)&p_h1hi, g_h1hi);
    cudaGetSymbolAddress((void**)&p_h1lo, g_h1lo);
    __half *p_w1h, *p_w2h;
    cudaGetSymbolAddress((void**)&p_w1h, g_w1h);
    cudaGetSymbolAddress((void**)&p_w2h, g_w2h);

    constexpr int SMEMD = 2 * (324 * 144 + 128 * 272);  // 162944
    constexpr int SMEMG = 2 * 3 * 128 * 80;             // 61440
    cudaFuncSetAttribute(deconv_mma_kernel<256, 128, 8, false, true>,
                         cudaFuncAttributeMaxDynamicSharedMemorySize, SMEMD);
    cudaFuncSetAttribute(deconv_mma_kernel<128, 64, 16, true, false>,
                         cudaFuncAttributeMaxDynamicSharedMemorySize, SMEMD);
    cudaFuncSetAttribute(dense_mma_kernel,
                         cudaFuncAttributeMaxDynamicSharedMemorySize, SMEMG);

    const int SETUP_TOTAL = 4 * 8 * 128 * 128 + 4 * 4 * 64 * 128 + DENSE_N * FEAT + DENSE_N + 286;
    setup_kernel<<<(SETUP_TOTAL + 255) / 256, 256>>>(w1, w2, w0, b0);
    wigner_kernel<<<(N_SAMP * REP * 6 + 127) / 128, 128>>>(angles, item_rep);
    dense_mma_kernel<<<dim3(DENSE_N / 128, N_SAMP / 128), 256, SMEMG>>>(
        p_ithi, p_itlo, p_w0h, p_b0r, p_h0hi, p_h0lo);
    deconv_mma_kernel<256, 128, 8, false, true><<<dim3(512, 4), 512, SMEMD>>>(
        p_h0hi, p_h0lo, p_w1h, p_h1hi, p_h1lo, nullptr);
    deconv_mma_kernel<128, 64, 16, true, false><<<dim3(2048, 2), 512, SMEMD>>>(
        p_h1hi, p_h1lo, p_w2h, nullptr, nullptr, p_h2);
    deconv3_kernel<<<N_SAMP, 256>>>(p_h2, w3, out);
}

// round 11
// speedup vs baseline: 1.7088x; 1.0474x over previous
#include <cuda_runtime.h>
#include <cuda_fp16.h>
#include <math.h>
#include <stdint.h>

typedef unsigned int u32;
typedef unsigned long long u64;

#define N_SAMP 2048
#define MDIMS  36
#define REP    10
#define FEAT   360
#define DENSE_N 16384        // 256*8*8

// ---------------- packed f32x2 helpers ----------------
__device__ __forceinline__ u64 fma2(u64 a, u64 b, u64 c) {
    u64 d;
    asm("fma.rn.f32x2 %0, %1, %2, %3;" : "=l"(d) : "l"(a), "l"(b), "l"(c));
    return d;
}
__device__ __forceinline__ u64 pack2(float lo, float hi) {
    u64 r; unsigned a = __float_as_uint(lo), b = __float_as_uint(hi);
    asm("mov.b64 %0, {%1, %2};" : "=l"(r) : "r"(a), "r"(b));
    return r;
}
__device__ __forceinline__ float2 unpk2(u64 p) {
    unsigned lo, hi;
    asm("mov.b64 {%0, %1}, %2;" : "=r"(lo), "=r"(hi) : "l"(p));
    return make_float2(__uint_as_float(lo), __uint_as_float(hi));
}

// ---------------- fp16 pack/unpack ----------------
__device__ __forceinline__ u32 f16pack(float lo, float hi) {
    u32 r;
    asm("cvt.rn.f16x2.f32 %0, %1, %2;" : "=r"(r) : "f"(hi), "f"(lo));
    return r;
}
__device__ __forceinline__ float2 f16unpk(u32 u) {
    __half2 h = *reinterpret_cast<__half2*>(&u);
    return __half22float2(h);
}

// ---------------- warp MMA + cp.async helpers ----------------
__device__ __forceinline__ u32 smem_to_u32(const void* p) {
    u32 a;
    asm("{ .reg .u64 t; cvta.to.shared.u64 t, %1; cvt.u32.u64 %0, t; }" : "=r"(a) : "l"(p));
    return a;
}
__device__ __forceinline__ void ldsm4(u32* r, u32 addr) {
    asm volatile("ldmatrix.sync.aligned.m8n8.x4.shared.b16 {%0,%1,%2,%3}, [%4];"
                 : "=r"(r[0]), "=r"(r[1]), "=r"(r[2]), "=r"(r[3]) : "r"(addr));
}
__device__ __forceinline__ void mma16816f(float* d, const u32* a, u32 b0, u32 b1) {
    asm volatile(
        "mma.sync.aligned.m16n8k16.row.col.f32.f16.f16.f32 "
        "{%0,%1,%2,%3}, {%4,%5,%6,%7}, {%8,%9}, {%0,%1,%2,%3};"
        : "+f"(d[0]), "+f"(d[1]), "+f"(d[2]), "+f"(d[3])
        : "r"(a[0]), "r"(a[1]), "r"(a[2]), "r"(a[3]), "r"(b0), "r"(b1));
}
__device__ __forceinline__ void cp16(u32 dst, const void* src, bool p) {
    asm volatile("cp.async.cg.shared.global [%0], [%1], 16, %2;"
                 :: "r"(dst), "l"(src), "r"(p ? 16 : 0) : "memory");
}
__device__ __forceinline__ void cp_commit() {
    asm volatile("cp.async.commit_group;" ::: "memory");
}
__device__ __forceinline__ void cp_wait1() {
    asm volatile("cp.async.wait_group 1;" ::: "memory");
}
__device__ __forceinline__ void cp_wait0() {
    asm volatile("cp.async.wait_group 0;" ::: "memory");
}

// ---------------- scratch ----------------
__device__ float g_JD[286];
__device__ __align__(16) __half g_itemhi[N_SAMP * FEAT];
__device__ __align__(16) __half g_itemlo[N_SAMP * FEAT];
__device__ __align__(16) __half g_h0hi[N_SAMP * 16384];      // NHWC [n,8,8,256]
__device__ __align__(16) __half g_h0lo[N_SAMP * 16384];
__device__ __align__(16) __half g_h1hi[N_SAMP * 256 * 128];  // NHWC [n,16,16,128]
__device__ __align__(16) __half g_h1lo[N_SAMP * 256 * 128];
__device__ __align__(16) float g_h2[N_SAMP * 1024 * 64];     // NHWC [n,32,32,64] fp32
__device__ __align__(16) __half g_w1h[4 * 128 * 1024];       // [par][chunk16][co][tap*16+ci]
__device__ __align__(16) __half g_w2h[4 * 64 * 512];
__device__ __align__(16) __half g_w0h[DENSE_N * FEAT];       // [j'=pix*256+c][k]
__device__ __align__(16) float g_b0r[DENSE_N];

__device__ __constant__ int c_off[7] = {0, 1, 10, 35, 84, 165, 286};

// ---------------- J_l math ----------------
__device__ double dfact(int n) { double r = 1.0; for (int i = 2; i <= n; i++) r *= (double)i; return r; }

__device__ double small_d(int l, int mp, int m) {
    const double ch = 0.70710678118654752440, sh = 0.70710678118654752440;
    double pref = sqrt(dfact(l + mp) * dfact(l - mp) * dfact(l + m) * dfact(l - m));
    int smin = max(0, m - mp), smax = min(l + m, l - mp);
    double tot = 0.0;
    for (int s = smin; s <= smax; s++) {
        double sign = ((mp - m + s) & 1) ? -1.0 : 1.0;
        double denom = dfact(l + m - s) * dfact(s) * dfact(mp - m + s) * dfact(l - mp - s);
        tot += sign / denom * pow(ch, (double)(2 * l + m - mp - 2 * s)) * pow(sh, (double)(mp - m + 2 * s));
    }
    return pref * tot;
}

__device__ void c2r_row(int l, int i, int* col, double* re, double* im, int* cnt) {
    int m = i - l;
    const double s = 0.70710678118654752440;
    if (m < 0) {
        double sgn = (m & 1) ? -1.0 : 1.0;
        col[0] = l + m; re[0] = 0.0; im[0] = s;
        col[1] = l - m; re[1] = 0.0; im[1] = -sgn * s;
        *cnt = 2;
    } else if (m == 0) {
        col[0] = l; re[0] = 1.0; im[0] = 0.0; *cnt = 1;
    } else {
        double sgn = (m & 1) ? -1.0 : 1.0;
        col[0] = l - m; re[0] = s;        im[0] = 0.0;
        col[1] = l + m; re[1] = sgn * s;  im[1] = 0.0;
        *cnt = 2;
    }
}

__device__ void jd_entry(int idx) {
    int l = 0;
    while (idx >= c_off[l + 1]) l++;
    int e = idx - c_off[l];
    int sz = 2 * l + 1;
    int i = e / sz, j = e % sz;
    int ca_c[2], cb_c[2], na, nb;
    double ca_re[2], ca_im[2], cb_re[2], cb_im[2];
    c2r_row(l, i, ca_c, ca_re, ca_im, &na);
    c2r_row(l, j, cb_c, cb_re, cb_im, &nb);
    double acc = 0.0;
    for (int a = 0; a < na; a++)
        for (int b = 0; b < nb; b++) {
            double cross = ca_re[a] * cb_re[b] + ca_im[a] * cb_im[b];
            if (cross != 0.0) acc += cross * small_d(l, ca_c[a] - l, cb_c[b] - l);
        }
    g_JD[idx] = (float)acc;
}

// ------- setup kernel: w1, w2 (16-ci chunks), w0(permuted), b0(permuted), J_l -------
__device__ __forceinline__ void repack_wgt(const float* w, __half* bh,
                                           int i, int COUT, int CIN, int NCHUNK) {
    int cii = i & 15;
    int tap = (i >> 4) & 3;
    int co  = (i >> 6) % COUT;
    int chunk = (i / (64 * COUT)) % NCHUNK;
    int par = i / (64 * COUT * NCHUNK);
    int ci = chunk * 16 + cii;
    int dy = tap >> 1, dx = tap & 1, ry = par >> 1, rx = par & 1;
    float v = w[((co * CIN + ci) * 4 + (2 * dy + ry)) * 4 + (2 * dx + rx)];
    bh[i] = __float2half(v);
}

__global__ void setup_kernel(const float* __restrict__ w1, const float* __restrict__ w2,
                             const float* __restrict__ w0, const float* __restrict__ b0) {
    const int T1 = 4 * 16 * 128 * 64;      // 524288
    const int T2 = 4 * 8 * 64 * 64;        // 131072
    const int T0 = DENSE_N * FEAT;         // 5898240
    int idx = blockIdx.x * 256 + threadIdx.x;
    if (idx < T1) {
        repack_wgt(w1, g_w1h, idx, 128, 256, 16);
    } else if (idx < T1 + T2) {
        repack_wgt(w2, g_w2h, idx - T1, 64, 128, 8);
    } else if (idx < T1 + T2 + T0) {
        int i = idx - T1 - T2;
        int jp = i / FEAT, k = i % FEAT;
        int pix = jp >> 8, c = jp & 255;
        g_w0h[i] = __float2half(w0[(size_t)k * DENSE_N + c * 64 + pix]);
    } else if (idx < T1 + T2 + T0 + DENSE_N) {
        int jp = idx - T1 - T2 - T0;
        g_b0r[jp] = b0[(jp & 255) * 64 + (jp >> 8)];
    } else if (idx < T1 + T2 + T0 + DENSE_N + 286) {
        jd_entry(idx - T1 - T2 - T0 - DENSE_N);
    }
}

// ---------------- Wigner (parallel over l) -> item fp16 hi/lo ----------------
__device__ __forceinline__ void zrot_apply(const float* v, int sz, int l, float ang, float* out) {
    for (int i = 0; i < sz; i++) {
        float f = (float)(l - i);
        float s, c;
        sincosf(f * ang, &s, &c);
        out[i] = c * v[i] + s * v[sz - 1 - i];
    }
}

__global__ void wigner_kernel(const float* __restrict__ angles, const float* __restrict__ item_rep) {
    int t = blockIdx.x * blockDim.x + threadIdx.x;
    if (t >= N_SAMP * REP * 6) return;
    int l = t % 6;
    int nr = t / 6;
    int n = nr / REP, r = nr % REP;
    float a0 = angles[n * 3 + 0], a1 = angles[n * 3 + 1], a2 = angles[n * 3 + 2];
    float v[11], w[11];
    int sz = 2 * l + 1;
    const float* J = &g_JD[c_off[l]];
    for (int i = 0; i < sz; i++) v[i] = item_rep[(l * l + i) * REP + r];
    zrot_apply(v, sz, l, a2, w);
    for (int i = 0; i < sz; i++) { float s = 0.f; for (int j = 0; j < sz; j++) s += J[i * sz + j] * w[j]; v[i] = s; }
    zrot_apply(v, sz, l, a1, w);
    for (int i = 0; i < sz; i++) { float s = 0.f; for (int j = 0; j < sz; j++) s += J[i * sz + j] * w[j]; v[i] = s; }
    zrot_apply(v, sz, l, a0, w);
    for (int i = 0; i < sz; i++) {
        size_t o = (size_t)n * FEAT + (l * l + i) * REP + r;
        float val = w[i];
        __half h = __float2half(val);
        g_itemhi[o] = h;
        g_itemlo[o] = __float2half(val - __half2float(h));
    }
}

// ---------------- dense HMMA: h0 = relu(item @ w0r + b0r), output IS NHWC ----------------
__global__ __launch_bounds__(256) void dense_mma_kernel(
    const __half* __restrict__ ahi, const __half* __restrict__ alo,
    const __half* __restrict__ bh_, const float* __restrict__ biasr,
    __half* __restrict__ chi, __half* __restrict__ clo) {
    constexpr int SROW = 80;
    constexpr int SLAB = 128 * SROW;       // 10240
    constexpr int STAGEB = 3 * SLAB;       // 30720
    constexpr int KCH = 12;

    extern __shared__ __align__(16) char smem[];
    const u32 u0 = smem_to_u32(smem);
    const int tid = threadIdx.x;
    const int wid = tid >> 5, lid = tid & 31;
    const int wm = wid >> 1, wn = wid & 1;
    const int nb0 = blockIdx.x * 128;
    const int m0  = blockIdx.y * 128;

    auto load_stage = [&](int s, int buf) {
        const int k0 = s * 32;
        const u32 uAh = u0 + buf * STAGEB;
        const u32 uAl = uAh + SLAB;
        const u32 uB  = uAl + SLAB;
#pragma unroll
        for (int t = 0; t < 2; t++) {
            int idx = tid + t * 256;
            int row = idx >> 2, qd = idx & 3;
            int k = k0 + qd * 8;
            bool p = k < FEAT;
            int kc = p ? k : (FEAT - 8);
            u32 doff = row * SROW + qd * 16;
            cp16(uAh + doff, &ahi[(size_t)(m0 + row) * FEAT + kc], p);
            cp16(uAl + doff, &alo[(size_t)(m0 + row) * FEAT + kc], p);
            cp16(uB  + doff, &bh_[(size_t)(nb0 + row) * FEAT + kc], p);
        }
        cp_commit();
    };

    const int lrow = lid & 15;
    const int lcol = (lid >> 4) << 4;

    float acc[2][8][4];
#pragma unroll
    for (int t = 0; t < 2; t++)
#pragma unroll
        for (int f = 0; f < 8; f++)
#pragma unroll
            for (int j = 0; j < 4; j++) acc[t][f][j] = 0.f;

    load_stage(0, 0);

    for (int s = 0; s < KCH; s++) {
        const int buf = s & 1;
        if (s + 1 < KCH) { load_stage(s + 1, buf ^ 1); cp_wait1(); }
        else             { cp_wait0(); }
        __syncthreads();
        const u32 uAh = u0 + buf * STAGEB;
        const u32 uAl = uAh + SLAB;
        const u32 uB  = uAl + SLAB;
#pragma unroll
        for (int ks = 0; ks < 2; ks++) {
            u32 ah[2][4], al[2][4], bh[4][4];
#pragma unroll
            for (int tm = 0; tm < 2; tm++) {
                u32 aaddr = (u32)((wm * 32 + tm * 16 + lrow) * SROW) + ks * 32 + lcol;
                ldsm4(ah[tm], uAh + aaddr);
                ldsm4(al[tm], uAl + aaddr);
            }
#pragma unroll
            for (int g = 0; g < 4; g++) {
                u32 baddr = (u32)((wn * 64 + g * 16 + lrow) * SROW) + ks * 32 + lcol;
                ldsm4(bh[g], uB + baddr);
            }
#pragma unroll
            for (int tm = 0; tm < 2; tm++)
#pragma unroll
                for (int g = 0; g < 4; g++)
#pragma unroll
                    for (int h = 0; h < 2; h++)
                        mma16816f(acc[tm][g * 2 + h], ah[tm], bh[g][h], bh[g][h + 2]);
#pragma unroll
            for (int tm = 0; tm < 2; tm++)
#pragma unroll
                for (int g = 0; g < 4; g++)
#pragma unroll
                    for (int h = 0; h < 2; h++)
                        mma16816f(acc[tm][g * 2 + h], al[tm], bh[g][h], bh[g][h + 2]);
        }
        __syncthreads();
    }

#pragma unroll
    for (int tm = 0; tm < 2; tm++) {
#pragma unroll
        for (int rr = 0; rr < 2; rr++) {
            int r = m0 + wm * 32 + tm * 16 + (lid >> 2) + rr * 8;
            size_t obase = (size_t)r * DENSE_N + nb0;
#pragma unroll
            for (int f = 0; f < 8; f++) {
                int jc = wn * 64 + f * 8 + (lid & 3) * 2;
                float v0 = fmaxf(acc[tm][f][rr * 2 + 0] + biasr[nb0 + jc], 0.f);
                float v1 = fmaxf(acc[tm][f][rr * 2 + 1] + biasr[nb0 + jc + 1], 0.f);
                u32 hp = f16pack(v0, v1);
                float2 hf = f16unpk(hp);
                u32 lp = f16pack(v0 - hf.x, v1 - hf.y);
                *(u32*)&chi[obase + jc] = hp;
                *(u32*)&clo[obase + jc] = lp;
            }
        }
    }
}

// ------- HMMA implicit-GEMM deconv, M=128/CTA, K16 stages, 2 CTA/SM --------
// SAMPLE_MODE (HIN==8): CTA = 2 samples, parity = blockIdx.y (0..3).
// RowMode (HIN==16, MERGE_RX): CTA = half sample (8 qy rows), ry = blockIdx.y.
template <int CIN, int COUT, int HIN, bool MERGE_RX, bool OUT_F16>
__global__ __launch_bounds__(256, 2) void deconv_mma_kernel(
    const __half* __restrict__ in_hi, const __half* __restrict__ in_lo,
    const __half* __restrict__ w_h,
    __half* __restrict__ out_hi, __half* __restrict__ out_lo,
    float* __restrict__ out_f) {
    constexpr int NCHUNK = CIN / 16;
    constexpr int HOUT = 2 * HIN;
    constexpr bool SAMPLE_MODE = (HIN == 8);
    constexpr int PW = SAMPLE_MODE ? 9 : 18;
    constexpr int SLOTS = SAMPLE_MODE ? 162 : 180;   // 2*81 | 10*18
    constexpr int SROW = 80;               // [32B hi][32B lo][16 pad]
    constexpr int ABYTES = SLOTS * SROW;   // 12960 | 14400
    constexpr int SROWB = 144;             // [128B w][16 pad]
    constexpr int BROWS = 128;             // 128 co | 2par x 64 co
    constexpr int BBYTES = BROWS * SROWB;  // 18432
    constexpr int STAGEB = ABYTES + BBYTES;
    constexpr int NPAR = MERGE_RX ? 2 : 1;
    constexpr int NG = COUT / 32;          // 4 | 2
    constexpr int NF8 = COUT / 16;         // 8 | 4

    extern __shared__ __align__(16) char smem[];
    const u32 u0 = smem_to_u32(smem);

    const int tid = threadIdx.x;
    const int wid = tid >> 5;
    const int lid = tid & 31;
    const int wm = wid >> 1;               // 0..3, m32 tiles
    const int wn = wid & 1;
    const int par = blockIdx.y;
    const int ry = MERGE_RX ? par : (par >> 1);
    const int rx0 = MERGE_RX ? 0 : (par & 1);
    const int n0 = SAMPLE_MODE ? blockIdx.x * 2 : (blockIdx.x >> 1);
    const int qy0 = SAMPLE_MODE ? 0 : ((blockIdx.x & 1) * 8);

    auto load_stage = [&](int s, int buf) {
        const int ci0 = s * 16;
        const u32 uA = u0 + buf * STAGEB;
        const u32 uB = uA + ABYTES;
#pragma unroll 2
        for (int idx = tid; idx < SLOTS * 2; idx += 256) {
            int slot = idx >> 1, qd = idx & 1;
            int n, y, x;
            if (SAMPLE_MODE) {
                int smp = slot / 81, rr = slot % 81;
                n = n0 + smp;
                y = rr / 9 - 1 + ry;
                x = rr % 9 - 1 + rx0;
            } else {
                n = n0;
                y = slot / 18 + qy0 - 1 + ry;
                x = slot % 18 - 1;
            }
            bool p = (y >= 0) && (y < HIN) && (x >= 0) && (x < HIN);
            int yc = p ? y : 0, xc = p ? x : 0;
            size_t base = (((size_t)n * HIN + yc) * HIN + xc) * CIN + ci0 + qd * 8;
            u32 doff = slot * SROW + qd * 16;
            cp16(uA + doff,      &in_hi[base], p);
            cp16(uA + doff + 32, &in_lo[base], p);
        }
#pragma unroll
        for (int k = 0; k < 4; k++) {
            int idx = tid + k * 256;
            int row = idx >> 3, qd = idx & 7;
            int co, wpar;
            if (MERGE_RX) { co = row & 63; wpar = ry * 2 + (row >> 6); }
            else          { co = row;      wpar = par; }
            size_t base = (((size_t)(wpar * NCHUNK + s) * COUT + co) << 6) + qd * 8;
            cp16(uB + row * SROWB + qd * 16, &w_h[base], true);
        }
        cp_commit();
    };

    const int lrow = lid & 15;
    const int lcol = (lid >> 4) << 4;
    int bslot[2];
#pragma unroll
    for (int tm = 0; tm < 2; tm++) {
        int row = wm * 32 + tm * 16 + lrow;
        if (SAMPLE_MODE) {
            int smp = row >> 6, q = row & 63;
            bslot[tm] = smp * 81 + (q >> 3) * 9 + (q & 7);
        } else {
            bslot[tm] = (row >> 4) * 18 + (row & 15);
        }
    }

    float acc[NPAR][2][NF8][4];
#pragma unroll
    for (int p = 0; p < NPAR; p++)
#pragma unroll
        for (int t = 0; t < 2; t++)
#pragma unroll
            for (int f = 0; f < NF8; f++)
#pragma unroll
                for (int j = 0; j < 4; j++) acc[p][t][f][j] = 0.f;

    load_stage(0, 0);

    for (int s = 0; s < NCHUNK; s++) {
        const int buf = s & 1;
        if (s + 1 < NCHUNK) { load_stage(s + 1, buf ^ 1); cp_wait1(); }
        else                { cp_wait0(); }
        __syncthreads();

        const u32 uA = u0 + buf * STAGEB;
        const u32 uB = uA + ABYTES;
#pragma unroll
        for (int tap = 0; tap < 4; tap++) {
            const int dy = tap >> 1, dx = tap & 1;
#pragma unroll
            for (int prx = 0; prx < NPAR; prx++) {
                u32 ah[2][4], al[2][4];
#pragma unroll
                for (int tm = 0; tm < 2; tm++) {
                    u32 aaddr = (u32)((bslot[tm] + dy * PW + dx + prx) * SROW) + lcol;
                    ldsm4(ah[tm], uA + aaddr);
                    ldsm4(al[tm], uA + aaddr + 32);
                }
#pragma unroll
                for (int g = 0; g < NG; g++) {
                    u32 bh[4];
                    u32 baddr = (u32)((prx * COUT + wn * (COUT / 2) + g * 16 + lrow) * SROWB)
                                + tap * 32 + lcol;
                    ldsm4(bh, uB + baddr);
#pragma unroll
                    for (int tm = 0; tm < 2; tm++) {
                        mma16816f(acc[prx][tm][g * 2 + 0], ah[tm], bh[0], bh[2]);
                        mma16816f(acc[prx][tm][g * 2 + 1], ah[tm], bh[1], bh[3]);
                    }
#pragma unroll
                    for (int tm = 0; tm < 2; tm++) {
                        mma16816f(acc[prx][tm][g * 2 + 0], al[tm], bh[0], bh[2]);
                        mma16816f(acc[prx][tm][g * 2 + 1], al[tm], bh[1], bh[3]);
                    }
                }
            }
        }
        __syncthreads();
    }

    // ---- epilogue: ReLU + NHWC store ----
#pragma unroll
    for (int prx = 0; prx < NPAR; prx++) {
        const int rx = MERGE_RX ? prx : rx0;
#pragma unroll
        for (int tm = 0; tm < 2; tm++) {
            int r0 = wm * 32 + tm * 16 + (lid >> 2);
#pragma unroll
            for (int rr = 0; rr < 2; rr++) {
                int r = r0 + rr * 8;
                int n, yo, xo;
                if (SAMPLE_MODE) {
                    n = n0 + (r >> 6);
                    int q = r & 63;
                    yo = 2 * (q >> 3) + ry;
                    xo = 2 * (q & 7) + rx;
                } else {
                    n = n0;
                    yo = 2 * (qy0 + (r >> 4)) + ry;
                    xo = 2 * (r & 15) + rx;
                }
                size_t obase = (((size_t)n * HOUT + yo) * HOUT + xo) * COUT;
#pragma unroll
                for (int f = 0; f < NF8; f++) {
                    int ch = wn * (COUT / 2) + f * 8 + (lid & 3) * 2;
                    float v0 = fmaxf(acc[prx][tm][f][rr * 2 + 0], 0.f);
                    float v1 = fmaxf(acc[prx][tm][f][rr * 2 + 1], 0.f);
                    if (OUT_F16) {
                        u32 hp = f16pack(v0, v1);
                        float2 hf = f16unpk(hp);
                        u32 lp = f16pack(v0 - hf.x, v1 - hf.y);
                        *(u32*)&out_hi[obase + ch] = hp;
                        *(u32*)&out_lo[obase + ch] = lp;
                    } else {
                        *(float2*)&out_f[obase + ch] = make_float2(v0, v1);
                    }
                }
            }
        }
    }
}

// ---------------- deconv3: 64 -> 3, NHWC fp32 input, NCHW output ----------------
__global__ __launch_bounds__(256) void deconv3_kernel(const float* __restrict__ in,
                                                      const float* __restrict__ wgt,
                                                      float* __restrict__ out) {
    int n = blockIdx.x;
    __shared__ float sin_[34 * 34 * 4];
    __shared__ float wsm[3 * 64 * 16 * 2];
    int tid = threadIdx.x;

    for (int idx = tid; idx < 3072; idx += 256) {
        int tap = idx & 15;
        int cc = idx >> 4;
        int co = cc % 3, ci = cc / 3;
        float w = wgt[(co * 64 + ci) * 16 + tap];
        wsm[((ci * 3 + co) * 16 + tap) * 2 + 0] = w;
        wsm[((ci * 3 + co) * 16 + tap) * 2 + 1] = w;
    }

    int qy0 = (tid >> 4) * 2;
    int qx0 = (tid & 15) * 2;
    u64 accp[3][8];
#pragma unroll
    for (int c = 0; c < 3; c++)
#pragma unroll
        for (int i = 0; i < 8; i++) accp[c][i] = 0ull;

    const float* in_n = in + (size_t)n * 1024 * 64;
    for (int ci0 = 0; ci0 < 64; ci0 += 4) {
        __syncthreads();
        for (int idx = tid; idx < 1156; idx += 256) {
            int py = idx / 34, px = idx % 34;
            int y = py - 1, x = px - 1;
            float4 v = make_float4(0.f, 0.f, 0.f, 0.f);
            if (y >= 0 && y < 32 && x >= 0 && x < 32)
                v = *(const float4*)&in_n[(y * 32 + x) * 64 + ci0];
            *(float4*)&sin_[idx * 4] = v;
        }
        __syncthreads();
#pragma unroll 1
        for (int ci = 0; ci < 4; ci++) {
            float iv[4][4];
#pragma unroll
            for (int yy = 0; yy < 4; yy++)
#pragma unroll
                for (int xx = 0; xx < 4; xx++)
                    iv[yy][xx] = sin_[((qy0 + yy) * 34 + qx0 + xx) * 4 + ci];
            u64 ivp2[4][3];
#pragma unroll
            for (int yy = 0; yy < 4; yy++)
#pragma unroll
                for (int xx = 0; xx < 3; xx++)
                    ivp2[yy][xx] = pack2(iv[yy][xx], iv[yy][xx + 1]);
#pragma unroll
            for (int co = 0; co < 3; co++) {
#pragma unroll
                for (int tap = 0; tap < 16; tap++) {
                    const int ky = tap >> 2, kx = tap & 3;
                    const int ry = ky & 1, dy = ky >> 1;
                    const int rx = kx & 1, dx = kx >> 1;
                    u64 wp = *(const u64*)&wsm[(((ci0 + ci) * 3 + co) * 16 + tap) * 2];
#pragma unroll
                    for (int qy = 0; qy < 2; qy++) {
                        const int o = qy * 4 + ry * 2 + rx;
                        accp[co][o] = fma2(wp, ivp2[qy + dy + ry][dx + rx], accp[co][o]);
                    }
                }
            }
        }
    }
    float* out_n = out + (size_t)n * 3 * 4096;
#pragma unroll
    for (int co = 0; co < 3; co++)
#pragma unroll
        for (int qy = 0; qy < 2; qy++)
#pragma unroll
            for (int ry = 0; ry < 2; ry++)
#pragma unroll
                for (int rx = 0; rx < 2; rx++) {
                    float2 v = unpk2(accp[co][qy * 4 + ry * 2 + rx]);
                    int yo = 2 * (qy0 + qy) + ry;
                    int xo0 = 2 * (qx0 + 0) + rx;
                    int xo1 = 2 * (qx0 + 1) + rx;
                    out_n[co * 4096 + yo * 64 + xo0] = v.x;
                    out_n[co * 4096 + yo * 64 + xo1] = v.y;
                }
}

// -----------------------------------------------------------------------------------------
extern "C" void kernel_launch(void* const* d_in, const int* in_sizes, int n_in,
                              void* d_out, int out_size) {
    (void)in_sizes; (void)n_in; (void)out_size;
    const float* angles   = (const float*)d_in[0];
    const float* item_rep = (const float*)d_in[1];
    const float* w0       = (const float*)d_in[2];
    const float* b0       = (const float*)d_in[3];
    const float* w1       = (const float*)d_in[4];
    const float* w2       = (const float*)d_in[5];
    const float* w3       = (const float*)d_in[6];
    float* out = (float*)d_out;

    float *p_h2, *p_b0r;
    cudaGetSymbolAddress((void**)&p_h2, g_h2);
    cudaGetSymbolAddress((void**)&p_b0r, g_b0r);
    __half *p_ithi, *p_itlo, *p_w0h;
    cudaGetSymbolAddress((void**)&p_ithi, g_itemhi);
    cudaGetSymbolAddress((void**)&p_itlo, g_itemlo);
    cudaGetSymbolAddress((void**)&p_w0h, g_w0h);
    __half *p_h0hi, *p_h0lo, *p_h1hi, *p_h1lo;
    cudaGetSymbolAddress((void**)&p_h0hi, g_h0hi);
    cudaGetSymbolAddress((void**)&p_h0lo, g_h0lo);
    cudaGetSymbolAddress((void**)&p_h1hi, g_h1hi);
    cudaGetSymbolAddress((void**)&p_h1lo, g_h1lo);
    __half *p_w1h, *p_w2h;
    cudaGetSymbolAddress((void**)&p_w1h, g_w1h);
    cudaGetSymbolAddress((void**)&p_w2h, g_w2h);

    constexpr int SMEMD1 = 2 * (162 * 80 + 128 * 144);  // 62784
    constexpr int SMEMD2 = 2 * (180 * 80 + 128 * 144);  // 65664
    constexpr int SMEMG  = 2 * 3 * 128 * 80;            // 61440
    cudaFuncSetAttribute(deconv_mma_kernel<256, 128, 8, false, true>,
                         cudaFuncAttributeMaxDynamicSharedMemorySize, SMEMD1);
    cudaFuncSetAttribute(deconv_mma_kernel<128, 64, 16, true, false>,
                         cudaFuncAttributeMaxDynamicSharedMemorySize, SMEMD2);
    cudaFuncSetAttribute(dense_mma_kernel,
                         cudaFuncAttributeMaxDynamicSharedMemorySize, SMEMG);

    const int SETUP_TOTAL = 4 * 16 * 128 * 64 + 4 * 8 * 64 * 64 + DENSE_N * FEAT + DENSE_N + 286;
    setup_kernel<<<(SETUP_TOTAL + 255) / 256, 256>>>(w1, w2, w0, b0);
    wigner_kernel<<<(N_SAMP * REP * 6 + 127) / 128, 128>>>(angles, item_rep);
    dense_mma_kernel<<<dim3(DENSE_N / 128, N_SAMP / 128), 256, SMEMG>>>(
        p_ithi, p_itlo, p_w0h, p_b0r, p_h0hi, p_h0lo);
    deconv_mma_kernel<256, 128, 8, false, true><<<dim3(1024, 4), 256, SMEMD1>>>(
        p_h0hi, p_h0lo, p_w1h, p_h1hi, p_h1lo, nullptr);
    deconv_mma_kernel<128, 64, 16, true, false><<<dim3(4096, 2), 256, SMEMD2>>>(
        p_h1hi, p_h1lo, p_w2h, nullptr, nullptr, p_h2);
    deconv3_kernel<<<N_SAMP, 256>>>(p_h2, w3, out);
}

// round 13
// speedup vs baseline: 2.1193x; 1.2402x over previous
#include <cuda_runtime.h>
#include <cuda_fp16.h>
#include <math.h>
#include <stdint.h>

typedef unsigned int u32;
typedef unsigned long long u64;

#define N_SAMP 2048
#define MDIMS  36
#define REP    10
#define FEAT   360
#define DENSE_N 16384        // 256*8*8

// ---------------- fp16 pack/unpack ----------------
__device__ __forceinline__ u32 f16pack(float lo, float hi) {
    u32 r;
    asm("cvt.rn.f16x2.f32 %0, %1, %2;" : "=r"(r) : "f"(hi), "f"(lo));
    return r;
}
__device__ __forceinline__ float2 f16unpk(u32 u) {
    __half2 h = *reinterpret_cast<__half2*>(&u);
    return __half22float2(h);
}

// ---------------- warp MMA + cp.async helpers ----------------
__device__ __forceinline__ u32 smem_to_u32(const void* p) {
    u32 a;
    asm("{ .reg .u64 t; cvta.to.shared.u64 t, %1; cvt.u32.u64 %0, t; }" : "=r"(a) : "l"(p));
    return a;
}
__device__ __forceinline__ void ldsm4(u32* r, u32 addr) {
    asm volatile("ldmatrix.sync.aligned.m8n8.x4.shared.b16 {%0,%1,%2,%3}, [%4];"
                 : "=r"(r[0]), "=r"(r[1]), "=r"(r[2]), "=r"(r[3]) : "r"(addr));
}
__device__ __forceinline__ void ldsm2(u32& r0, u32& r1, u32 addr) {
    asm volatile("ldmatrix.sync.aligned.m8n8.x2.shared.b16 {%0,%1}, [%2];"
                 : "=r"(r0), "=r"(r1) : "r"(addr));
}
__device__ __forceinline__ void mma16816f(float* d, const u32* a, u32 b0, u32 b1) {
    asm volatile(
        "mma.sync.aligned.m16n8k16.row.col.f32.f16.f16.f32 "
        "{%0,%1,%2,%3}, {%4,%5,%6,%7}, {%8,%9}, {%0,%1,%2,%3};"
        : "+f"(d[0]), "+f"(d[1]), "+f"(d[2]), "+f"(d[3])
        : "r"(a[0]), "r"(a[1]), "r"(a[2]), "r"(a[3]), "r"(b0), "r"(b1));
}
__device__ __forceinline__ void cp16(u32 dst, const void* src, bool p) {
    asm volatile("cp.async.cg.shared.global [%0], [%1], 16, %2;"
                 :: "r"(dst), "l"(src), "r"(p ? 16 : 0) : "memory");
}
__device__ __forceinline__ void cp_commit() {
    asm volatile("cp.async.commit_group;" ::: "memory");
}
__device__ __forceinline__ void cp_wait1() {
    asm volatile("cp.async.wait_group 1;" ::: "memory");
}
__device__ __forceinline__ void cp_wait0() {
    asm volatile("cp.async.wait_group 0;" ::: "memory");
}

// ---------------- scratch ----------------
__device__ float g_JD[286];
__device__ __align__(16) __half g_itemhi[N_SAMP * FEAT];
__device__ __align__(16) __half g_itemlo[N_SAMP * FEAT];
__device__ __align__(16) __half g_h0hi[N_SAMP * 16384];      // NHWC [n,8,8,256]
__device__ __align__(16) __half g_h0lo[N_SAMP * 16384];
__device__ __align__(16) __half g_h1hi[N_SAMP * 256 * 128];  // NHWC [n,16,16,128]
__device__ __align__(16) __half g_h1lo[N_SAMP * 256 * 128];
__device__ __align__(16) __half g_h2hi[N_SAMP * 1024 * 64];  // NHWC [n,32,32,64]
__device__ __align__(16) __half g_h2lo[N_SAMP * 1024 * 64];
__device__ __align__(16) __half g_w1h[4 * 128 * 1024];       // [par][chunk16][co][tap*16+ci]
__device__ __align__(16) __half g_w2h[4 * 64 * 512];
__device__ __align__(16) __half g_w3h[4 * 4 * 8 * 64];       // [par][chunk16][co8][tap*16+ci]
__device__ __align__(16) __half g_w0h[DENSE_N * FEAT];       // [j'=pix*256+c][k]
__device__ __align__(16) float g_b0r[DENSE_N];

__device__ __constant__ int c_off[7] = {0, 1, 10, 35, 84, 165, 286};

// ---------------- J_l math ----------------
__device__ double dfact(int n) { double r = 1.0; for (int i = 2; i <= n; i++) r *= (double)i; return r; }

__device__ double small_d(int l, int mp, int m) {
    const double ch = 0.70710678118654752440, sh = 0.70710678118654752440;
    double pref = sqrt(dfact(l + mp) * dfact(l - mp) * dfact(l + m) * dfact(l - m));
    int smin = max(0, m - mp), smax = min(l + m, l - mp);
    double tot = 0.0;
    for (int s = smin; s <= smax; s++) {
        double sign = ((mp - m + s) & 1) ? -1.0 : 1.0;
        double denom = dfact(l + m - s) * dfact(s) * dfact(mp - m + s) * dfact(l - mp - s);
        tot += sign / denom * pow(ch, (double)(2 * l + m - mp - 2 * s)) * pow(sh, (double)(mp - m + 2 * s));
    }
    return pref * tot;
}

__device__ void c2r_row(int l, int i, int* col, double* re, double* im, int* cnt) {
    int m = i - l;
    const double s = 0.70710678118654752440;
    if (m < 0) {
        double sgn = (m & 1) ? -1.0 : 1.0;
        col[0] = l + m; re[0] = 0.0; im[0] = s;
        col[1] = l - m; re[1] = 0.0; im[1] = -sgn * s;
        *cnt = 2;
    } else if (m == 0) {
        col[0] = l; re[0] = 1.0; im[0] = 0.0; *cnt = 1;
    } else {
        double sgn = (m & 1) ? -1.0 : 1.0;
        col[0] = l - m; re[0] = s;        im[0] = 0.0;
        col[1] = l + m; re[1] = sgn * s;  im[1] = 0.0;
        *cnt = 2;
    }
}

__device__ void jd_entry(int idx) {
    int l = 0;
    while (idx >= c_off[l + 1]) l++;
    int e = idx - c_off[l];
    int sz = 2 * l + 1;
    int i = e / sz, j = e % sz;
    int ca_c[2], cb_c[2], na, nb;
    double ca_re[2], ca_im[2], cb_re[2], cb_im[2];
    c2r_row(l, i, ca_c, ca_re, ca_im, &na);
    c2r_row(l, j, cb_c, cb_re, cb_im, &nb);
    double acc = 0.0;
    for (int a = 0; a < na; a++)
        for (int b = 0; b < nb; b++) {
            double cross = ca_re[a] * cb_re[b] + ca_im[a] * cb_im[b];
            if (cross != 0.0) acc += cross * small_d(l, ca_c[a] - l, cb_c[b] - l);
        }
    g_JD[idx] = (float)acc;
}

// ------- setup kernel: w1, w2, w3 (padded co8), w0(permuted), b0(permuted), J_l -------
__device__ __forceinline__ void repack_wgt(const float* w, __half* bh,
                                           int i, int COUT, int CIN, int NCHUNK) {
    int cii = i & 15;
    int tap = (i >> 4) & 3;
    int co  = (i >> 6) % COUT;
    int chunk = (i / (64 * COUT)) % NCHUNK;
    int par = i / (64 * COUT * NCHUNK);
    int ci = chunk * 16 + cii;
    int dy = tap >> 1, dx = tap & 1, ry = par >> 1, rx = par & 1;
    float v = w[((co * CIN + ci) * 4 + (2 * dy + ry)) * 4 + (2 * dx + rx)];
    bh[i] = __float2half(v);
}

__global__ void setup_kernel(const float* __restrict__ w1, const float* __restrict__ w2,
                             const float* __restrict__ w3,
                             const float* __restrict__ w0, const float* __restrict__ b0) {
    const int T1 = 4 * 16 * 128 * 64;      // 524288
    const int T2 = 4 * 8 * 64 * 64;        // 131072
    const int T3 = 4 * 4 * 8 * 64;         // 8192
    const int T0 = DENSE_N * FEAT;         // 5898240
    int idx = blockIdx.x * 256 + threadIdx.x;
    if (idx < T1) {
        repack_wgt(w1, g_w1h, idx, 128, 256, 16);
    } else if (idx < T1 + T2) {
        repack_wgt(w2, g_w2h, idx - T1, 64, 128, 8);
    } else if (idx < T1 + T2 + T3) {
        int i = idx - T1 - T2;
        int cii = i & 15, tap = (i >> 4) & 3, co8 = (i >> 6) & 7;
        int chunk = (i >> 9) & 3, par = (i >> 11) & 3;
        float v = 0.f;
        if (co8 < 3) {
            int ci = chunk * 16 + cii;
            int dy = tap >> 1, dx = tap & 1, ry = par >> 1, rx = par & 1;
            v = w3[((co8 * 64 + ci) * 4 + (2 * dy + ry)) * 4 + (2 * dx + rx)];
        }
        g_w3h[i] = __float2half(v);
    } else if (idx < T1 + T2 + T3 + T0) {
        int i = idx - T1 - T2 - T3;
        int jp = i / FEAT, k = i % FEAT;
        int pix = jp >> 8, c = jp & 255;
        g_w0h[i] = __float2half(w0[(size_t)k * DENSE_N + c * 64 + pix]);
    } else if (idx < T1 + T2 + T3 + T0 + DENSE_N) {
        int jp = idx - T1 - T2 - T3 - T0;
        g_b0r[jp] = b0[(jp & 255) * 64 + (jp >> 8)];
    } else if (idx < T1 + T2 + T3 + T0 + DENSE_N + 286) {
        jd_entry(idx - T1 - T2 - T3 - T0 - DENSE_N);
    }
}

// ---------------- Wigner (parallel over l) -> item fp16 hi/lo ----------------
__device__ __forceinline__ void zrot_apply(const float* v, int sz, int l, float ang, float* out) {
    for (int i = 0; i < sz; i++) {
        float f = (float)(l - i);
        float s, c;
        sincosf(f * ang, &s, &c);
        out[i] = c * v[i] + s * v[sz - 1 - i];
    }
}

__global__ void wigner_kernel(const float* __restrict__ angles, const float* __restrict__ item_rep) {
    int t = blockIdx.x * blockDim.x + threadIdx.x;
    if (t >= N_SAMP * REP * 6) return;
    int l = t % 6;
    int nr = t / 6;
    int n = nr / REP, r = nr % REP;
    float a0 = angles[n * 3 + 0], a1 = angles[n * 3 + 1], a2 = angles[n * 3 + 2];
    float v[11], w[11];
    int sz = 2 * l + 1;
    const float* J = &g_JD[c_off[l]];
    for (int i = 0; i < sz; i++) v[i] = item_rep[(l * l + i) * REP + r];
    zrot_apply(v, sz, l, a2, w);
    for (int i = 0; i < sz; i++) { float s = 0.f; for (int j = 0; j < sz; j++) s += J[i * sz + j] * w[j]; v[i] = s; }
    zrot_apply(v, sz, l, a1, w);
    for (int i = 0; i < sz; i++) { float s = 0.f; for (int j = 0; j < sz; j++) s += J[i * sz + j] * w[j]; v[i] = s; }
    zrot_apply(v, sz, l, a0, w);
    for (int i = 0; i < sz; i++) {
        size_t o = (size_t)n * FEAT + (l * l + i) * REP + r;
        float val = w[i];
        __half h = __float2half(val);
        g_itemhi[o] = h;
        g_itemlo[o] = __float2half(val - __half2float(h));
    }
}

// ---------------- dense HMMA: h0 = relu(item @ w0r + b0r), output IS NHWC ----------------
__global__ __launch_bounds__(256) void dense_mma_kernel(
    const __half* __restrict__ ahi, const __half* __restrict__ alo,
    const __half* __restrict__ bh_, const float* __restrict__ biasr,
    __half* __restrict__ chi, __half* __restrict__ clo) {
    constexpr int SROW = 80;
    constexpr int SLAB = 128 * SROW;       // 10240
    constexpr int STAGEB = 3 * SLAB;       // 30720
    constexpr int KCH = 12;

    extern __shared__ __align__(16) char smem[];
    const u32 u0 = smem_to_u32(smem);
    const int tid = threadIdx.x;
    const int wid = tid >> 5, lid = tid & 31;
    const int wm = wid >> 1, wn = wid & 1;
    const int nb0 = blockIdx.x * 128;
    const int m0  = blockIdx.y * 128;

    auto load_stage = [&](int s, int buf) {
        const int k0 = s * 32;
        const u32 uAh = u0 + buf * STAGEB;
        const u32 uAl = uAh + SLAB;
        const u32 uB  = uAl + SLAB;
#pragma unroll
        for (int t = 0; t < 2; t++) {
            int idx = tid + t * 256;
            int row = idx >> 2, qd = idx & 3;
            int k = k0 + qd * 8;
            bool p = k < FEAT;
            int kc = p ? k : (FEAT - 8);
            u32 doff = row * SROW + qd * 16;
            cp16(uAh + doff, &ahi[(size_t)(m0 + row) * FEAT + kc], p);
            cp16(uAl + doff, &alo[(size_t)(m0 + row) * FEAT + kc], p);
            cp16(uB  + doff, &bh_[(size_t)(nb0 + row) * FEAT + kc], p);
        }
        cp_commit();
    };

    const int lrow = lid & 15;
    const int lcol = (lid >> 4) << 4;

    float acc[2][8][4];
#pragma unroll
    for (int t = 0; t < 2; t++)
#pragma unroll
        for (int f = 0; f < 8; f++)
#pragma unroll
            for (int j = 0; j < 4; j++) acc[t][f][j] = 0.f;

    load_stage(0, 0);

    for (int s = 0; s < KCH; s++) {
        const int buf = s & 1;
        if (s + 1 < KCH) { load_stage(s + 1, buf ^ 1); cp_wait1(); }
        else             { cp_wait0(); }
        __syncthreads();
        const u32 uAh = u0 + buf * STAGEB;
        const u32 uAl = uAh + SLAB;
        const u32 uB  = uAl + SLAB;
#pragma unroll
        for (int ks = 0; ks < 2; ks++) {
            u32 ah[2][4], al[2][4], bh[4][4];
#pragma unroll
            for (int tm = 0; tm < 2; tm++) {
                u32 aaddr = (u32)((wm * 32 + tm * 16 + lrow) * SROW) + ks * 32 + lcol;
                ldsm4(ah[tm], uAh + aaddr);
                ldsm4(al[tm], uAl + aaddr);
            }
#pragma unroll
            for (int g = 0; g < 4; g++) {
                u32 baddr = (u32)((wn * 64 + g * 16 + lrow) * SROW) + ks * 32 + lcol;
                ldsm4(bh[g], uB + baddr);
            }
#pragma unroll
            for (int tm = 0; tm < 2; tm++)
#pragma unroll
                for (int g = 0; g < 4; g++)
#pragma unroll
                    for (int h = 0; h < 2; h++)
                        mma16816f(acc[tm][g * 2 + h], ah[tm], bh[g][h], bh[g][h + 2]);
#pragma unroll
            for (int tm = 0; tm < 2; tm++)
#pragma unroll
                for (int g = 0; g < 4; g++)
#pragma unroll
                    for (int h = 0; h < 2; h++)
                        mma16816f(acc[tm][g * 2 + h], al[tm], bh[g][h], bh[g][h + 2]);
        }
        __syncthreads();
    }

#pragma unroll
    for (int tm = 0; tm < 2; tm++) {
#pragma unroll
        for (int rr = 0; rr < 2; rr++) {
            int r = m0 + wm * 32 + tm * 16 + (lid >> 2) + rr * 8;
            size_t obase = (size_t)r * DENSE_N + nb0;
#pragma unroll
            for (int f = 0; f < 8; f++) {
                int jc = wn * 64 + f * 8 + (lid & 3) * 2;
                float v0 = fmaxf(acc[tm][f][rr * 2 + 0] + biasr[nb0 + jc], 0.f);
                float v1 = fmaxf(acc[tm][f][rr * 2 + 1] + biasr[nb0 + jc + 1], 0.f);
                u32 hp = f16pack(v0, v1);
                float2 hf = f16unpk(hp);
                u32 lp = f16pack(v0 - hf.x, v1 - hf.y);
                *(u32*)&chi[obase + jc] = hp;
                *(u32*)&clo[obase + jc] = lp;
            }
        }
    }
}

// ------- HMMA implicit-GEMM deconv, M=128/CTA, K16 stages, 2 CTA/SM --------
template <int CIN, int COUT, int HIN, bool MERGE_RX>
__global__ __launch_bounds__(256, 2) void deconv_mma_kernel(
    const __half* __restrict__ in_hi, const __half* __restrict__ in_lo,
    const __half* __restrict__ w_h,
    __half* __restrict__ out_hi, __half* __restrict__ out_lo) {
    constexpr int NCHUNK = CIN / 16;
    constexpr int HOUT = 2 * HIN;
    constexpr bool SAMPLE_MODE = (HIN == 8);
    constexpr int PW = SAMPLE_MODE ? 9 : 18;
    constexpr int SLOTS = SAMPLE_MODE ? 162 : 180;   // 2*81 | 10*18
    constexpr int SROW = 80;               // [32B hi][32B lo][16 pad]
    constexpr int ABYTES = SLOTS * SROW;
    constexpr int SROWB = 144;             // [128B w][16 pad]
    constexpr int BROWS = 128;
    constexpr int BBYTES = BROWS * SROWB;
    constexpr int STAGEB = ABYTES + BBYTES;
    constexpr int NPAR = MERGE_RX ? 2 : 1;
    constexpr int NG = COUT / 32;
    constexpr int NF8 = COUT / 16;

    extern __shared__ __align__(16) char smem[];
    const u32 u0 = smem_to_u32(smem);

    const int tid = threadIdx.x;
    const int wid = tid >> 5;
    const int lid = tid & 31;
    const int wm = wid >> 1;
    const int wn = wid & 1;
    const int par = blockIdx.y;
    const int ry = MERGE_RX ? par : (par >> 1);
    const int rx0 = MERGE_RX ? 0 : (par & 1);
    const int n0 = SAMPLE_MODE ? blockIdx.x * 2 : (blockIdx.x >> 1);
    const int qy0 = SAMPLE_MODE ? 0 : ((blockIdx.x & 1) * 8);

    auto load_stage = [&](int s, int buf) {
        const int ci0 = s * 16;
        const u32 uA = u0 + buf * STAGEB;
        const u32 uB = uA + ABYTES;
#pragma unroll 2
        for (int idx = tid; idx < SLOTS * 2; idx += 256) {
            int slot = idx >> 1, qd = idx & 1;
            int n, y, x;
            if (SAMPLE_MODE) {
                int smp = slot / 81, rr = slot % 81;
                n = n0 + smp;
                y = rr / 9 - 1 + ry;
                x = rr % 9 - 1 + rx0;
            } else {
                n = n0;
                y = slot / 18 + qy0 - 1 + ry;
                x = slot % 18 - 1;
            }
            bool p = (y >= 0) && (y < HIN) && (x >= 0) && (x < HIN);
            int yc = p ? y : 0, xc = p ? x : 0;
            size_t base = (((size_t)n * HIN + yc) * HIN + xc) * CIN + ci0 + qd * 8;
            u32 doff = slot * SROW + qd * 16;
            cp16(uA + doff,      &in_hi[base], p);
            cp16(uA + doff + 32, &in_lo[base], p);
        }
#pragma unroll
        for (int k = 0; k < 4; k++) {
            int idx = tid + k * 256;
            int row = idx >> 3, qd = idx & 7;
            int co, wpar;
            if (MERGE_RX) { co = row & 63; wpar = ry * 2 + (row >> 6); }
            else          { co = row;      wpar = par; }
            size_t base = (((size_t)(wpar * NCHUNK + s) * COUT + co) << 6) + qd * 8;
            cp16(uB + row * SROWB + qd * 16, &w_h[base], true);
        }
        cp_commit();
    };

    const int lrow = lid & 15;
    const int lcol = (lid >> 4) << 4;
    int bslot[2];
#pragma unroll
    for (int tm = 0; tm < 2; tm++) {
        int row = wm * 32 + tm * 16 + lrow;
        if (SAMPLE_MODE) {
            int smp = row >> 6, q = row & 63;
            bslot[tm] = smp * 81 + (q >> 3) * 9 + (q & 7);
        } else {
            bslot[tm] = (row >> 4) * 18 + (row & 15);
        }
    }

    float acc[NPAR][2][NF8][4];
#pragma unroll
    for (int p = 0; p < NPAR; p++)
#pragma unroll
        for (int t = 0; t < 2; t++)
#pragma unroll
            for (int f = 0; f < NF8; f++)
#pragma unroll
                for (int j = 0; j < 4; j++) acc[p][t][f][j] = 0.f;

    load_stage(0, 0);

    for (int s = 0; s < NCHUNK; s++) {
        const int buf = s & 1;
        if (s + 1 < NCHUNK) { load_stage(s + 1, buf ^ 1); cp_wait1(); }
        else                { cp_wait0(); }
        __syncthreads();

        const u32 uA = u0 + buf * STAGEB;
        const u32 uB = uA + ABYTES;
#pragma unroll
        for (int tap = 0; tap < 4; tap++) {
            const int dy = tap >> 1, dx = tap & 1;
#pragma unroll
            for (int prx = 0; prx < NPAR; prx++) {
                u32 ah[2][4], al[2][4];
#pragma unroll
                for (int tm = 0; tm < 2; tm++) {
                    u32 aaddr = (u32)((bslot[tm] + dy * PW + dx + prx) * SROW) + lcol;
                    ldsm4(ah[tm], uA + aaddr);
                    ldsm4(al[tm], uA + aaddr + 32);
                }
#pragma unroll
                for (int g = 0; g < NG; g++) {
                    u32 bh[4];
                    u32 baddr = (u32)((prx * COUT + wn * (COUT / 2) + g * 16 + lrow) * SROWB)
                                + tap * 32 + lcol;
                    ldsm4(bh, uB + baddr);
#pragma unroll
                    for (int tm = 0; tm < 2; tm++) {
                        mma16816f(acc[prx][tm][g * 2 + 0], ah[tm], bh[0], bh[2]);
                        mma16816f(acc[prx][tm][g * 2 + 1], ah[tm], bh[1], bh[3]);
                    }
#pragma unroll
                    for (int tm = 0; tm < 2; tm++) {
                        mma16816f(acc[prx][tm][g * 2 + 0], al[tm], bh[0], bh[2]);
                        mma16816f(acc[prx][tm][g * 2 + 1], al[tm], bh[1], bh[3]);
                    }
                }
            }
        }
        __syncthreads();
    }

    // ---- epilogue: ReLU + fp16 hi/lo NHWC store ----
#pragma unroll
    for (int prx = 0; prx < NPAR; prx++) {
        const int rx = MERGE_RX ? prx : rx0;
#pragma unroll
        for (int tm = 0; tm < 2; tm++) {
            int r0 = wm * 32 + tm * 16 + (lid >> 2);
#pragma unroll
            for (int rr = 0; rr < 2; rr++) {
                int r = r0 + rr * 8;
                int n, yo, xo;
                if (SAMPLE_MODE) {
                    n = n0 + (r >> 6);
                    int q = r & 63;
                    yo = 2 * (q >> 3) + ry;
                    xo = 2 * (q & 7) + rx;
                } else {
                    n = n0;
                    yo = 2 * (qy0 + (r >> 4)) + ry;
                    xo = 2 * (r & 15) + rx;
                }
                size_t obase = (((size_t)n * HOUT + yo) * HOUT + xo) * COUT;
#pragma unroll
                for (int f = 0; f < NF8; f++) {
                    int ch = wn * (COUT / 2) + f * 8 + (lid & 3) * 2;
                    float v0 = fmaxf(acc[prx][tm][f][rr * 2 + 0], 0.f);
                    float v1 = fmaxf(acc[prx][tm][f][rr * 2 + 1], 0.f);
                    u32 hp = f16pack(v0, v1);
                    float2 hf = f16unpk(hp);
                    u32 lp = f16pack(v0 - hf.x, v1 - hf.y);
                    *(u32*)&out_hi[obase + ch] = hp;
                    *(u32*)&out_lo[obase + ch] = lp;
                }
            }
        }
    }
}

// ------- deconv3 HMMA: 64 -> 3 (N padded to 8), all 4 parities share one patch -------
// CTA = 8 qy x 32 qx pixel rows (quarter sample). Output NCHW fp32 (no relu).
__global__ __launch_bounds__(256, 2) void deconv3_mma_kernel(
    const __half* __restrict__ in_hi, const __half* __restrict__ in_lo,
    const __half* __restrict__ w3h, float* __restrict__ out) {
    constexpr int SLOTS = 340;             // 10 x 34
    constexpr int SROW = 80;               // [32B hi][32B lo][16 pad]
    constexpr int ABYTES = SLOTS * SROW;   // 27200
    constexpr int SROWB = 144;             // [128B: 4 taps x 16ci][16 pad]
    constexpr int BBYTES = 32 * SROWB;     // 4608
    constexpr int STAGEB = ABYTES + BBYTES;// 31808
    constexpr int NCH = 4;                 // 64 ci / 16

    extern __shared__ __align__(16) char smem[];
    const u32 u0 = smem_to_u32(smem);

    const int tid = threadIdx.x;
    const int wid = tid >> 5;
    const int lid = tid & 31;
    const int n = blockIdx.x >> 2;
    const int qy0 = (blockIdx.x & 3) * 8;

    auto load_stage = [&](int s, int buf) {
        const int ci0 = s * 16;
        const u32 uA = u0 + buf * STAGEB;
        const u32 uB = uA + ABYTES;
#pragma unroll 3
        for (int idx = tid; idx < SLOTS * 2; idx += 256) {
            int slot = idx >> 1, qd = idx & 1;
            int y = slot / 34 + qy0 - 1;
            int x = slot % 34 - 1;
            bool p = (y >= 0) && (y < 32) && (x >= 0) && (x < 32);
            int yc = p ? y : 0, xc = p ? x : 0;
            size_t base = (((size_t)n * 32 + yc) * 32 + xc) * 64 + ci0 + qd * 8;
            u32 doff = slot * SROW + qd * 16;
            cp16(uA + doff,      &in_hi[base], p);
            cp16(uA + doff + 32, &in_lo[base], p);
        }
        {   // B: 32 rows (4 par x 8 co8) x 8 x 16B
            int row = tid >> 3, qd = tid & 7;
            int par = row >> 3, co8 = row & 7;
            size_t base = (((size_t)(par * NCH + s) * 8 + co8) << 6) + qd * 8;
            cp16(uB + row * SROWB + qd * 16, &w3h[base], true);
        }
        cp_commit();
    };

    const int lrow = lid & 15;
    const int lcol = (lid >> 4) << 4;
    int bslot[2];
#pragma unroll
    for (int tm = 0; tm < 2; tm++) {
        int row = wid * 32 + tm * 16 + lrow;
        bslot[tm] = (row >> 5) * 34 + (row & 31);
    }
    const int b_row8 = lid & 7;
    const int b_koff = ((lid >> 3) & 1) * 16;

    float acc[4][2][4];
#pragma unroll
    for (int p = 0; p < 4; p++)
#pragma unroll
        for (int t = 0; t < 2; t++)
#pragma unroll
            for (int j = 0; j < 4; j++) acc[p][t][j] = 0.f;

    load_stage(0, 0);

    for (int s = 0; s < NCH; s++) {
        const int buf = s & 1;
        if (s + 1 < NCH) { load_stage(s + 1, buf ^ 1); cp_wait1(); }
        else             { cp_wait0(); }
        __syncthreads();

        const u32 uA = u0 + buf * STAGEB;
        const u32 uB = uA + ABYTES;
#pragma unroll
        for (int tap = 0; tap < 4; tap++) {
            const int dy = tap >> 1, dx = tap & 1;
#pragma unroll
            for (int par = 0; par < 4; par++) {
                const int ry = par >> 1, rx = par & 1;
                u32 ah[2][4], al[2][4];
#pragma unroll
                for (int tm = 0; tm < 2; tm++) {
                    u32 aaddr = (u32)((bslot[tm] + (dy + ry) * 34 + dx + rx) * SROW) + lcol;
                    ldsm4(ah[tm], uA + aaddr);
                    ldsm4(al[tm], uA + aaddr + 32);
                }
                u32 b0, b1;
                ldsm2(b0, b1, uB + (u32)((par * 8 + b_row8) * SROWB) + tap * 32 + b_koff);
#pragma unroll
                for (int tm = 0; tm < 2; tm++)
                    mma16816f(acc[par][tm], ah[tm], b0, b1);
#pragma unroll
                for (int tm = 0; tm < 2; tm++)
                    mma16816f(acc[par][tm], al[tm], b0, b1);
            }
        }
        __syncthreads();
    }

    // ---- epilogue: NCHW fp32 scatter (co < 3) ----
    float* out_n = out + (size_t)n * 3 * 4096;
    const int nbase = (lid & 3) * 2;
#pragma unroll
    for (int par = 0; par < 4; par++) {
        const int ry = par >> 1, rx = par & 1;
#pragma unroll
        for (int tm = 0; tm < 2; tm++) {
#pragma unroll
            for (int rr = 0; rr < 2; rr++) {
                int r = wid * 32 + tm * 16 + (lid >> 2) + rr * 8;
                int yo = 2 * (qy0 + (r >> 5)) + ry;
                int xo = 2 * (r & 31) + rx;
#pragma unroll
                for (int j = 0; j < 2; j++) {
                    int co = nbase + j;
                    if (co < 3)
                        out_n[co * 4096 + yo * 64 + xo] = acc[par][tm][rr * 2 + j];
                }
            }
        }
    }
}

// -----------------------------------------------------------------------------------------
extern "C" void kernel_launch(void* const* d_in, const int* in_sizes, int n_in,
                              void* d_out, int out_size) {
    (void)in_sizes; (void)n_in; (void)out_size;
    const float* angles   = (const float*)d_in[0];
    const float* item_rep = (const float*)d_in[1];
    const float* w0       = (const float*)d_in[2];
    const float* b0       = (const float*)d_in[3];
    const float* w1       = (const float*)d_in[4];
    const float* w2       = (const float*)d_in[5];
    const float* w3       = (const float*)d_in[6];
    float* out = (float*)d_out;

    float* p_b0r;
    cudaGetSymbolAddress((void**)&p_b0r, g_b0r);
    __half *p_ithi, *p_itlo, *p_w0h;
    cudaGetSymbolAddress((void**)&p_ithi, g_itemhi);
    cudaGetSymbolAddress((void**)&p_itlo, g_itemlo);
    cudaGetSymbolAddress((void**)&p_w0h, g_w0h);
    __half *p_h0hi, *p_h0lo, *p_h1hi, *p_h1lo, *p_h2hi, *p_h2lo;
    cudaGetSymbolAddress((void**)&p_h0hi, g_h0hi);
    cudaGetSymbolAddress((void**)&p_h0lo, g_h0lo);
    cudaGetSymbolAddress((void**)&p_h1hi, g_h1hi);
    cudaGetSymbolAddress((void**)&p_h1lo, g_h1lo);
    cudaGetSymbolAddress((void**)&p_h2hi, g_h2hi);
    cudaGetSymbolAddress((void**)&p_h2lo, g_h2lo);
    __half *p_w1h, *p_w2h, *p_w3h;
    cudaGetSymbolAddress((void**)&p_w1h, g_w1h);
    cudaGetSymbolAddress((void**)&p_w2h, g_w2h);
    cudaGetSymbolAddress((void**)&p_w3h, g_w3h);

    constexpr int SMEMD1 = 2 * (162 * 80 + 128 * 144);  // 62784
    constexpr int SMEMD2 = 2 * (180 * 80 + 128 * 144);  // 65664
    constexpr int SMEMD3 = 2 * (340 * 80 + 32 * 144);   // 63616
    constexpr int SMEMG  = 2 * 3 * 128 * 80;            // 61440
    cudaFuncSetAttribute(deconv_mma_kernel<256, 128, 8, false>,
                         cudaFuncAttributeMaxDynamicSharedMemorySize, SMEMD1);
    cudaFuncSetAttribute(deconv_mma_kernel<128, 64, 16, true>,
                         cudaFuncAttributeMaxDynamicSharedMemorySize, SMEMD2);
    cudaFuncSetAttribute(deconv3_mma_kernel,
                         cudaFuncAttributeMaxDynamicSharedMemorySize, SMEMD3);
    cudaFuncSetAttribute(dense_mma_kernel,
                         cudaFuncAttributeMaxDynamicSharedMemorySize, SMEMG);

    const int SETUP_TOTAL = 4 * 16 * 128 * 64 + 4 * 8 * 64 * 64 + 4 * 4 * 8 * 64
                            + DENSE_N * FEAT + DENSE_N + 286;
    setup_kernel<<<(SETUP_TOTAL + 255) / 256, 256>>>(w1, w2, w3, w0, b0);
    wigner_kernel<<<(N_SAMP * REP * 6 + 127) / 128, 128>>>(angles, item_rep);
    dense_mma_kernel<<<dim3(DENSE_N / 128, N_SAMP / 128), 256, SMEMG>>>(
        p_ithi, p_itlo, p_w0h, p_b0r, p_h0hi, p_h0lo);
    deconv_mma_kernel<256, 128, 8, false><<<dim3(1024, 4), 256, SMEMD1>>>(
        p_h0hi, p_h0lo, p_w1h, p_h1hi, p_h1lo);
    deconv_mma_kernel<128, 64, 16, true><<<dim3(4096, 2), 256, SMEMD2>>>(
        p_h1hi, p_h1lo, p_w2h, p_h2hi, p_h2lo);
    deconv3_mma_kernel<<<N_SAMP * 4, 256, SMEMD3>>>(p_h2hi, p_h2lo, p_w3h, out);
}

// round 14
// speedup vs baseline: 2.1615x; 1.0199x over previous
#include <cuda_runtime.h>
#include <cuda_fp16.h>
#include <math.h>
#include <stdint.h>

typedef unsigned int u32;
typedef unsigned long long u64;

#define N_SAMP 2048
#define MDIMS  36
#define REP    10
#define FEAT   360
#define DENSE_N 16384        // 256*8*8

// ---------------- fp16 pack/unpack ----------------
__device__ __forceinline__ u32 f16pack(float lo, float hi) {
    u32 r;
    asm("cvt.rn.f16x2.f32 %0, %1, %2;" : "=r"(r) : "f"(hi), "f"(lo));
    return r;
}
__device__ __forceinline__ float2 f16unpk(u32 u) {
    __half2 h = *reinterpret_cast<__half2*>(&u);
    return __half22float2(h);
}

// ---------------- warp MMA + cp.async helpers ----------------
__device__ __forceinline__ u32 smem_to_u32(const void* p) {
    u32 a;
    asm("{ .reg .u64 t; cvta.to.shared.u64 t, %1; cvt.u32.u64 %0, t; }" : "=r"(a) : "l"(p));
    return a;
}
__device__ __forceinline__ void ldsm4(u32* r, u32 addr) {
    asm volatile("ldmatrix.sync.aligned.m8n8.x4.shared.b16 {%0,%1,%2,%3}, [%4];"
                 : "=r"(r[0]), "=r"(r[1]), "=r"(r[2]), "=r"(r[3]) : "r"(addr));
}
__device__ __forceinline__ void ldsm2(u32& r0, u32& r1, u32 addr) {
    asm volatile("ldmatrix.sync.aligned.m8n8.x2.shared.b16 {%0,%1}, [%2];"
                 : "=r"(r0), "=r"(r1) : "r"(addr));
}
__device__ __forceinline__ void mma16816f(float* d, const u32* a, u32 b0, u32 b1) {
    asm volatile(
        "mma.sync.aligned.m16n8k16.row.col.f32.f16.f16.f32 "
        "{%0,%1,%2,%3}, {%4,%5,%6,%7}, {%8,%9}, {%0,%1,%2,%3};"
        : "+f"(d[0]), "+f"(d[1]), "+f"(d[2]), "+f"(d[3])
        : "r"(a[0]), "r"(a[1]), "r"(a[2]), "r"(a[3]), "r"(b0), "r"(b1));
}
__device__ __forceinline__ void cp16(u32 dst, const void* src, bool p) {
    asm volatile("cp.async.cg.shared.global [%0], [%1], 16, %2;"
                 :: "r"(dst), "l"(src), "r"(p ? 16 : 0) : "memory");
}
__device__ __forceinline__ void cp_commit() {
    asm volatile("cp.async.commit_group;" ::: "memory");
}
__device__ __forceinline__ void cp_wait1() {
    asm volatile("cp.async.wait_group 1;" ::: "memory");
}
__device__ __forceinline__ void cp_wait0() {
    asm volatile("cp.async.wait_group 0;" ::: "memory");
}

// ---------------- scratch ----------------
__device__ float g_JD[286];
__device__ __align__(16) __half g_itemhi[N_SAMP * FEAT];
__device__ __align__(16) __half g_itemlo[N_SAMP * FEAT];
__device__ __align__(16) __half g_h0hi[N_SAMP * 16384];      // NHWC [n,8,8,256]
__device__ __align__(16) __half g_h0lo[N_SAMP * 16384];
__device__ __align__(16) __half g_h1hi[N_SAMP * 256 * 128];  // NHWC [n,16,16,128]
__device__ __align__(16) __half g_h1lo[N_SAMP * 256 * 128];
__device__ __align__(16) __half g_h2hi[N_SAMP * 1024 * 64];  // NHWC [n,32,32,64]
__device__ __align__(16) __half g_h2lo[N_SAMP * 1024 * 64];
__device__ __align__(16) __half g_w1h[4 * 128 * 1024];       // [par][chunk16][co][tap*16+ci]
__device__ __align__(16) __half g_w2h[4 * 64 * 512];
__device__ __align__(16) __half g_w3h[4 * 4 * 8 * 64];       // [par][chunk16][co8][tap*16+ci]
__device__ __align__(16) __half g_w0h[DENSE_N * FEAT];       // [j'=pix*256+c][k]
__device__ __align__(16) float g_b0r[DENSE_N];

__device__ __constant__ int c_off[7] = {0, 1, 10, 35, 84, 165, 286};

// ---------------- J_l math ----------------
__device__ double dfact(int n) { double r = 1.0; for (int i = 2; i <= n; i++) r *= (double)i; return r; }

__device__ double small_d(int l, int mp, int m) {
    const double ch = 0.70710678118654752440, sh = 0.70710678118654752440;
    double pref = sqrt(dfact(l + mp) * dfact(l - mp) * dfact(l + m) * dfact(l - m));
    int smin = max(0, m - mp), smax = min(l + m, l - mp);
    double tot = 0.0;
    for (int s = smin; s <= smax; s++) {
        double sign = ((mp - m + s) & 1) ? -1.0 : 1.0;
        double denom = dfact(l + m - s) * dfact(s) * dfact(mp - m + s) * dfact(l - mp - s);
        tot += sign / denom * pow(ch, (double)(2 * l + m - mp - 2 * s)) * pow(sh, (double)(mp - m + 2 * s));
    }
    return pref * tot;
}

__device__ void c2r_row(int l, int i, int* col, double* re, double* im, int* cnt) {
    int m = i - l;
    const double s = 0.70710678118654752440;
    if (m < 0) {
        double sgn = (m & 1) ? -1.0 : 1.0;
        col[0] = l + m; re[0] = 0.0; im[0] = s;
        col[1] = l - m; re[1] = 0.0; im[1] = -sgn * s;
        *cnt = 2;
    } else if (m == 0) {
        col[0] = l; re[0] = 1.0; im[0] = 0.0; *cnt = 1;
    } else {
        double sgn = (m & 1) ? -1.0 : 1.0;
        col[0] = l - m; re[0] = s;        im[0] = 0.0;
        col[1] = l + m; re[1] = sgn * s;  im[1] = 0.0;
        *cnt = 2;
    }
}

__device__ void jd_entry(int idx) {
    int l = 0;
    while (idx >= c_off[l + 1]) l++;
    int e = idx - c_off[l];
    int sz = 2 * l + 1;
    int i = e / sz, j = e % sz;
    int ca_c[2], cb_c[2], na, nb;
    double ca_re[2], ca_im[2], cb_re[2], cb_im[2];
    c2r_row(l, i, ca_c, ca_re, ca_im, &na);
    c2r_row(l, j, cb_c, cb_re, cb_im, &nb);
    double acc = 0.0;
    for (int a = 0; a < na; a++)
        for (int b = 0; b < nb; b++) {
            double cross = ca_re[a] * cb_re[b] + ca_im[a] * cb_im[b];
            if (cross != 0.0) acc += cross * small_d(l, ca_c[a] - l, cb_c[b] - l);
        }
    g_JD[idx] = (float)acc;
}

// ------- setup kernel: w1, w2, w3 (padded co8), w0(permuted), b0(permuted), J_l -------
__device__ __forceinline__ void repack_wgt(const float* w, __half* bh,
                                           int i, int COUT, int CIN, int NCHUNK) {
    int cii = i & 15;
    int tap = (i >> 4) & 3;
    int co  = (i >> 6) % COUT;
    int chunk = (i / (64 * COUT)) % NCHUNK;
    int par = i / (64 * COUT * NCHUNK);
    int ci = chunk * 16 + cii;
    int dy = tap >> 1, dx = tap & 1, ry = par >> 1, rx = par & 1;
    float v = w[((co * CIN + ci) * 4 + (2 * dy + ry)) * 4 + (2 * dx + rx)];
    bh[i] = __float2half(v);
}

__global__ void setup_kernel(const float* __restrict__ w1, const float* __restrict__ w2,
                             const float* __restrict__ w3,
                             const float* __restrict__ w0, const float* __restrict__ b0) {
    const int T1 = 4 * 16 * 128 * 64;      // 524288
    const int T2 = 4 * 8 * 64 * 64;        // 131072
    const int T3 = 4 * 4 * 8 * 64;         // 8192
    const int T0 = DENSE_N * FEAT;         // 5898240
    int idx = blockIdx.x * 256 + threadIdx.x;
    if (idx < T1) {
        repack_wgt(w1, g_w1h, idx, 128, 256, 16);
    } else if (idx < T1 + T2) {
        repack_wgt(w2, g_w2h, idx - T1, 64, 128, 8);
    } else if (idx < T1 + T2 + T3) {
        int i = idx - T1 - T2;
        int cii = i & 15, tap = (i >> 4) & 3, co8 = (i >> 6) & 7;
        int chunk = (i >> 9) & 3, par = (i >> 11) & 3;
        float v = 0.f;
        if (co8 < 3) {
            int ci = chunk * 16 + cii;
            int dy = tap >> 1, dx = tap & 1, ry = par >> 1, rx = par & 1;
            v = w3[((co8 * 64 + ci) * 4 + (2 * dy + ry)) * 4 + (2 * dx + rx)];
        }
        g_w3h[i] = __float2half(v);
    } else if (idx < T1 + T2 + T3 + T0) {
        int i = idx - T1 - T2 - T3;
        int jp = i / FEAT, k = i % FEAT;
        int pix = jp >> 8, c = jp & 255;
        g_w0h[i] = __float2half(w0[(size_t)k * DENSE_N + c * 64 + pix]);
    } else if (idx < T1 + T2 + T3 + T0 + DENSE_N) {
        int jp = idx - T1 - T2 - T3 - T0;
        g_b0r[jp] = b0[(jp & 255) * 64 + (jp >> 8)];
    } else if (idx < T1 + T2 + T3 + T0 + DENSE_N + 286) {
        jd_entry(idx - T1 - T2 - T3 - T0 - DENSE_N);
    }
}

// ---------------- Wigner (parallel over l) -> item fp16 hi/lo ----------------
__device__ __forceinline__ void zrot_apply(const float* v, int sz, int l, float ang, float* out) {
    for (int i = 0; i < sz; i++) {
        float f = (float)(l - i);
        float s, c;
        sincosf(f * ang, &s, &c);
        out[i] = c * v[i] + s * v[sz - 1 - i];
    }
}

__global__ void wigner_kernel(const float* __restrict__ angles, const float* __restrict__ item_rep) {
    int t = blockIdx.x * blockDim.x + threadIdx.x;
    if (t >= N_SAMP * REP * 6) return;
    int l = t % 6;
    int nr = t / 6;
    int n = nr / REP, r = nr % REP;
    float a0 = angles[n * 3 + 0], a1 = angles[n * 3 + 1], a2 = angles[n * 3 + 2];
    float v[11], w[11];
    int sz = 2 * l + 1;
    const float* J = &g_JD[c_off[l]];
    for (int i = 0; i < sz; i++) v[i] = item_rep[(l * l + i) * REP + r];
    zrot_apply(v, sz, l, a2, w);
    for (int i = 0; i < sz; i++) { float s = 0.f; for (int j = 0; j < sz; j++) s += J[i * sz + j] * w[j]; v[i] = s; }
    zrot_apply(v, sz, l, a1, w);
    for (int i = 0; i < sz; i++) { float s = 0.f; for (int j = 0; j < sz; j++) s += J[i * sz + j] * w[j]; v[i] = s; }
    zrot_apply(v, sz, l, a0, w);
    for (int i = 0; i < sz; i++) {
        size_t o = (size_t)n * FEAT + (l * l + i) * REP + r;
        float val = w[i];
        __half h = __float2half(val);
        g_itemhi[o] = h;
        g_itemlo[o] = __float2half(val - __half2float(h));
    }
}

// ---------------- dense HMMA: h0 = relu(item @ w0r + b0r), output IS NHWC ----------------
// 3-buffer single-sync pipeline.
__global__ __launch_bounds__(256) void dense_mma_kernel(
    const __half* __restrict__ ahi, const __half* __restrict__ alo,
    const __half* __restrict__ bh_, const float* __restrict__ biasr,
    __half* __restrict__ chi, __half* __restrict__ clo) {
    constexpr int SROW = 80;
    constexpr int SLAB = 128 * SROW;       // 10240
    constexpr int STAGEB = 3 * SLAB;       // 30720
    constexpr int KCH = 12;

    extern __shared__ __align__(16) char smem[];
    const u32 u0 = smem_to_u32(smem);
    const int tid = threadIdx.x;
    const int wid = tid >> 5, lid = tid & 31;
    const int wm = wid >> 1, wn = wid & 1;
    const int nb0 = blockIdx.x * 128;
    const int m0  = blockIdx.y * 128;

    auto load_stage = [&](int s, int buf) {
        const int k0 = s * 32;
        const u32 uAh = u0 + buf * STAGEB;
        const u32 uAl = uAh + SLAB;
        const u32 uB  = uAl + SLAB;
#pragma unroll
        for (int t = 0; t < 2; t++) {
            int idx = tid + t * 256;
            int row = idx >> 2, qd = idx & 3;
            int k = k0 + qd * 8;
            bool p = k < FEAT;
            int kc = p ? k : (FEAT - 8);
            u32 doff = row * SROW + qd * 16;
            cp16(uAh + doff, &ahi[(size_t)(m0 + row) * FEAT + kc], p);
            cp16(uAl + doff, &alo[(size_t)(m0 + row) * FEAT + kc], p);
            cp16(uB  + doff, &bh_[(size_t)(nb0 + row) * FEAT + kc], p);
        }
        cp_commit();
    };

    const int lrow = lid & 15;
    const int lcol = (lid >> 4) << 4;

    float acc[2][8][4];
#pragma unroll
    for (int t = 0; t < 2; t++)
#pragma unroll
        for (int f = 0; f < 8; f++)
#pragma unroll
            for (int j = 0; j < 4; j++) acc[t][f][j] = 0.f;

    load_stage(0, 0);
    load_stage(1, 1);

    for (int s = 0; s < KCH; s++) {
        if (s + 1 < KCH) cp_wait1(); else cp_wait0();
        __syncthreads();
        if (s + 2 < KCH) load_stage(s + 2, (s + 2) % 3);
        const u32 uAh = u0 + (s % 3) * STAGEB;
        const u32 uAl = uAh + SLAB;
        const u32 uB  = uAl + SLAB;
#pragma unroll
        for (int ks = 0; ks < 2; ks++) {
            u32 ah[2][4], al[2][4], bh[4][4];
#pragma unroll
            for (int tm = 0; tm < 2; tm++) {
                u32 aaddr = (u32)((wm * 32 + tm * 16 + lrow) * SROW) + ks * 32 + lcol;
                ldsm4(ah[tm], uAh + aaddr);
                ldsm4(al[tm], uAl + aaddr);
            }
#pragma unroll
            for (int g = 0; g < 4; g++) {
                u32 baddr = (u32)((wn * 64 + g * 16 + lrow) * SROW) + ks * 32 + lcol;
                ldsm4(bh[g], uB + baddr);
            }
#pragma unroll
            for (int tm = 0; tm < 2; tm++)
#pragma unroll
                for (int g = 0; g < 4; g++)
#pragma unroll
                    for (int h = 0; h < 2; h++)
                        mma16816f(acc[tm][g * 2 + h], ah[tm], bh[g][h], bh[g][h + 2]);
#pragma unroll
            for (int tm = 0; tm < 2; tm++)
#pragma unroll
                for (int g = 0; g < 4; g++)
#pragma unroll
                    for (int h = 0; h < 2; h++)
                        mma16816f(acc[tm][g * 2 + h], al[tm], bh[g][h], bh[g][h + 2]);
        }
    }

#pragma unroll
    for (int tm = 0; tm < 2; tm++) {
#pragma unroll
        for (int rr = 0; rr < 2; rr++) {
            int r = m0 + wm * 32 + tm * 16 + (lid >> 2) + rr * 8;
            size_t obase = (size_t)r * DENSE_N + nb0;
#pragma unroll
            for (int f = 0; f < 8; f++) {
                int jc = wn * 64 + f * 8 + (lid & 3) * 2;
                float v0 = fmaxf(acc[tm][f][rr * 2 + 0] + biasr[nb0 + jc], 0.f);
                float v1 = fmaxf(acc[tm][f][rr * 2 + 1] + biasr[nb0 + jc + 1], 0.f);
                u32 hp = f16pack(v0, v1);
                float2 hf = f16unpk(hp);
                u32 lp = f16pack(v0 - hf.x, v1 - hf.y);
                *(u32*)&chi[obase + jc] = hp;
                *(u32*)&clo[obase + jc] = lp;
            }
        }
    }
}

// ------- HMMA implicit-GEMM deconv, M=128/CTA, K16 stages, 3-buffer single-sync ------
template <int CIN, int COUT, int HIN, bool MERGE_RX>
__global__ __launch_bounds__(256, 2) void deconv_mma_kernel(
    const __half* __restrict__ in_hi, const __half* __restrict__ in_lo,
    const __half* __restrict__ w_h,
    __half* __restrict__ out_hi, __half* __restrict__ out_lo) {
    constexpr int NCHUNK = CIN / 16;
    constexpr int HOUT = 2 * HIN;
    constexpr bool SAMPLE_MODE = (HIN == 8);
    constexpr int PW = SAMPLE_MODE ? 9 : 18;
    constexpr int SLOTS = SAMPLE_MODE ? 162 : 180;   // 2*81 | 10*18
    constexpr int SROW = 80;               // [32B hi][32B lo][16 pad]
    constexpr int ABYTES = SLOTS * SROW;
    constexpr int SROWB = 144;             // [128B w][16 pad]
    constexpr int BROWS = 128;
    constexpr int BBYTES = BROWS * SROWB;
    constexpr int STAGEB = ABYTES + BBYTES;
    constexpr int NPAR = MERGE_RX ? 2 : 1;
    constexpr int NG = COUT / 32;
    constexpr int NF8 = COUT / 16;

    extern __shared__ __align__(16) char smem[];
    const u32 u0 = smem_to_u32(smem);

    const int tid = threadIdx.x;
    const int wid = tid >> 5;
    const int lid = tid & 31;
    const int wm = wid >> 1;
    const int wn = wid & 1;
    const int par = blockIdx.y;
    const int ry = MERGE_RX ? par : (par >> 1);
    const int rx0 = MERGE_RX ? 0 : (par & 1);
    const int n0 = SAMPLE_MODE ? blockIdx.x * 2 : (blockIdx.x >> 1);
    const int qy0 = SAMPLE_MODE ? 0 : ((blockIdx.x & 1) * 8);

    auto load_stage = [&](int s, int buf) {
        const int ci0 = s * 16;
        const u32 uA = u0 + buf * STAGEB;
        const u32 uB = uA + ABYTES;
#pragma unroll 2
        for (int idx = tid; idx < SLOTS * 2; idx += 256) {
            int slot = idx >> 1, qd = idx & 1;
            int n, y, x;
            if (SAMPLE_MODE) {
                int smp = slot / 81, rr = slot % 81;
                n = n0 + smp;
                y = rr / 9 - 1 + ry;
                x = rr % 9 - 1 + rx0;
            } else {
                n = n0;
                y = slot / 18 + qy0 - 1 + ry;
                x = slot % 18 - 1;
            }
            bool p = (y >= 0) && (y < HIN) && (x >= 0) && (x < HIN);
            int yc = p ? y : 0, xc = p ? x : 0;
            size_t base = (((size_t)n * HIN + yc) * HIN + xc) * CIN + ci0 + qd * 8;
            u32 doff = slot * SROW + qd * 16;
            cp16(uA + doff,      &in_hi[base], p);
            cp16(uA + doff + 32, &in_lo[base], p);
        }
#pragma unroll
        for (int k = 0; k < 4; k++) {
            int idx = tid + k * 256;
            int row = idx >> 3, qd = idx & 7;
            int co, wpar;
            if (MERGE_RX) { co = row & 63; wpar = ry * 2 + (row >> 6); }
            else          { co = row;      wpar = par; }
            size_t base = (((size_t)(wpar * NCHUNK + s) * COUT + co) << 6) + qd * 8;
            cp16(uB + row * SROWB + qd * 16, &w_h[base], true);
        }
        cp_commit();
    };

    const int lrow = lid & 15;
    const int lcol = (lid >> 4) << 4;
    int bslot[2];
#pragma unroll
    for (int tm = 0; tm < 2; tm++) {
        int row = wm * 32 + tm * 16 + lrow;
        if (SAMPLE_MODE) {
            int smp = row >> 6, q = row & 63;
            bslot[tm] = smp * 81 + (q >> 3) * 9 + (q & 7);
        } else {
            bslot[tm] = (row >> 4) * 18 + (row & 15);
        }
    }

    float acc[NPAR][2][NF8][4];
#pragma unroll
    for (int p = 0; p < NPAR; p++)
#pragma unroll
        for (int t = 0; t < 2; t++)
#pragma unroll
            for (int f = 0; f < NF8; f++)
#pragma unroll
                for (int j = 0; j < 4; j++) acc[p][t][f][j] = 0.f;

    load_stage(0, 0);
    load_stage(1, 1);

    for (int s = 0; s < NCHUNK; s++) {
        if (s + 1 < NCHUNK) cp_wait1(); else cp_wait0();
        __syncthreads();
        if (s + 2 < NCHUNK) load_stage(s + 2, (s + 2) % 3);

        const u32 uA = u0 + (s % 3) * STAGEB;
        const u32 uB = uA + ABYTES;
#pragma unroll
        for (int tap = 0; tap < 4; tap++) {
            const int dy = tap >> 1, dx = tap & 1;
#pragma unroll
            for (int prx = 0; prx < NPAR; prx++) {
                u32 ah[2][4], al[2][4];
#pragma unroll
                for (int tm = 0; tm < 2; tm++) {
                    u32 aaddr = (u32)((bslot[tm] + dy * PW + dx + prx) * SROW) + lcol;
                    ldsm4(ah[tm], uA + aaddr);
                    ldsm4(al[tm], uA + aaddr + 32);
                }
#pragma unroll
                for (int g = 0; g < NG; g++) {
                    u32 bh[4];
                    u32 baddr = (u32)((prx * COUT + wn * (COUT / 2) + g * 16 + lrow) * SROWB)
                                + tap * 32 + lcol;
                    ldsm4(bh, uB + baddr);
#pragma unroll
                    for (int tm = 0; tm < 2; tm++) {
                        mma16816f(acc[prx][tm][g * 2 + 0], ah[tm], bh[0], bh[2]);
                        mma16816f(acc[prx][tm][g * 2 + 1], ah[tm], bh[1], bh[3]);
                    }
#pragma unroll
                    for (int tm = 0; tm < 2; tm++) {
                        mma16816f(acc[prx][tm][g * 2 + 0], al[tm], bh[0], bh[2]);
                        mma16816f(acc[prx][tm][g * 2 + 1], al[tm], bh[1], bh[3]);
                    }
                }
            }
        }
    }

    // ---- epilogue: ReLU + fp16 hi/lo NHWC store ----
#pragma unroll
    for (int prx = 0; prx < NPAR; prx++) {
        const int rx = MERGE_RX ? prx : rx0;
#pragma unroll
        for (int tm = 0; tm < 2; tm++) {
            int r0 = wm * 32 + tm * 16 + (lid >> 2);
#pragma unroll
            for (int rr = 0; rr < 2; rr++) {
                int r = r0 + rr * 8;
                int n, yo, xo;
                if (SAMPLE_MODE) {
                    n = n0 + (r >> 6);
                    int q = r & 63;
                    yo = 2 * (q >> 3) + ry;
                    xo = 2 * (q & 7) + rx;
                } else {
                    n = n0;
                    yo = 2 * (qy0 + (r >> 4)) + ry;
                    xo = 2 * (r & 15) + rx;
                }
                size_t obase = (((size_t)n * HOUT + yo) * HOUT + xo) * COUT;
#pragma unroll
                for (int f = 0; f < NF8; f++) {
                    int ch = wn * (COUT / 2) + f * 8 + (lid & 3) * 2;
                    float v0 = fmaxf(acc[prx][tm][f][rr * 2 + 0], 0.f);
                    float v1 = fmaxf(acc[prx][tm][f][rr * 2 + 1], 0.f);
                    u32 hp = f16pack(v0, v1);
                    float2 hf = f16unpk(hp);
                    u32 lp = f16pack(v0 - hf.x, v1 - hf.y);
                    *(u32*)&out_hi[obase + ch] = hp;
                    *(u32*)&out_lo[obase + ch] = lp;
                }
            }
        }
    }
}

// ------- deconv3 HMMA: 64 -> 3 (N padded to 8), A fragments shared over (tap,par) ------
// CTA = 8 qy x 32 qx pixel rows. Output NCHW fp32 (no relu).
__global__ __launch_bounds__(256, 2) void deconv3_mma_kernel(
    const __half* __restrict__ in_hi, const __half* __restrict__ in_lo,
    const __half* __restrict__ w3h, float* __restrict__ out) {
    constexpr int SLOTS = 340;             // 10 x 34
    constexpr int SROW = 80;               // [32B hi][32B lo][16 pad]
    constexpr int ABYTES = SLOTS * SROW;   // 27200
    constexpr int SROWB = 144;             // [128B: 4 taps x 16ci][16 pad]
    constexpr int BBYTES = 32 * SROWB;     // 4608
    constexpr int STAGEB = ABYTES + BBYTES;// 31808
    constexpr int NCH = 4;                 // 64 ci / 16

    extern __shared__ __align__(16) char smem[];
    const u32 u0 = smem_to_u32(smem);

    const int tid = threadIdx.x;
    const int wid = tid >> 5;
    const int lid = tid & 31;
    const int n = blockIdx.x >> 2;
    const int qy0 = (blockIdx.x & 3) * 8;

    auto load_stage = [&](int s, int buf) {
        const int ci0 = s * 16;
        const u32 uA = u0 + buf * STAGEB;
        const u32 uB = uA + ABYTES;
#pragma unroll 3
        for (int idx = tid; idx < SLOTS * 2; idx += 256) {
            int slot = idx >> 1, qd = idx & 1;
            int y = slot / 34 + qy0 - 1;
            int x = slot % 34 - 1;
            bool p = (y >= 0) && (y < 32) && (x >= 0) && (x < 32);
            int yc = p ? y : 0, xc = p ? x : 0;
            size_t base = (((size_t)n * 32 + yc) * 32 + xc) * 64 + ci0 + qd * 8;
            u32 doff = slot * SROW + qd * 16;
            cp16(uA + doff,      &in_hi[base], p);
            cp16(uA + doff + 32, &in_lo[base], p);
        }
        {   // B: 32 rows (4 par x 8 co8) x 8 x 16B
            int row = tid >> 3, qd = tid & 7;
            int par = row >> 3, co8 = row & 7;
            size_t base = (((size_t)(par * NCH + s) * 8 + co8) << 6) + qd * 8;
            cp16(uB + row * SROWB + qd * 16, &w3h[base], true);
        }
        cp_commit();
    };

    const int lrow = lid & 15;
    const int lcol = (lid >> 4) << 4;
    int bslot[2];
#pragma unroll
    for (int tm = 0; tm < 2; tm++) {
        int row = wid * 32 + tm * 16 + lrow;
        bslot[tm] = (row >> 5) * 34 + (row & 31);
    }
    const int b_row8 = lid & 7;
    const int b_koff = ((lid >> 3) & 1) * 16;

    float acc[4][2][4];
#pragma unroll
    for (int p = 0; p < 4; p++)
#pragma unroll
        for (int t = 0; t < 2; t++)
#pragma unroll
            for (int j = 0; j < 4; j++) acc[p][t][j] = 0.f;

    load_stage(0, 0);
    load_stage(1, 1);

    for (int s = 0; s < NCH; s++) {
        if (s + 1 < NCH) cp_wait1(); else cp_wait0();
        __syncthreads();
        if (s + 2 < NCH) load_stage(s + 2, (s + 2) % 3);

        const u32 uA = u0 + (s % 3) * STAGEB;
        const u32 uB = uA + ABYTES;
        // A fragments depend only on (sy, sx) = (dy+ry, dx+rx) in 3x3 — load per sy row.
#pragma unroll
        for (int sy = 0; sy < 3; sy++) {
            u32 af[3][2][2][4];   // [sx][tm][hi/lo][frag]
#pragma unroll
            for (int sx = 0; sx < 3; sx++)
#pragma unroll
                for (int tm = 0; tm < 2; tm++) {
                    u32 aaddr = (u32)((bslot[tm] + sy * 34 + sx) * SROW) + lcol;
                    ldsm4(af[sx][tm][0], uA + aaddr);
                    ldsm4(af[sx][tm][1], uA + aaddr + 32);
                }
#pragma unroll
            for (int dy = 0; dy < 2; dy++) {
                const int ry = sy - dy;
                if (ry < 0 || ry > 1) continue;
#pragma unroll
                for (int dx = 0; dx < 2; dx++)
#pragma unroll
                    for (int rx = 0; rx < 2; rx++) {
                        const int sx = dx + rx;
                        const int par = ry * 2 + rx;
                        const int tap = dy * 2 + dx;
                        u32 b0, b1;
                        ldsm2(b0, b1, uB + (u32)((par * 8 + b_row8) * SROWB) + tap * 32 + b_koff);
#pragma unroll
                        for (int tm = 0; tm < 2; tm++)
                            mma16816f(acc[par][tm], af[sx][tm][0], b0, b1);
#pragma unroll
                        for (int tm = 0; tm < 2; tm++)
                            mma16816f(acc[par][tm], af[sx][tm][1], b0, b1);
                    }
            }
        }
    }

    // ---- epilogue: NCHW fp32 scatter (co < 3) ----
    float* out_n = out + (size_t)n * 3 * 4096;
    const int nbase = (lid & 3) * 2;
#pragma unroll
    for (int par = 0; par < 4; par++) {
        const int ry = par >> 1, rx = par & 1;
#pragma unroll
        for (int tm = 0; tm < 2; tm++) {
#pragma unroll
            for (int rr = 0; rr < 2; rr++) {
                int r = wid * 32 + tm * 16 + (lid >> 2) + rr * 8;
                int yo = 2 * (qy0 + (r >> 5)) + ry;
                int xo = 2 * (r & 31) + rx;
#pragma unroll
                for (int j = 0; j < 2; j++) {
                    int co = nbase + j;
                    if (co < 3)
                        out_n[co * 4096 + yo * 64 + xo] = acc[par][tm][rr * 2 + j];
                }
            }
        }
    }
}

// -----------------------------------------------------------------------------------------
extern "C" void kernel_launch(void* const* d_in, const int* in_sizes, int n_in,
                              void* d_out, int out_size) {
    (void)in_sizes; (void)n_in; (void)out_size;
    const float* angles   = (const float*)d_in[0];
    const float* item_rep = (const float*)d_in[1];
    const float* w0       = (const float*)d_in[2];
    const float* b0       = (const float*)d_in[3];
    const float* w1       = (const float*)d_in[4];
    const float* w2       = (const float*)d_in[5];
    const float* w3       = (const float*)d_in[6];
    float* out = (float*)d_out;

    float* p_b0r;
    cudaGetSymbolAddress((void**)&p_b0r, g_b0r);
    __half *p_ithi, *p_itlo, *p_w0h;
    cudaGetSymbolAddress((void**)&p_ithi, g_itemhi);
    cudaGetSymbolAddress((void**)&p_itlo, g_itemlo);
    cudaGetSymbolAddress((void**)&p_w0h, g_w0h);
    __half *p_h0hi, *p_h0lo, *p_h1hi, *p_h1lo, *p_h2hi, *p_h2lo;
    cudaGetSymbolAddress((void**)&p_h0hi, g_h0hi);
    cudaGetSymbolAddress((void**)&p_h0lo, g_h0lo);
    cudaGetSymbolAddress((void**)&p_h1hi, g_h1hi);
    cudaGetSymbolAddress((void**)&p_h1lo, g_h1lo);
    cudaGetSymbolAddress((void**)&p_h2hi, g_h2hi);
    cudaGetSymbolAddress((void**)&p_h2lo, g_h2lo);
    __half *p_w1h, *p_w2h, *p_w3h;
    cudaGetSymbolAddress((void**)&p_w1h, g_w1h);
    cudaGetSymbolAddress((void**)&p_w2h, g_w2h);
    cudaGetSymbolAddress((void**)&p_w3h, g_w3h);

    constexpr int SMEMD1 = 3 * (162 * 80 + 128 * 144);  // 94176
    constexpr int SMEMD2 = 3 * (180 * 80 + 128 * 144);  // 98496
    constexpr int SMEMD3 = 3 * (340 * 80 + 32 * 144);   // 95424
    constexpr int SMEMG  = 3 * 3 * 128 * 80;            // 92160
    cudaFuncSetAttribute(deconv_mma_kernel<256, 128, 8, false>,
                         cudaFuncAttributeMaxDynamicSharedMemorySize, SMEMD1);
    cudaFuncSetAttribute(deconv_mma_kernel<128, 64, 16, true>,
                         cudaFuncAttributeMaxDynamicSharedMemorySize, SMEMD2);
    cudaFuncSetAttribute(deconv3_mma_kernel,
                         cudaFuncAttributeMaxDynamicSharedMemorySize, SMEMD3);
    cudaFuncSetAttribute(dense_mma_kernel,
                         cudaFuncAttributeMaxDynamicSharedMemorySize, SMEMG);

    const int SETUP_TOTAL = 4 * 16 * 128 * 64 + 4 * 8 * 64 * 64 + 4 * 4 * 8 * 64
                            + DENSE_N * FEAT + DENSE_N + 286;
    setup_kernel<<<(SETUP_TOTAL + 255) / 256, 256>>>(w1, w2, w3, w0, b0);
    wigner_kernel<<<(N_SAMP * REP * 6 + 127) / 128, 128>>>(angles, item_rep);
    dense_mma_kernel<<<dim3(DENSE_N / 128, N_SAMP / 128), 256, SMEMG>>>(
        p_ithi, p_itlo, p_w0h, p_b0r, p_h0hi, p_h0lo);
    deconv_mma_kernel<256, 128, 8, false><<<dim3(1024, 4), 256, SMEMD1>>>(
        p_h0hi, p_h0lo, p_w1h, p_h1hi, p_h1lo);
    deconv_mma_kernel<128, 64, 16, true><<<dim3(4096, 2), 256, SMEMD2>>>(
        p_h1hi, p_h1lo, p_w2h, p_h2hi, p_h2lo);
    deconv3_mma_kernel<<<N_SAMP * 4, 256, SMEMD3>>>(p_h2hi, p_h2lo, p_w3h, out);
}